// round 6
// baseline (speedup 1.0000x reference)
#include <cuda_runtime.h>
#include <cuda_bf16.h>
#include <float.h>
#include <math.h>
#include <stdint.h>

// Problem constants (fixed shapes)
#define BN_TOT 64      // b*r
#define NB 2           // b
#define RR 32          // r
#define NN 512         // n
#define DIMC 256       // DIM
#define HH 8           // heads
#define DH 64          // dim_head
#define INNERD 512     // HH*DH
#define KW 15          // conv kernel

// ---------------- scratch (device globals; no allocations allowed) ----------
__device__ float g_dots[NB * HH * NN * NN];         // logits fp32

__device__ uint16_t g_xs_h[BN_TOT * NN * DIMC],  g_xs_l[BN_TOT * NN * DIMC];
__device__ uint16_t g_hdw_h[BN_TOT * NN * DIMC], g_hdw_l[BN_TOT * NN * DIMC];
__device__ uint16_t g_pww_h[INNERD * DIMC],      g_pww_l[INNERD * DIMC];
__device__ uint16_t g_wkvT_h[2 * INNERD * DIMC], g_wkvT_l[2 * INNERD * DIMC];
__device__ uint16_t g_woT_h[DIMC * INNERD],      g_woT_l[DIMC * INNERD];
__device__ uint16_t g_qr_h[NB * HH * NN * RR * DH], g_qr_l[NB * HH * NN * RR * DH];
__device__ uint16_t g_kr_h[NB * HH * NN * RR * DH], g_kr_l[NB * HH * NN * RR * DH];
__device__ uint16_t g_attn_h[NB * HH * NN * NN], g_attn_l[NB * HH * NN * NN];
__device__ uint16_t g_vT_h[BN_TOT * INNERD * NN], g_vT_l[BN_TOT * INNERD * NN];
__device__ uint16_t g_oi_h[BN_TOT * NN * INNERD], g_oi_l[BN_TOT * NN * INNERD];

__device__ unsigned char g_mask[BN_TOT * NN];
__device__ float g_has_rows[BN_TOT];
__device__ float g_m_any[NB * NN];
__device__ float g_alpha[NB];
__device__ float g_sin[NN * 32];
__device__ float g_cos[NN * 32];
__device__ int g_mask_mode;

// ========================= helpers ===========================================
__device__ __forceinline__ uint32_t smem_u32(const void* p) {
    uint32_t a;
    asm("{ .reg .u64 t; cvta.to.shared.u64 t, %1; cvt.u32.u64 %0, t; }" : "=r"(a) : "l"(p));
    return a;
}

#define LDSM4(r, addr)                                                          \
    asm volatile("ldmatrix.sync.aligned.m8n8.x4.shared.b16 {%0,%1,%2,%3}, [%4];" \
                 : "=r"((r)[0]), "=r"((r)[1]), "=r"((r)[2]), "=r"((r)[3])       \
                 : "r"(addr))

#define MMA16816(c, a, b)                                                       \
    asm volatile("mma.sync.aligned.m16n8k16.row.col.f32.bf16.bf16.f32 "         \
                 "{%0,%1,%2,%3}, {%4,%5,%6,%7}, {%8,%9}, {%0,%1,%2,%3};"        \
                 : "+f"((c)[0]), "+f"((c)[1]), "+f"((c)[2]), "+f"((c)[3])       \
                 : "r"((a)[0]), "r"((a)[1]), "r"((a)[2]), "r"((a)[3]),          \
                   "r"((b)[0]), "r"((b)[1]))

#define CP16(dst, src)                                                          \
    asm volatile("cp.async.cg.shared.global [%0], [%1], 16;" :: "r"(dst), "l"(src) : "memory")
#define CP_COMMIT() asm volatile("cp.async.commit_group;" ::: "memory")
#define CP_WAIT1()  asm volatile("cp.async.wait_group 1;" ::: "memory")
#define CP_WAIT0()  asm volatile("cp.async.wait_group 0;" ::: "memory")

// byte offset in a 64B-per-row bf16 tile (32 k values/row), bank-swizzled
__device__ __forceinline__ uint32_t soff(int row, int kcol) {
    return (uint32_t)(row * 64 + ((kcol * 2) ^ (((row >> 1) & 3) << 4)));
}

// exact truncation split: v = hi(bf16) + lo(bf16 rounded)
__device__ __forceinline__ void fsplit(float v, uint16_t& h, uint16_t& l) {
    uint32_t u = __float_as_uint(v);
    uint32_t hu = u & 0xFFFF0000u;
    h = (uint16_t)(hu >> 16);
    l = __bfloat16_as_ushort(__float2bfloat16(v - __uint_as_float(hu)));
}

// ========================= mask / small kernels ==============================
__global__ void k_detect(const unsigned char* m) {
    __shared__ int s_high, s_odd;
    if (threadIdx.x == 0) { s_high = 0; s_odd = 0; }
    __syncthreads();
    for (int idx = threadIdx.x; idx < BN_TOT * NN; idx += blockDim.x) {
        unsigned char v = m[idx];
        if (v > 1) s_high = 1;
        if ((idx & 3) && v) s_odd = 1;
    }
    __syncthreads();
    if (threadIdx.x == 0) g_mask_mode = s_high ? 2 : (s_odd ? 0 : 1);
}
__global__ void k_norm_mask(const void* m) {
    int idx = blockIdx.x * blockDim.x + threadIdx.x;
    if (idx >= BN_TOT * NN) return;
    int mode = g_mask_mode;
    unsigned char v;
    if (mode == 0)      v = (((const unsigned char*)m)[idx] != 0);
    else if (mode == 1) v = (((const int*)m)[idx] != 0);
    else                v = (((const float*)m)[idx] != 0.0f);
    g_mask[idx] = v;
}
__global__ void k_hasrows() {
    int bn = blockIdx.x;
    int any = 0;
    for (int j = threadIdx.x; j < NN; j += blockDim.x) any |= g_mask[bn * NN + j];
    __shared__ int s;
    if (threadIdx.x == 0) s = 0;
    __syncthreads();
    if (any) s = 1;
    __syncthreads();
    if (threadIdx.x == 0) g_has_rows[bn] = (float)s;
}
__global__ void k_many() {
    int b = blockIdx.x;
    int i = threadIdx.x;
    int any = 0;
    for (int r = 0; r < RR; r++) any |= g_mask[(b * RR + r) * NN + i];
    g_m_any[b * NN + i] = (float)any;
    if (i == 0) {
        float s = 0.f;
        for (int r = 0; r < RR; r++) s += g_has_rows[b * RR + r];
        g_alpha[b] = (s > 0.f) ? 0.125f * rsqrtf(s) : 0.f;
    }
}
__global__ void k_trig() {
    int i = blockIdx.x;        // 512
    int j = threadIdx.x;       // 32
    float inv = exp2f(-((float)(2 * j) / 64.0f) * 13.287712379549449f);
    float ang = (float)i * inv;
    g_sin[i * 32 + j] = sinf(ang);
    g_cos[i * 32 + j] = cosf(ang);
}

// ---------------- splits / transposes ---------------------------------------
__global__ void k_split(const float* __restrict__ src, uint16_t* __restrict__ h,
                        uint16_t* __restrict__ l, int n) {
    int i = blockIdx.x * blockDim.x + threadIdx.x;
    if (i >= n) return;
    fsplit(src[i], h[i], l[i]);
}
__global__ void k_wkvT(const float* __restrict__ w) {   // (256,1024)->(1024,256) split
    int i = blockIdx.x * 256 + threadIdx.x;
    int n = i >> 8, k = i & 255;
    fsplit(w[k * 1024 + n], g_wkvT_h[i], g_wkvT_l[i]);
}
__global__ void k_woT(const float* __restrict__ w) {    // (512,256)->(256,512) split
    int i = blockIdx.x * 256 + threadIdx.x;
    int n = i >> 9, k = i & 511;
    fsplit(w[k * 256 + n], g_woT_h[i], g_woT_l[i]);
}

// ---------------- depthwise conv (writes split) ------------------------------
__global__ void k_conv(const float* __restrict__ x,
                       const float* __restrict__ dww,
                       const float* __restrict__ dwb) {
    int bn = blockIdx.x >> 9;
    int i  = blockIdx.x & 511;
    int c  = threadIdx.x;
    float acc = dwb[c];
    const float* xr = x + (size_t)bn * NN * DIMC + c;
#pragma unroll
    for (int k = 0; k < KW; k++) {
        int ii = i + k - KW / 2;
        if (ii >= 0 && ii < NN) acc += xr[(size_t)ii * DIMC] * dww[c * KW + k];
    }
    size_t o = ((size_t)bn * NN + i) * DIMC + c;
    fsplit(acc, g_hdw_h[o], g_hdw_l[o]);
}

// ---------------- masked softmax (writes split) ------------------------------
__global__ void k_softmax() {
    int row = blockIdx.x;
    int b = row >> 12;
    int i = row & 511;
    const float* p = g_dots + (size_t)row * NN;
    float rv = g_m_any[b * NN + i];
    int t = threadIdx.x;

    float m0 = g_m_any[b * NN + t];
    float m1 = g_m_any[b * NN + t + 256];
    float x0 = (rv != 0.f && m0 != 0.f) ? p[t]       : -FLT_MAX;
    float x1 = (rv != 0.f && m1 != 0.f) ? p[t + 256] : -FLT_MAX;

    __shared__ float red[256];
    float mx = fmaxf(x0, x1);
    red[t] = mx;
    __syncthreads();
    for (int s = 128; s > 0; s >>= 1) {
        if (t < s) red[t] = fmaxf(red[t], red[t + s]);
        __syncthreads();
    }
    mx = red[0];
    __syncthreads();
    float e0 = expf(x0 - mx), e1 = expf(x1 - mx);
    red[t] = e0 + e1;
    __syncthreads();
    for (int s = 128; s > 0; s >>= 1) {
        if (t < s) red[t] += red[t + s];
        __syncthreads();
    }
    float inv = 1.0f / red[0];
    size_t o = (size_t)row * NN;
    fsplit(e0 * inv, g_attn_h[o + t],       g_attn_l[o + t]);
    fsplit(e1 * inv, g_attn_h[o + t + 256], g_attn_l[o + t + 256]);
}

// ================== mma.sync bf16-split NT GEMM (3-stage cp.async) ===========
struct GemmP {
    const uint16_t *Ah, *Al; long long lda; long long a_bs;
    const uint16_t *Bh, *Bl; long long ldb; long long b_bs;
    float* C;                                  // fp32 out (or null)
    uint16_t *Ch, *Cl;                         // split out (or null)
    long long ldc; long long c_bs;
    int K;
    const float* bias;
    const float* alpha_vec; int alpha_shift;
    int mode;   // 0 normal batch, 1 = AV addressing
    int emode;  // 0 plain, 1 rotary->qr (has_rows), 2 rotary->kr, 3 vT transpose-split
};

// rotary epilogue: (v_e, v_o) at global row `row`, even col `col` (hd space)
__device__ __forceinline__ void rot_store(uint16_t* __restrict__ Rh,
                                          uint16_t* __restrict__ Rl,
                                          int row, int col, float ve, float vo,
                                          bool isq) {
    int i = row & 511, bn = row >> 9;
    int h = col >> 6, d = col & 63, j = d >> 1;
    float s = g_sin[i * 32 + j], c = g_cos[i * 32 + j];
    float oe = ve * c - vo * s;
    float oo = vo * c + ve * s;
    if (isq) {
        float hr = g_has_rows[bn];
        oe *= hr; oo *= hr;
    }
    int b = bn >> 5, r = bn & 31;
    size_t dst = (((size_t)(b * HH + h) * NN + i) * (RR * DH)) + r * DH + d;
    uint16_t h0, l0, h1, l1;
    fsplit(oe, h0, l0); fsplit(oo, h1, l1);
    *(uint32_t*)(Rh + dst) = (uint32_t)h0 | ((uint32_t)h1 << 16);
    *(uint32_t*)(Rl + dst) = (uint32_t)l0 | ((uint32_t)l1 << 16);
}

template <int TN>
__global__ void __launch_bounds__(256) k_mma(GemmP p) {
    constexpr int NT8 = TN / 32;
    constexpr int NX4 = NT8 / 2;
    constexpr uint32_t SS = 16384 + TN * 128;    // stage stride bytes
    extern __shared__ __align__(128) char dsm[];
    uint32_t sb = smem_u32(dsm);

    int tid = threadIdx.x, wid = tid >> 5, lane = tid & 31;
    int bx = blockIdx.x, by = blockIdx.y, z = blockIdx.z;

    size_t abase, cbase;
    size_t bbase = (size_t)z * p.b_bs + (size_t)bx * TN * p.ldb;
    if (p.mode == 0) {
        abase = (size_t)z * p.a_bs;
        cbase = (size_t)z * p.c_bs;
    } else {                                  // AV: z = bn*8 + h
        int bn = z >> 3, h = z & 7, b = bn >> 5;
        abase = (size_t)(b * HH + h) * p.a_bs;
        cbase = (size_t)bn * p.c_bs + h * 64;
    }
    abase += (size_t)by * 128 * p.lda;
    const uint16_t* Ah = p.Ah + abase;
    const uint16_t* Al = p.Al + abase;
    const uint16_t* Bh = p.Bh + bbase;
    const uint16_t* Bl = p.Bl + bbase;

    int m0 = (wid & 1) * 64;
    int n0 = (wid >> 1) * (TN / 4);
    int arow = m0 + (lane & 7) + ((lane >> 3) & 1) * 8;
    int akb  = ((lane >> 4) & 1) * 8;
    int brow = n0 + (lane & 7) + ((lane >> 4) & 1) * 8;
    int bkb  = ((lane >> 3) & 1) * 8;

    float acc[4][NT8][4];
#pragma unroll
    for (int i = 0; i < 4; i++)
#pragma unroll
        for (int j = 0; j < NT8; j++)
#pragma unroll
            for (int q = 0; q < 4; q++) acc[i][j][q] = 0.f;

    int KC = p.K >> 5;

    auto load_stage = [&](int st, int k0) {
        uint32_t base = sb + (uint32_t)st * SS;
#pragma unroll 2
        for (int idx = tid; idx < 512; idx += 256) {
            int row = idx >> 2, c = idx & 3;
            uint32_t off = (uint32_t)(row * 64 + ((c * 16) ^ (((row >> 1) & 3) << 4)));
            CP16(base + off,        Ah + (size_t)row * p.lda + k0 + c * 8);
            CP16(base + 8192 + off, Al + (size_t)row * p.lda + k0 + c * 8);
        }
#pragma unroll 2
        for (int idx = tid; idx < TN * 4; idx += 256) {
            int row = idx >> 2, c = idx & 3;
            uint32_t off = (uint32_t)(row * 64 + ((c * 16) ^ (((row >> 1) & 3) << 4)));
            CP16(base + 16384 + off,           Bh + (size_t)row * p.ldb + k0 + c * 8);
            CP16(base + 16384 + TN * 64 + off, Bl + (size_t)row * p.ldb + k0 + c * 8);
        }
    };

    load_stage(0, 0);
    CP_COMMIT();
    if (KC > 1) { load_stage(1, 32); CP_COMMIT(); }

    int st = 0;
    for (int ch = 0; ch < KC; ch++) {
        if (ch + 2 <= KC) CP_WAIT1(); else CP_WAIT0();
        __syncthreads();
        if (ch + 2 < KC) {
            int st2 = st + 2; if (st2 >= 3) st2 -= 3;
            load_stage(st2, (ch + 2) << 5);
            CP_COMMIT();
        }

        uint32_t base = sb + (uint32_t)st * SS;
        uint32_t aHiB = base, aLoB = base + 8192;
        uint32_t bHiB = base + 16384, bLoB = base + 16384 + TN * 64;

#pragma unroll
        for (int kk = 0; kk < 32; kk += 16) {
            uint32_t ah[4][4];
#pragma unroll
            for (int mt = 0; mt < 4; mt++)
                LDSM4(ah[mt], aHiB + soff(arow + mt * 16, kk + akb));
            uint32_t bh[NX4][4];
#pragma unroll
            for (int nx = 0; nx < NX4; nx++)
                LDSM4(bh[nx], bHiB + soff(brow + nx * 16, kk + bkb));
#pragma unroll
            for (int mt = 0; mt < 4; mt++)
#pragma unroll
                for (int nt = 0; nt < NT8; nt++)
                    MMA16816(acc[mt][nt], ah[mt], &bh[nt >> 1][(nt & 1) * 2]);

            uint32_t bl[NX4][4];
#pragma unroll
            for (int nx = 0; nx < NX4; nx++)
                LDSM4(bl[nx], bLoB + soff(brow + nx * 16, kk + bkb));
#pragma unroll
            for (int mt = 0; mt < 4; mt++)
#pragma unroll
                for (int nt = 0; nt < NT8; nt++)
                    MMA16816(acc[mt][nt], ah[mt], &bl[nt >> 1][(nt & 1) * 2]);

            uint32_t al[4][4];
#pragma unroll
            for (int mt = 0; mt < 4; mt++)
                LDSM4(al[mt], aLoB + soff(arow + mt * 16, kk + akb));
#pragma unroll
            for (int mt = 0; mt < 4; mt++)
#pragma unroll
                for (int nt = 0; nt < NT8; nt++)
                    MMA16816(acc[mt][nt], al[mt], &bh[nt >> 1][(nt & 1) * 2]);
        }
        st++; if (st >= 3) st = 0;
    }

    // epilogue
    float alpha = p.alpha_vec ? p.alpha_vec[z >> p.alpha_shift] : 1.0f;
    int r0 = by * 128 + m0 + (lane >> 2);
    int c0 = bx * TN + n0 + (lane & 3) * 2;

    if (p.emode == 3) {
        // V-projection: transpose tile through smem, write split vT directly.
        __syncthreads();
        float* sm = (float*)dsm;
        int rl = m0 + (lane >> 2);
        int cl = n0 + (lane & 3) * 2;
#pragma unroll
        for (int mt = 0; mt < 4; mt++)
#pragma unroll
            for (int nt = 0; nt < NT8; nt++) {
                int cc = cl + nt * 8, rr = rl + mt * 16;
                sm[(cc + 0) * 129 + rr]     = acc[mt][nt][0];
                sm[(cc + 1) * 129 + rr]     = acc[mt][nt][1];
                sm[(cc + 0) * 129 + rr + 8] = acc[mt][nt][2];
                sm[(cc + 1) * 129 + rr + 8] = acc[mt][nt][3];
            }
        __syncthreads();
        int bn = (by * 128) >> 9, i0g = (by * 128) & 511, hd0 = bx * TN;
        int hd = tid >> 1, jh = (tid & 1) * 64;
        size_t dst = ((size_t)bn * 512 + hd0 + hd) * 512 + i0g + jh;
        const float* srow = sm + hd * 129 + jh;
#pragma unroll 8
        for (int j = 0; j < 64; j += 2) {
            uint16_t h0, l0, h1, l1;
            fsplit(srow[j], h0, l0); fsplit(srow[j + 1], h1, l1);
            *(uint32_t*)(g_vT_h + dst + j) = (uint32_t)h0 | ((uint32_t)h1 << 16);
            *(uint32_t*)(g_vT_l + dst + j) = (uint32_t)l0 | ((uint32_t)l1 << 16);
        }
        return;
    }

#pragma unroll
    for (int mt = 0; mt < 4; mt++) {
#pragma unroll
        for (int nt = 0; nt < NT8; nt++) {
            int row = r0 + mt * 16;
            int col = c0 + nt * 8;
            float b0 = 0.f, b1 = 0.f;
            if (p.bias) { b0 = p.bias[col]; b1 = p.bias[col + 1]; }
            float v00 = acc[mt][nt][0] * alpha + b0;
            float v01 = acc[mt][nt][1] * alpha + b1;
            float v10 = acc[mt][nt][2] * alpha + b0;
            float v11 = acc[mt][nt][3] * alpha + b1;
            if (p.emode == 1) {
                rot_store(g_qr_h, g_qr_l, row, col, v00, v01, true);
                rot_store(g_qr_h, g_qr_l, row + 8, col, v10, v11, true);
            } else if (p.emode == 2) {
                rot_store(g_kr_h, g_kr_l, row, col, v00, v01, false);
                rot_store(g_kr_h, g_kr_l, row + 8, col, v10, v11, false);
            } else {
                if (p.C) {
                    *(float2*)(p.C + cbase + (size_t)row * p.ldc + col) = make_float2(v00, v01);
                    *(float2*)(p.C + cbase + (size_t)(row + 8) * p.ldc + col) = make_float2(v10, v11);
                }
                if (p.Ch) {
                    uint16_t h0, l0, h1, l1;
                    fsplit(v00, h0, l0); fsplit(v01, h1, l1);
                    *(uint32_t*)(p.Ch + cbase + (size_t)row * p.ldc + col) = (uint32_t)h0 | ((uint32_t)h1 << 16);
                    *(uint32_t*)(p.Cl + cbase + (size_t)row * p.ldc + col) = (uint32_t)l0 | ((uint32_t)l1 << 16);
                    fsplit(v10, h0, l0); fsplit(v11, h1, l1);
                    *(uint32_t*)(p.Ch + cbase + (size_t)(row + 8) * p.ldc + col) = (uint32_t)h0 | ((uint32_t)h1 << 16);
                    *(uint32_t*)(p.Cl + cbase + (size_t)(row + 8) * p.ldc + col) = (uint32_t)l0 | ((uint32_t)l1 << 16);
                }
            }
        }
    }
}

// ---------------- launch -----------------------------------------------------
#define SYM(var, sym) decltype(&sym[0]) var; cudaGetSymbolAddress((void**)&var, sym)

extern "C" void kernel_launch(void* const* d_in, const int* in_sizes, int n_in,
                              void* d_out, int out_size) {
    const float* x    = (const float*)d_in[0];
    const void*  mask = d_in[1];
    const float* dw_w = (const float*)d_in[3];
    const float* dw_b = (const float*)d_in[4];
    const float* pw_w = (const float*)d_in[5];
    const float* pw_b = (const float*)d_in[6];
    const float* w_kv = (const float*)d_in[7];
    const float* w_o  = (const float*)d_in[8];
    const float* b_o  = (const float*)d_in[9];
    float* out = (float*)d_out;

    const int SM128 = 3 * (16384 + 128 * 128);   // 98304 (also covers 66KB transpose)
    const int SM64  = 3 * (16384 + 64 * 128);    // 73728
    cudaFuncSetAttribute(k_mma<128>, cudaFuncAttributeMaxDynamicSharedMemorySize, SM128);
    cudaFuncSetAttribute(k_mma<64>,  cudaFuncAttributeMaxDynamicSharedMemorySize, SM64);

    SYM(dots_p, g_dots);
    SYM(xs_h, g_xs_h);    SYM(xs_l, g_xs_l);
    SYM(hdw_h, g_hdw_h);  SYM(hdw_l, g_hdw_l);
    SYM(pww_h, g_pww_h);  SYM(pww_l, g_pww_l);
    SYM(wkvT_h, g_wkvT_h); SYM(wkvT_l, g_wkvT_l);
    SYM(woT_h, g_woT_h);  SYM(woT_l, g_woT_l);
    SYM(qr_h, g_qr_h);    SYM(qr_l, g_qr_l);
    SYM(kr_h, g_kr_h);    SYM(kr_l, g_kr_l);
    SYM(attn_h, g_attn_h); SYM(attn_l, g_attn_l);
    SYM(vT_h, g_vT_h);    SYM(vT_l, g_vT_l);
    SYM(oi_h, g_oi_h);    SYM(oi_l, g_oi_l);
    SYM(alpha_p, g_alpha);

    k_detect<<<1, 256>>>((const unsigned char*)mask);
    k_norm_mask<<<(BN_TOT * NN + 255) / 256, 256>>>(mask);
    k_hasrows<<<BN_TOT, 256>>>();
    k_many<<<NB, NN>>>();
    k_trig<<<NN, 32>>>();

    k_split<<<(BN_TOT * NN * DIMC) / 256, 256>>>(x, xs_h, xs_l, BN_TOT * NN * DIMC);
    k_split<<<(INNERD * DIMC) / 256, 256>>>(pw_w, pww_h, pww_l, INNERD * DIMC);
    k_wkvT<<<(2 * INNERD * DIMC) / 256, 256>>>(w_kv);
    k_woT<<<(DIMC * INNERD) / 256, 256>>>(w_o);

    k_conv<<<BN_TOT * NN, DIMC>>>(x, dw_w, dw_b);

    // qproj + bias + rotary + has_rows -> qr split  (M=32768, N=512, K=256)
    {
        GemmP p = {hdw_h, hdw_l, DIMC, 0, pww_h, pww_l, DIMC, 0,
                   nullptr, nullptr, nullptr, 0, 0,
                   DIMC, pw_b, nullptr, 0, 0, 1};
        k_mma<128><<<dim3(4, 256, 1), 256, SM128>>>(p);
    }
    // K proj + rotary -> kr split  (M=32768, N=512, K=256; B = wkvT rows 0..511)
    {
        GemmP p = {xs_h, xs_l, DIMC, 0, wkvT_h, wkvT_l, DIMC, 0,
                   nullptr, nullptr, nullptr, 0, 0,
                   DIMC, nullptr, nullptr, 0, 0, 2};
        k_mma<128><<<dim3(4, 256, 1), 256, SM128>>>(p);
    }
    // V proj -> vT split (transposed in epilogue)  (M=32768, N=512, K=256)
    {
        GemmP p = {xs_h, xs_l, DIMC, 0, wkvT_h + INNERD * DIMC, wkvT_l + INNERD * DIMC, DIMC, 0,
                   nullptr, nullptr, nullptr, 0, 0,
                   DIMC, nullptr, nullptr, 0, 0, 3};
        k_mma<128><<<dim3(4, 256, 1), 256, SM128>>>(p);
    }
    // dots: 16 batches, M=N=512, K=2048 -> g_dots fp32 (alpha per b)
    {
        GemmP p = {qr_h, qr_l, 2048, (long long)NN * 2048, kr_h, kr_l, 2048, (long long)NN * 2048,
                   dots_p, nullptr, nullptr, NN, (long long)NN * NN,
                   2048, nullptr, alpha_p, 3, 0, 0};
        k_mma<128><<<dim3(4, 4, 16), 256, SM128>>>(p);
    }
    k_softmax<<<NB * HH * NN, 256>>>();
    // AV: 512 batches (bn,h), M=512, N=64, K=512 -> oi split
    {
        GemmP p = {attn_h, attn_l, NN, (long long)NN * NN, vT_h, vT_l, NN, (long long)DH * NN,
                   nullptr, oi_h, oi_l, INNERD, (long long)NN * INNERD,
                   NN, nullptr, nullptr, 0, 1, 0};
        k_mma<64><<<dim3(1, 4, BN_TOT * HH), 256, SM64>>>(p);
    }
    // final: M=32768, N=256, K=512 -> out fp32 (+bias)
    {
        GemmP p = {oi_h, oi_l, INNERD, 0, woT_h, woT_l, INNERD, 0,
                   out, nullptr, nullptr, DIMC, 0,
                   INNERD, b_o, nullptr, 0, 0, 0};
        k_mma<128><<<dim3(2, 256, 1), 256, SM128>>>(p);
    }
}

// round 7
// speedup vs baseline: 1.1922x; 1.1922x over previous
#include <cuda_runtime.h>
#include <cuda_bf16.h>
#include <cuda_fp16.h>
#include <float.h>
#include <math.h>
#include <stdint.h>

// Problem constants (fixed shapes)
#define BN_TOT 64      // b*r
#define NB 2           // b
#define RR 32          // r
#define NN 512         // n
#define DIMC 256       // DIM
#define HH 8           // heads
#define DH 64          // dim_head
#define INNERD 512     // HH*DH
#define KW 15          // conv kernel

// ---------------- scratch (device globals; no allocations allowed) ----------
__device__ float g_v[BN_TOT * NN * INNERD];         // v fp32 (bn, i, hd)
__device__ float g_dots[NB * HH * NN * NN];         // logits fp32

// fp16 2-term (A-side) / hi-only (B-side) operands
__device__ uint16_t g_xs_h[BN_TOT * NN * DIMC],  g_xs_l[BN_TOT * NN * DIMC];
__device__ uint16_t g_hdw_h[BN_TOT * NN * DIMC], g_hdw_l[BN_TOT * NN * DIMC];
__device__ uint16_t g_pww_h[INNERD * DIMC];                 // B hi only
__device__ uint16_t g_wkvT_h[2 * INNERD * DIMC];            // B hi only
__device__ uint16_t g_woT_h[DIMC * INNERD];                 // B hi only
__device__ uint16_t g_vT_h[BN_TOT * INNERD * NN];           // B hi only
__device__ uint16_t g_attn_h[NB * HH * NN * NN], g_attn_l[NB * HH * NN * NN];
__device__ uint16_t g_oi_h[BN_TOT * NN * INNERD], g_oi_l[BN_TOT * NN * INNERD];
// bf16 3-term operands for dots
__device__ uint16_t g_qr_h[NB * HH * NN * RR * DH], g_qr_l[NB * HH * NN * RR * DH];
__device__ uint16_t g_kr_h[NB * HH * NN * RR * DH], g_kr_l[NB * HH * NN * RR * DH];

__device__ unsigned char g_mask[BN_TOT * NN];
__device__ float g_has_rows[BN_TOT];
__device__ float g_m_any[NB * NN];
__device__ float g_alpha[NB];
__device__ float g_sin[NN * 32];
__device__ float g_cos[NN * 32];
__device__ int g_mask_mode;

// ========================= helpers ===========================================
__device__ __forceinline__ uint32_t smem_u32(const void* p) {
    uint32_t a;
    asm("{ .reg .u64 t; cvta.to.shared.u64 t, %1; cvt.u32.u64 %0, t; }" : "=r"(a) : "l"(p));
    return a;
}

#define LDSM4(r, addr)                                                          \
    asm volatile("ldmatrix.sync.aligned.m8n8.x4.shared.b16 {%0,%1,%2,%3}, [%4];" \
                 : "=r"((r)[0]), "=r"((r)[1]), "=r"((r)[2]), "=r"((r)[3])       \
                 : "r"(addr))

template <int MODE>   // 0 = bf16, 1 = fp16
__device__ __forceinline__ void mma_t(float* c, const uint32_t* a, const uint32_t* b) {
    if (MODE == 0) {
        asm volatile("mma.sync.aligned.m16n8k16.row.col.f32.bf16.bf16.f32 "
                     "{%0,%1,%2,%3}, {%4,%5,%6,%7}, {%8,%9}, {%0,%1,%2,%3};"
                     : "+f"(c[0]), "+f"(c[1]), "+f"(c[2]), "+f"(c[3])
                     : "r"(a[0]), "r"(a[1]), "r"(a[2]), "r"(a[3]), "r"(b[0]), "r"(b[1]));
    } else {
        asm volatile("mma.sync.aligned.m16n8k16.row.col.f32.f16.f16.f32 "
                     "{%0,%1,%2,%3}, {%4,%5,%6,%7}, {%8,%9}, {%0,%1,%2,%3};"
                     : "+f"(c[0]), "+f"(c[1]), "+f"(c[2]), "+f"(c[3])
                     : "r"(a[0]), "r"(a[1]), "r"(a[2]), "r"(a[3]), "r"(b[0]), "r"(b[1]));
    }
}

#define CP16(dst, src)                                                          \
    asm volatile("cp.async.cg.shared.global [%0], [%1], 16;" :: "r"(dst), "l"(src) : "memory")
#define CP_COMMIT() asm volatile("cp.async.commit_group;" ::: "memory")
#define CP_WAIT1()  asm volatile("cp.async.wait_group 1;" ::: "memory")
#define CP_WAIT0()  asm volatile("cp.async.wait_group 0;" ::: "memory")

// byte offset in a 64B-per-row 16-bit tile (32 k values/row), bank-swizzled
__device__ __forceinline__ uint32_t soff(int row, int kcol) {
    return (uint32_t)(row * 64 + ((kcol * 2) ^ (((row >> 1) & 3) << 4)));
}

// exact truncation split to bf16 hi + bf16 lo
__device__ __forceinline__ void fsplit(float v, uint16_t& h, uint16_t& l) {
    uint32_t u = __float_as_uint(v);
    uint32_t hu = u & 0xFFFF0000u;
    h = (uint16_t)(hu >> 16);
    l = __bfloat16_as_ushort(__float2bfloat16(v - __uint_as_float(hu)));
}
// fp16 2-term split: v ≈ hi + lo exactly to ~22 bits
__device__ __forceinline__ void hsplit(float v, uint16_t& h, uint16_t& l) {
    __half hh = __float2half_rn(v);
    h = __half_as_ushort(hh);
    l = __half_as_ushort(__float2half_rn(v - __half2float(hh)));
}
__device__ __forceinline__ uint16_t h16(float v) {
    return __half_as_ushort(__float2half_rn(v));
}

// ========================= mask / small kernels ==============================
__global__ void k_detect(const unsigned char* m) {
    __shared__ int s_high, s_odd;
    if (threadIdx.x == 0) { s_high = 0; s_odd = 0; }
    __syncthreads();
    for (int idx = threadIdx.x; idx < BN_TOT * NN; idx += blockDim.x) {
        unsigned char v = m[idx];
        if (v > 1) s_high = 1;
        if ((idx & 3) && v) s_odd = 1;
    }
    __syncthreads();
    if (threadIdx.x == 0) g_mask_mode = s_high ? 2 : (s_odd ? 0 : 1);
}
__global__ void k_norm_mask(const void* m) {
    int idx = blockIdx.x * blockDim.x + threadIdx.x;
    if (idx >= BN_TOT * NN) return;
    int mode = g_mask_mode;
    unsigned char v;
    if (mode == 0)      v = (((const unsigned char*)m)[idx] != 0);
    else if (mode == 1) v = (((const int*)m)[idx] != 0);
    else                v = (((const float*)m)[idx] != 0.0f);
    g_mask[idx] = v;
}
__global__ void k_hasrows() {
    int bn = blockIdx.x;
    int any = 0;
    for (int j = threadIdx.x; j < NN; j += blockDim.x) any |= g_mask[bn * NN + j];
    __shared__ int s;
    if (threadIdx.x == 0) s = 0;
    __syncthreads();
    if (any) s = 1;
    __syncthreads();
    if (threadIdx.x == 0) g_has_rows[bn] = (float)s;
}
__global__ void k_many() {
    int b = blockIdx.x;
    int i = threadIdx.x;
    int any = 0;
    for (int r = 0; r < RR; r++) any |= g_mask[(b * RR + r) * NN + i];
    g_m_any[b * NN + i] = (float)any;
    if (i == 0) {
        float s = 0.f;
        for (int r = 0; r < RR; r++) s += g_has_rows[b * RR + r];
        g_alpha[b] = (s > 0.f) ? 0.125f * rsqrtf(s) : 0.f;
    }
}
__global__ void k_trig() {
    int i = blockIdx.x;        // 512
    int j = threadIdx.x;       // 32
    float inv = exp2f(-((float)(2 * j) / 64.0f) * 13.287712379549449f);
    float ang = (float)i * inv;
    g_sin[i * 32 + j] = sinf(ang);
    g_cos[i * 32 + j] = cosf(ang);
}

// ---------------- splits / transposes ---------------------------------------
__global__ void k_hsplit(const float* __restrict__ src, uint16_t* __restrict__ h,
                         uint16_t* __restrict__ l, int n) {
    int i = blockIdx.x * blockDim.x + threadIdx.x;
    if (i >= n) return;
    hsplit(src[i], h[i], l[i]);
}
__global__ void k_hi(const float* __restrict__ src, uint16_t* __restrict__ h, int n) {
    int i = blockIdx.x * blockDim.x + threadIdx.x;
    if (i >= n) return;
    h[i] = h16(src[i]);
}
__global__ void k_wkvT(const float* __restrict__ w) {   // (256,1024)->(1024,256) hi
    int i = blockIdx.x * 256 + threadIdx.x;
    int n = i >> 8, k = i & 255;
    g_wkvT_h[i] = h16(w[k * 1024 + n]);
}
__global__ void k_woT(const float* __restrict__ w) {    // (512,256)->(256,512) hi
    int i = blockIdx.x * 256 + threadIdx.x;
    int n = i >> 9, k = i & 511;
    g_woT_h[i] = h16(w[k * 256 + n]);
}
__global__ void k_vT() {   // v (bn, j, hd) -> vT_h[(bn*512+hd)*512 + j]
    __shared__ float t[32][33];
    int bn = blockIdx.z;
    int j0 = blockIdx.x * 32, hd0 = blockIdx.y * 32;
    int lx = threadIdx.x, ly = threadIdx.y;  // 32 x 8
    for (int dy = 0; dy < 32; dy += 8) {
        int j = j0 + ly + dy, hd = hd0 + lx;
        t[ly + dy][lx] = g_v[((size_t)bn * NN + j) * INNERD + hd];
    }
    __syncthreads();
    for (int dy = 0; dy < 32; dy += 8) {
        int hd = hd0 + ly + dy, j = j0 + lx;
        g_vT_h[((size_t)bn * 512 + hd) * 512 + j] = h16(t[lx][ly + dy]);
    }
}

// ---------------- depthwise conv (writes fp16 split) -------------------------
__global__ void k_conv(const float* __restrict__ x,
                       const float* __restrict__ dww,
                       const float* __restrict__ dwb) {
    int bn = blockIdx.x >> 9;
    int i  = blockIdx.x & 511;
    int c  = threadIdx.x;
    float acc = dwb[c];
    const float* xr = x + (size_t)bn * NN * DIMC + c;
#pragma unroll
    for (int k = 0; k < KW; k++) {
        int ii = i + k - KW / 2;
        if (ii >= 0 && ii < NN) acc += xr[(size_t)ii * DIMC] * dww[c * KW + k];
    }
    size_t o = ((size_t)bn * NN + i) * DIMC + c;
    hsplit(acc, g_hdw_h[o], g_hdw_l[o]);
}

// ---------------- masked softmax (writes fp16 split) -------------------------
__global__ void k_softmax() {
    int row = blockIdx.x;
    int b = row >> 12;
    int i = row & 511;
    const float* p = g_dots + (size_t)row * NN;
    float rv = g_m_any[b * NN + i];
    int t = threadIdx.x;

    float m0 = g_m_any[b * NN + t];
    float m1 = g_m_any[b * NN + t + 256];
    float x0 = (rv != 0.f && m0 != 0.f) ? p[t]       : -FLT_MAX;
    float x1 = (rv != 0.f && m1 != 0.f) ? p[t + 256] : -FLT_MAX;

    __shared__ float red[256];
    float mx = fmaxf(x0, x1);
    red[t] = mx;
    __syncthreads();
    for (int s = 128; s > 0; s >>= 1) {
        if (t < s) red[t] = fmaxf(red[t], red[t + s]);
        __syncthreads();
    }
    mx = red[0];
    __syncthreads();
    float e0 = expf(x0 - mx), e1 = expf(x1 - mx);
    red[t] = e0 + e1;
    __syncthreads();
    for (int s = 128; s > 0; s >>= 1) {
        if (t < s) red[t] += red[t + s];
        __syncthreads();
    }
    float inv = 1.0f / red[0];
    size_t o = (size_t)row * NN;
    hsplit(e0 * inv, g_attn_h[o + t],       g_attn_l[o + t]);
    hsplit(e1 * inv, g_attn_h[o + t + 256], g_attn_l[o + t + 256]);
}

// ================== mma.sync split NT GEMM (2-stage cp.async) ================
// MODE 0: bf16 3-term (A hi/lo, B hi/lo).  MODE 1: fp16 2-term (A hi/lo, B hi).
struct GemmP {
    const uint16_t *Ah, *Al; long long lda; long long a_bs;
    const uint16_t *Bh, *Bl; long long ldb; long long b_bs;
    float* C;                                  // fp32 out (or null)
    uint16_t *Ch, *Cl;                         // split out (or null)
    long long ldc; long long c_bs;
    int K;
    const float* bias;
    const float* alpha_vec; int alpha_shift;
    int mode;   // 0 normal batch, 1 = AV addressing
    int emode;  // 0 plain, 1 rotary->qr (has_rows), 2 rotary->kr
};

// rotary epilogue (bf16 split outputs for dots operands)
__device__ __forceinline__ void rot_store(uint16_t* __restrict__ Rh,
                                          uint16_t* __restrict__ Rl,
                                          int row, int col, float ve, float vo,
                                          bool isq) {
    int i = row & 511, bn = row >> 9;
    int h = col >> 6, d = col & 63, j = d >> 1;
    float s = g_sin[i * 32 + j], c = g_cos[i * 32 + j];
    float oe = ve * c - vo * s;
    float oo = vo * c + ve * s;
    if (isq) {
        float hr = g_has_rows[bn];
        oe *= hr; oo *= hr;
    }
    int b = bn >> 5, r = bn & 31;
    size_t dst = (((size_t)(b * HH + h) * NN + i) * (RR * DH)) + r * DH + d;
    uint16_t h0, l0, h1, l1;
    fsplit(oe, h0, l0); fsplit(oo, h1, l1);
    *(uint32_t*)(Rh + dst) = (uint32_t)h0 | ((uint32_t)h1 << 16);
    *(uint32_t*)(Rl + dst) = (uint32_t)l0 | ((uint32_t)l1 << 16);
}

template <int TN, int MODE>
__global__ void __launch_bounds__(256) k_mma(GemmP p) {
    constexpr int NT8 = TN / 32;
    constexpr int NX4 = NT8 / 2;
    constexpr uint32_t SS = (MODE == 0) ? (16384u + TN * 128u) : (16384u + TN * 64u);
    extern __shared__ __align__(128) char dsm[];
    uint32_t sb = smem_u32(dsm);

    int tid = threadIdx.x, wid = tid >> 5, lane = tid & 31;
    int bx = blockIdx.x, by = blockIdx.y, z = blockIdx.z;

    size_t abase, cbase;
    size_t bbase = (size_t)z * p.b_bs + (size_t)bx * TN * p.ldb;
    if (p.mode == 0) {
        abase = (size_t)z * p.a_bs;
        cbase = (size_t)z * p.c_bs;
    } else {                                  // AV: z = bn*8 + h
        int bn = z >> 3, h = z & 7, b = bn >> 5;
        abase = (size_t)(b * HH + h) * p.a_bs;
        cbase = (size_t)bn * p.c_bs + h * 64;
    }
    abase += (size_t)by * 128 * p.lda;
    const uint16_t* Ah = p.Ah + abase;
    const uint16_t* Al = p.Al + abase;
    const uint16_t* Bh = p.Bh + bbase;
    const uint16_t* Bl = (MODE == 0) ? (p.Bl + bbase) : nullptr;

    int m0 = (wid & 1) * 64;
    int n0 = (wid >> 1) * (TN / 4);
    int arow = m0 + (lane & 7) + ((lane >> 3) & 1) * 8;
    int akb  = ((lane >> 4) & 1) * 8;
    int brow = n0 + (lane & 7) + ((lane >> 4) & 1) * 8;
    int bkb  = ((lane >> 3) & 1) * 8;

    float acc[4][NT8][4];
#pragma unroll
    for (int i = 0; i < 4; i++)
#pragma unroll
        for (int j = 0; j < NT8; j++)
#pragma unroll
            for (int q = 0; q < 4; q++) acc[i][j][q] = 0.f;

    int KC = p.K >> 5;

    auto load_stage = [&](int st, int k0) {
        uint32_t base = sb + (uint32_t)st * SS;
#pragma unroll 2
        for (int idx = tid; idx < 512; idx += 256) {
            int row = idx >> 2, c = idx & 3;
            uint32_t off = (uint32_t)(row * 64 + ((c * 16) ^ (((row >> 1) & 3) << 4)));
            CP16(base + off,        Ah + (size_t)row * p.lda + k0 + c * 8);
            CP16(base + 8192 + off, Al + (size_t)row * p.lda + k0 + c * 8);
        }
#pragma unroll 2
        for (int idx = tid; idx < TN * 4; idx += 256) {
            int row = idx >> 2, c = idx & 3;
            uint32_t off = (uint32_t)(row * 64 + ((c * 16) ^ (((row >> 1) & 3) << 4)));
            CP16(base + 16384 + off, Bh + (size_t)row * p.ldb + k0 + c * 8);
            if (MODE == 0)
                CP16(base + 16384 + TN * 64 + off, Bl + (size_t)row * p.ldb + k0 + c * 8);
        }
    };

    load_stage(0, 0);
    CP_COMMIT();

    for (int ch = 0; ch < KC; ch++) {
        if (ch + 1 < KC) {
            load_stage((ch + 1) & 1, (ch + 1) << 5);
            CP_COMMIT();
            CP_WAIT1();
        } else {
            CP_WAIT0();
        }
        __syncthreads();

        uint32_t base = sb + (uint32_t)(ch & 1) * SS;
        uint32_t aHiB = base, aLoB = base + 8192;
        uint32_t bHiB = base + 16384, bLoB = base + 16384 + TN * 64;

#pragma unroll
        for (int kk = 0; kk < 32; kk += 16) {
            uint32_t ah[4][4];
#pragma unroll
            for (int mt = 0; mt < 4; mt++)
                LDSM4(ah[mt], aHiB + soff(arow + mt * 16, kk + akb));
            uint32_t bh[NX4][4];
#pragma unroll
            for (int nx = 0; nx < NX4; nx++)
                LDSM4(bh[nx], bHiB + soff(brow + nx * 16, kk + bkb));
#pragma unroll
            for (int mt = 0; mt < 4; mt++)
#pragma unroll
                for (int nt = 0; nt < NT8; nt++)
                    mma_t<MODE>(acc[mt][nt], ah[mt], &bh[nt >> 1][(nt & 1) * 2]);

            if (MODE == 0) {
                uint32_t bl[NX4][4];
#pragma unroll
                for (int nx = 0; nx < NX4; nx++)
                    LDSM4(bl[nx], bLoB + soff(brow + nx * 16, kk + bkb));
#pragma unroll
                for (int mt = 0; mt < 4; mt++)
#pragma unroll
                    for (int nt = 0; nt < NT8; nt++)
                        mma_t<MODE>(acc[mt][nt], ah[mt], &bl[nt >> 1][(nt & 1) * 2]);
            }

            uint32_t al[4][4];
#pragma unroll
            for (int mt = 0; mt < 4; mt++)
                LDSM4(al[mt], aLoB + soff(arow + mt * 16, kk + akb));
#pragma unroll
            for (int mt = 0; mt < 4; mt++)
#pragma unroll
                for (int nt = 0; nt < NT8; nt++)
                    mma_t<MODE>(acc[mt][nt], al[mt], &bh[nt >> 1][(nt & 1) * 2]);
        }
        __syncthreads();
    }

    // epilogue
    float alpha = p.alpha_vec ? p.alpha_vec[z >> p.alpha_shift] : 1.0f;
    int r0 = by * 128 + m0 + (lane >> 2);
    int c0 = bx * TN + n0 + (lane & 3) * 2;
#pragma unroll
    for (int mt = 0; mt < 4; mt++) {
#pragma unroll
        for (int nt = 0; nt < NT8; nt++) {
            int row = r0 + mt * 16;
            int col = c0 + nt * 8;
            float b0 = 0.f, b1 = 0.f;
            if (p.bias) { b0 = p.bias[col]; b1 = p.bias[col + 1]; }
            float v00 = acc[mt][nt][0] * alpha + b0;
            float v01 = acc[mt][nt][1] * alpha + b1;
            float v10 = acc[mt][nt][2] * alpha + b0;
            float v11 = acc[mt][nt][3] * alpha + b1;
            if (p.emode == 1) {
                rot_store(g_qr_h, g_qr_l, row, col, v00, v01, true);
                rot_store(g_qr_h, g_qr_l, row + 8, col, v10, v11, true);
            } else if (p.emode == 2) {
                rot_store(g_kr_h, g_kr_l, row, col, v00, v01, false);
                rot_store(g_kr_h, g_kr_l, row + 8, col, v10, v11, false);
            } else {
                if (p.C) {
                    *(float2*)(p.C + cbase + (size_t)row * p.ldc + col) = make_float2(v00, v01);
                    *(float2*)(p.C + cbase + (size_t)(row + 8) * p.ldc + col) = make_float2(v10, v11);
                }
                if (p.Ch) {
                    uint16_t h0, l0, h1, l1;
                    hsplit(v00, h0, l0); hsplit(v01, h1, l1);
                    *(uint32_t*)(p.Ch + cbase + (size_t)row * p.ldc + col) = (uint32_t)h0 | ((uint32_t)h1 << 16);
                    *(uint32_t*)(p.Cl + cbase + (size_t)row * p.ldc + col) = (uint32_t)l0 | ((uint32_t)l1 << 16);
                    hsplit(v10, h0, l0); hsplit(v11, h1, l1);
                    *(uint32_t*)(p.Ch + cbase + (size_t)(row + 8) * p.ldc + col) = (uint32_t)h0 | ((uint32_t)h1 << 16);
                    *(uint32_t*)(p.Cl + cbase + (size_t)(row + 8) * p.ldc + col) = (uint32_t)l0 | ((uint32_t)l1 << 16);
                }
            }
        }
    }
}

// ---------------- launch -----------------------------------------------------
#define SYM(var, sym) decltype(&sym[0]) var; cudaGetSymbolAddress((void**)&var, sym)

extern "C" void kernel_launch(void* const* d_in, const int* in_sizes, int n_in,
                              void* d_out, int out_size) {
    const float* x    = (const float*)d_in[0];
    const void*  mask = d_in[1];
    const float* dw_w = (const float*)d_in[3];
    const float* dw_b = (const float*)d_in[4];
    const float* pw_w = (const float*)d_in[5];
    const float* pw_b = (const float*)d_in[6];
    const float* w_kv = (const float*)d_in[7];
    const float* w_o  = (const float*)d_in[8];
    const float* b_o  = (const float*)d_in[9];
    float* out = (float*)d_out;

    const int SM128_3 = 2 * (16384 + 128 * 128);   // 65536 (bf16 3-term)
    const int SM128_2 = 2 * (16384 + 128 * 64);    // 49152 (fp16 2-term)
    const int SM64_2  = 2 * (16384 + 64 * 64);     // 40960
    cudaFuncSetAttribute(k_mma<128, 0>, cudaFuncAttributeMaxDynamicSharedMemorySize, SM128_3);
    cudaFuncSetAttribute(k_mma<128, 1>, cudaFuncAttributeMaxDynamicSharedMemorySize, SM128_2);
    cudaFuncSetAttribute(k_mma<64, 1>,  cudaFuncAttributeMaxDynamicSharedMemorySize, SM64_2);

    SYM(v_p, g_v);  SYM(dots_p, g_dots);
    SYM(xs_h, g_xs_h);    SYM(xs_l, g_xs_l);
    SYM(hdw_h, g_hdw_h);  SYM(hdw_l, g_hdw_l);
    SYM(pww_h, g_pww_h);
    SYM(wkvT_h, g_wkvT_h);
    SYM(woT_h, g_woT_h);
    SYM(qr_h, g_qr_h);    SYM(qr_l, g_qr_l);
    SYM(kr_h, g_kr_h);    SYM(kr_l, g_kr_l);
    SYM(attn_h, g_attn_h); SYM(attn_l, g_attn_l);
    SYM(vT_h, g_vT_h);
    SYM(oi_h, g_oi_h);    SYM(oi_l, g_oi_l);
    SYM(alpha_p, g_alpha);

    k_detect<<<1, 256>>>((const unsigned char*)mask);
    k_norm_mask<<<(BN_TOT * NN + 255) / 256, 256>>>(mask);
    k_hasrows<<<BN_TOT, 256>>>();
    k_many<<<NB, NN>>>();
    k_trig<<<NN, 32>>>();

    k_hsplit<<<(BN_TOT * NN * DIMC) / 256, 256>>>(x, xs_h, xs_l, BN_TOT * NN * DIMC);
    k_hi<<<(INNERD * DIMC) / 256, 256>>>(pw_w, pww_h, INNERD * DIMC);
    k_wkvT<<<(2 * INNERD * DIMC) / 256, 256>>>(w_kv);
    k_woT<<<(DIMC * INNERD) / 256, 256>>>(w_o);

    k_conv<<<BN_TOT * NN, DIMC>>>(x, dw_w, dw_b);

    // qproj + bias + rotary + has_rows -> qr (bf16 split)  (M=32768, N=512, K=256)
    {
        GemmP p = {hdw_h, hdw_l, DIMC, 0, pww_h, nullptr, DIMC, 0,
                   nullptr, nullptr, nullptr, 0, 0,
                   DIMC, pw_b, nullptr, 0, 0, 1};
        k_mma<128, 1><<<dim3(4, 256, 1), 256, SM128_2>>>(p);
    }
    // K proj + rotary -> kr (bf16 split)  (M=32768, N=512, K=256)
    {
        GemmP p = {xs_h, xs_l, DIMC, 0, wkvT_h, nullptr, DIMC, 0,
                   nullptr, nullptr, nullptr, 0, 0,
                   DIMC, nullptr, nullptr, 0, 0, 2};
        k_mma<128, 1><<<dim3(4, 256, 1), 256, SM128_2>>>(p);
    }
    // V proj -> g_v fp32  (M=32768, N=512, K=256)
    {
        GemmP p = {xs_h, xs_l, DIMC, 0, wkvT_h + INNERD * DIMC, nullptr, DIMC, 0,
                   v_p, nullptr, nullptr, INNERD, 0,
                   DIMC, nullptr, nullptr, 0, 0, 0};
        k_mma<128, 1><<<dim3(4, 256, 1), 256, SM128_2>>>(p);
    }
    k_vT<<<dim3(16, 16, BN_TOT), dim3(32, 8)>>>();
    // dots: bf16 3-term, 16 batches, M=N=512, K=2048 -> fp32 (alpha per b)
    {
        GemmP p = {qr_h, qr_l, 2048, (long long)NN * 2048, kr_h, kr_l, 2048, (long long)NN * 2048,
                   dots_p, nullptr, nullptr, NN, (long long)NN * NN,
                   2048, nullptr, alpha_p, 3, 0, 0};
        k_mma<128, 0><<<dim3(4, 4, 16), 256, SM128_3>>>(p);
    }
    k_softmax<<<NB * HH * NN, 256>>>();
    // AV: fp16 2-term, 512 batches (bn,h), M=512, N=64, K=512 -> oi split
    {
        GemmP p = {attn_h, attn_l, NN, (long long)NN * NN, vT_h, nullptr, NN, (long long)DH * NN,
                   nullptr, oi_h, oi_l, INNERD, (long long)NN * INNERD,
                   NN, nullptr, nullptr, 0, 1, 0};
        k_mma<64, 1><<<dim3(1, 4, BN_TOT * HH), 256, SM64_2>>>(p);
    }
    // final: fp16 2-term, M=32768, N=256, K=512 -> out fp32 (+bias)
    {
        GemmP p = {oi_h, oi_l, INNERD, 0, woT_h, nullptr, INNERD, 0,
                   out, nullptr, nullptr, DIMC, 0,
                   INNERD, b_o, nullptr, 0, 0, 0};
        k_mma<128, 1><<<dim3(2, 256, 1), 256, SM128_2>>>(p);
    }
}

// round 8
// speedup vs baseline: 1.3725x; 1.1512x over previous
#include <cuda_runtime.h>
#include <cuda_bf16.h>
#include <cuda_fp16.h>
#include <float.h>
#include <math.h>
#include <stdint.h>

// Problem constants (fixed shapes)
#define BN_TOT 64      // b*r
#define NB 2           // b
#define RR 32          // r
#define NN 512         // n
#define DIMC 256       // DIM
#define HH 8           // heads
#define DH 64          // dim_head
#define INNERD 512     // HH*DH
#define KW 15          // conv kernel

// ---------------- scratch (device globals; no allocations allowed) ----------
__device__ float g_v[BN_TOT * NN * INNERD];         // v fp32 (bn, i, hd)
__device__ float g_dots[NB * HH * NN * NN];         // logits fp32

// fp16 2-term (A-side) / hi-only (B-side) operands
__device__ uint16_t g_xs_h[BN_TOT * NN * DIMC],  g_xs_l[BN_TOT * NN * DIMC];
__device__ uint16_t g_hdw_h[BN_TOT * NN * DIMC], g_hdw_l[BN_TOT * NN * DIMC];
__device__ uint16_t g_pww_h[INNERD * DIMC];                 // B hi only
__device__ uint16_t g_wkvT_h[2 * INNERD * DIMC];            // B hi only
__device__ uint16_t g_woT_h[DIMC * INNERD];                 // B hi only
__device__ uint16_t g_vT_h[BN_TOT * INNERD * NN];           // B hi only
__device__ uint16_t g_attn_h[NB * HH * NN * NN], g_attn_l[NB * HH * NN * NN];
__device__ uint16_t g_oi_h[BN_TOT * NN * INNERD], g_oi_l[BN_TOT * NN * INNERD];
// dots operands: q fp16 2-term, k fp16 hi-only
__device__ uint16_t g_qr_h[NB * HH * NN * RR * DH], g_qr_l[NB * HH * NN * RR * DH];
__device__ uint16_t g_kr_h[NB * HH * NN * RR * DH];

__device__ unsigned char g_mask[BN_TOT * NN];
__device__ float g_has_rows[BN_TOT];
__device__ float g_m_any[NB * NN];
__device__ float g_alpha[NB];
__device__ float g_sin[NN * 32];
__device__ float g_cos[NN * 32];
__device__ int g_mask_mode;

// ========================= helpers ===========================================
__device__ __forceinline__ uint32_t smem_u32(const void* p) {
    uint32_t a;
    asm("{ .reg .u64 t; cvta.to.shared.u64 t, %1; cvt.u32.u64 %0, t; }" : "=r"(a) : "l"(p));
    return a;
}

#define LDSM4(r, addr)                                                          \
    asm volatile("ldmatrix.sync.aligned.m8n8.x4.shared.b16 {%0,%1,%2,%3}, [%4];" \
                 : "=r"((r)[0]), "=r"((r)[1]), "=r"((r)[2]), "=r"((r)[3])       \
                 : "r"(addr))

template <int MODE>   // 0 = bf16, 1 = fp16
__device__ __forceinline__ void mma_t(float* c, const uint32_t* a, const uint32_t* b) {
    if (MODE == 0) {
        asm volatile("mma.sync.aligned.m16n8k16.row.col.f32.bf16.bf16.f32 "
                     "{%0,%1,%2,%3}, {%4,%5,%6,%7}, {%8,%9}, {%0,%1,%2,%3};"
                     : "+f"(c[0]), "+f"(c[1]), "+f"(c[2]), "+f"(c[3])
                     : "r"(a[0]), "r"(a[1]), "r"(a[2]), "r"(a[3]), "r"(b[0]), "r"(b[1]));
    } else {
        asm volatile("mma.sync.aligned.m16n8k16.row.col.f32.f16.f16.f32 "
                     "{%0,%1,%2,%3}, {%4,%5,%6,%7}, {%8,%9}, {%0,%1,%2,%3};"
                     : "+f"(c[0]), "+f"(c[1]), "+f"(c[2]), "+f"(c[3])
                     : "r"(a[0]), "r"(a[1]), "r"(a[2]), "r"(a[3]), "r"(b[0]), "r"(b[1]));
    }
}

#define CP16(dst, src)                                                          \
    asm volatile("cp.async.cg.shared.global [%0], [%1], 16;" :: "r"(dst), "l"(src) : "memory")
#define CP_COMMIT() asm volatile("cp.async.commit_group;" ::: "memory")
#define CP_WAIT1()  asm volatile("cp.async.wait_group 1;" ::: "memory")
#define CP_WAIT0()  asm volatile("cp.async.wait_group 0;" ::: "memory")

// byte offset in a 64B-per-row 16-bit tile (32 k values/row), bank-swizzled
__device__ __forceinline__ uint32_t soff(int row, int kcol) {
    return (uint32_t)(row * 64 + ((kcol * 2) ^ (((row >> 1) & 3) << 4)));
}

// fp16 2-term split: v ≈ hi + lo exactly to ~22 bits
__device__ __forceinline__ void hsplit(float v, uint16_t& h, uint16_t& l) {
    __half hh = __float2half_rn(v);
    h = __half_as_ushort(hh);
    l = __half_as_ushort(__float2half_rn(v - __half2float(hh)));
}
__device__ __forceinline__ uint16_t h16(float v) {
    return __half_as_ushort(__float2half_rn(v));
}

// ========================= mask / small kernels ==============================
__global__ void k_detect(const unsigned char* m) {
    __shared__ int s_high, s_odd;
    if (threadIdx.x == 0) { s_high = 0; s_odd = 0; }
    __syncthreads();
    for (int idx = threadIdx.x; idx < BN_TOT * NN; idx += blockDim.x) {
        unsigned char v = m[idx];
        if (v > 1) s_high = 1;
        if ((idx & 3) && v) s_odd = 1;
    }
    __syncthreads();
    if (threadIdx.x == 0) g_mask_mode = s_high ? 2 : (s_odd ? 0 : 1);
}
__global__ void k_norm_mask(const void* m) {
    int idx = blockIdx.x * blockDim.x + threadIdx.x;
    if (idx >= BN_TOT * NN) return;
    int mode = g_mask_mode;
    unsigned char v;
    if (mode == 0)      v = (((const unsigned char*)m)[idx] != 0);
    else if (mode == 1) v = (((const int*)m)[idx] != 0);
    else                v = (((const float*)m)[idx] != 0.0f);
    g_mask[idx] = v;
}
__global__ void k_hasrows() {
    int bn = blockIdx.x;
    int any = 0;
    for (int j = threadIdx.x; j < NN; j += blockDim.x) any |= g_mask[bn * NN + j];
    __shared__ int s;
    if (threadIdx.x == 0) s = 0;
    __syncthreads();
    if (any) s = 1;
    __syncthreads();
    if (threadIdx.x == 0) g_has_rows[bn] = (float)s;
}
__global__ void k_many() {
    int b = blockIdx.x;
    int i = threadIdx.x;
    int any = 0;
    for (int r = 0; r < RR; r++) any |= g_mask[(b * RR + r) * NN + i];
    g_m_any[b * NN + i] = (float)any;
    if (i == 0) {
        float s = 0.f;
        for (int r = 0; r < RR; r++) s += g_has_rows[b * RR + r];
        g_alpha[b] = (s > 0.f) ? 0.125f * rsqrtf(s) : 0.f;
    }
}
__global__ void k_trig() {
    int i = blockIdx.x;        // 512
    int j = threadIdx.x;       // 32
    float inv = exp2f(-((float)(2 * j) / 64.0f) * 13.287712379549449f);
    float ang = (float)i * inv;
    g_sin[i * 32 + j] = sinf(ang);
    g_cos[i * 32 + j] = cosf(ang);
}

// ---------------- splits / transposes ---------------------------------------
__global__ void k_hsplit(const float* __restrict__ src, uint16_t* __restrict__ h,
                         uint16_t* __restrict__ l, int n) {
    int i = blockIdx.x * blockDim.x + threadIdx.x;
    if (i >= n) return;
    hsplit(src[i], h[i], l[i]);
}
__global__ void k_hi(const float* __restrict__ src, uint16_t* __restrict__ h, int n) {
    int i = blockIdx.x * blockDim.x + threadIdx.x;
    if (i >= n) return;
    h[i] = h16(src[i]);
}
__global__ void k_wkvT(const float* __restrict__ w) {   // (256,1024)->(1024,256) hi
    int i = blockIdx.x * 256 + threadIdx.x;
    int n = i >> 8, k = i & 255;
    g_wkvT_h[i] = h16(w[k * 1024 + n]);
}
__global__ void k_woT(const float* __restrict__ w) {    // (512,256)->(256,512) hi
    int i = blockIdx.x * 256 + threadIdx.x;
    int n = i >> 9, k = i & 511;
    g_woT_h[i] = h16(w[k * 256 + n]);
}
__global__ void k_vT() {   // v (bn, j, hd) -> vT_h[(bn*512+hd)*512 + j]
    __shared__ float t[32][33];
    int bn = blockIdx.z;
    int j0 = blockIdx.x * 32, hd0 = blockIdx.y * 32;
    int lx = threadIdx.x, ly = threadIdx.y;  // 32 x 8
    for (int dy = 0; dy < 32; dy += 8) {
        int j = j0 + ly + dy, hd = hd0 + lx;
        t[ly + dy][lx] = g_v[((size_t)bn * NN + j) * INNERD + hd];
    }
    __syncthreads();
    for (int dy = 0; dy < 32; dy += 8) {
        int hd = hd0 + ly + dy, j = j0 + lx;
        g_vT_h[((size_t)bn * 512 + hd) * 512 + j] = h16(t[lx][ly + dy]);
    }
}

// ---------------- depthwise conv: sliding register window --------------------
// grid (4 segments, 64 bn), 256 threads (one per channel). x read exactly once.
__global__ void __launch_bounds__(256) k_conv2(const float* __restrict__ x,
                                               const float* __restrict__ dww,
                                               const float* __restrict__ dwb) {
    int c = threadIdx.x;
    int bn = blockIdx.y, seg = blockIdx.x;
    int i0 = seg * 128;
    float w[KW];
#pragma unroll
    for (int k = 0; k < KW; k++) w[k] = dww[c * KW + k];
    float bias = dwb[c];
    const float* xr = x + (size_t)bn * NN * DIMC + c;

    float win[KW];
#pragma unroll
    for (int k = 0; k < KW; k++) {
        int ii = i0 - KW / 2 + k;
        win[k] = (ii >= 0 && ii < NN) ? xr[(size_t)ii * DIMC] : 0.f;
    }
    uint16_t* oh = g_hdw_h + ((size_t)bn * NN + i0) * DIMC + c;
    uint16_t* ol = g_hdw_l + ((size_t)bn * NN + i0) * DIMC + c;
    for (int i = i0; i < i0 + 128; i++) {
        float acc = bias;
#pragma unroll
        for (int k = 0; k < KW; k++) acc = fmaf(win[k], w[k], acc);
        uint16_t hh, ll;
        hsplit(acc, hh, ll);
        *oh = hh; *ol = ll;
        oh += DIMC; ol += DIMC;
#pragma unroll
        for (int k = 0; k < KW - 1; k++) win[k] = win[k + 1];
        int ii = i + KW / 2 + 1;
        win[KW - 1] = (ii < NN) ? xr[(size_t)ii * DIMC] : 0.f;
    }
}

// ---------------- masked softmax (writes fp16 split) -------------------------
__global__ void k_softmax() {
    int row = blockIdx.x;
    int b = row >> 12;
    int i = row & 511;
    const float* p = g_dots + (size_t)row * NN;
    float rv = g_m_any[b * NN + i];
    int t = threadIdx.x;

    float m0 = g_m_any[b * NN + t];
    float m1 = g_m_any[b * NN + t + 256];
    float x0 = (rv != 0.f && m0 != 0.f) ? p[t]       : -FLT_MAX;
    float x1 = (rv != 0.f && m1 != 0.f) ? p[t + 256] : -FLT_MAX;

    __shared__ float red[256];
    float mx = fmaxf(x0, x1);
    red[t] = mx;
    __syncthreads();
    for (int s = 128; s > 0; s >>= 1) {
        if (t < s) red[t] = fmaxf(red[t], red[t + s]);
        __syncthreads();
    }
    mx = red[0];
    __syncthreads();
    float e0 = expf(x0 - mx), e1 = expf(x1 - mx);
    red[t] = e0 + e1;
    __syncthreads();
    for (int s = 128; s > 0; s >>= 1) {
        if (t < s) red[t] += red[t + s];
        __syncthreads();
    }
    float inv = 1.0f / red[0];
    size_t o = (size_t)row * NN;
    hsplit(e0 * inv, g_attn_h[o + t],       g_attn_l[o + t]);
    hsplit(e1 * inv, g_attn_h[o + t + 256], g_attn_l[o + t + 256]);
}

// ================== mma.sync split NT GEMM (2-stage cp.async) ================
// MODE 0: bf16 3-term (A hi/lo, B hi/lo).  MODE 1: fp16 2-term (A hi/lo, B hi).
struct GemmP {
    const uint16_t *Ah, *Al; long long lda; long long a_bs;
    const uint16_t *Bh, *Bl; long long ldb; long long b_bs;
    float* C;                                  // fp32 out (or null)
    uint16_t *Ch, *Cl;                         // split out (or null)
    long long ldc; long long c_bs;
    int K;
    const float* bias;
    const float* alpha_vec; int alpha_shift;
    int mode;   // 0 normal batch, 1 = AV addressing
    int emode;  // 0 plain, 1 rotary->qr (has_rows), 2 rotary->kr
};

// rotary epilogue: q -> fp16 2-term (qr_h/qr_l); k -> fp16 hi only (kr_h)
__device__ __forceinline__ void rot_store(int row, int col, float ve, float vo,
                                          bool isq) {
    int i = row & 511, bn = row >> 9;
    int h = col >> 6, d = col & 63, j = d >> 1;
    float s = g_sin[i * 32 + j], c = g_cos[i * 32 + j];
    float oe = ve * c - vo * s;
    float oo = vo * c + ve * s;
    int b = bn >> 5, r = bn & 31;
    size_t dst = (((size_t)(b * HH + h) * NN + i) * (RR * DH)) + r * DH + d;
    if (isq) {
        float hr = g_has_rows[bn];
        oe *= hr; oo *= hr;
        uint16_t h0, l0, h1, l1;
        hsplit(oe, h0, l0); hsplit(oo, h1, l1);
        *(uint32_t*)(g_qr_h + dst) = (uint32_t)h0 | ((uint32_t)h1 << 16);
        *(uint32_t*)(g_qr_l + dst) = (uint32_t)l0 | ((uint32_t)l1 << 16);
    } else {
        *(uint32_t*)(g_kr_h + dst) =
            (uint32_t)h16(oe) | ((uint32_t)h16(oo) << 16);
    }
}

template <int TN, int MODE>
__global__ void __launch_bounds__(256) k_mma(GemmP p) {
    constexpr int NT8 = TN / 32;
    constexpr int NX4 = NT8 / 2;
    constexpr uint32_t SS = (MODE == 0) ? (16384u + TN * 128u) : (16384u + TN * 64u);
    extern __shared__ __align__(128) char dsm[];
    uint32_t sb = smem_u32(dsm);

    int tid = threadIdx.x, wid = tid >> 5, lane = tid & 31;
    int bx = blockIdx.x, by = blockIdx.y, z = blockIdx.z;

    size_t abase, cbase;
    size_t bbase = (size_t)z * p.b_bs + (size_t)bx * TN * p.ldb;
    if (p.mode == 0) {
        abase = (size_t)z * p.a_bs;
        cbase = (size_t)z * p.c_bs;
    } else {                                  // AV: z = bn*8 + h
        int bn = z >> 3, h = z & 7, b = bn >> 5;
        abase = (size_t)(b * HH + h) * p.a_bs;
        cbase = (size_t)bn * p.c_bs + h * 64;
    }
    abase += (size_t)by * 128 * p.lda;
    const uint16_t* Ah = p.Ah + abase;
    const uint16_t* Al = p.Al + abase;
    const uint16_t* Bh = p.Bh + bbase;
    const uint16_t* Bl = (MODE == 0) ? (p.Bl + bbase) : nullptr;

    int m0 = (wid & 1) * 64;
    int n0 = (wid >> 1) * (TN / 4);
    int arow = m0 + (lane & 7) + ((lane >> 3) & 1) * 8;
    int akb  = ((lane >> 4) & 1) * 8;
    int brow = n0 + (lane & 7) + ((lane >> 4) & 1) * 8;
    int bkb  = ((lane >> 3) & 1) * 8;

    float acc[4][NT8][4];
#pragma unroll
    for (int i = 0; i < 4; i++)
#pragma unroll
        for (int j = 0; j < NT8; j++)
#pragma unroll
            for (int q = 0; q < 4; q++) acc[i][j][q] = 0.f;

    int KC = p.K >> 5;

    auto load_stage = [&](int st, int k0) {
        uint32_t base = sb + (uint32_t)st * SS;
#pragma unroll 2
        for (int idx = tid; idx < 512; idx += 256) {
            int row = idx >> 2, c = idx & 3;
            uint32_t off = (uint32_t)(row * 64 + ((c * 16) ^ (((row >> 1) & 3) << 4)));
            CP16(base + off,        Ah + (size_t)row * p.lda + k0 + c * 8);
            CP16(base + 8192 + off, Al + (size_t)row * p.lda + k0 + c * 8);
        }
#pragma unroll 2
        for (int idx = tid; idx < TN * 4; idx += 256) {
            int row = idx >> 2, c = idx & 3;
            uint32_t off = (uint32_t)(row * 64 + ((c * 16) ^ (((row >> 1) & 3) << 4)));
            CP16(base + 16384 + off, Bh + (size_t)row * p.ldb + k0 + c * 8);
            if (MODE == 0)
                CP16(base + 16384 + TN * 64 + off, Bl + (size_t)row * p.ldb + k0 + c * 8);
        }
    };

    load_stage(0, 0);
    CP_COMMIT();

    for (int ch = 0; ch < KC; ch++) {
        if (ch + 1 < KC) {
            load_stage((ch + 1) & 1, (ch + 1) << 5);
            CP_COMMIT();
            CP_WAIT1();
        } else {
            CP_WAIT0();
        }
        __syncthreads();

        uint32_t base = sb + (uint32_t)(ch & 1) * SS;
        uint32_t aHiB = base, aLoB = base + 8192;
        uint32_t bHiB = base + 16384, bLoB = base + 16384 + TN * 64;

#pragma unroll
        for (int kk = 0; kk < 32; kk += 16) {
            uint32_t ah[4][4];
#pragma unroll
            for (int mt = 0; mt < 4; mt++)
                LDSM4(ah[mt], aHiB + soff(arow + mt * 16, kk + akb));
            uint32_t bh[NX4][4];
#pragma unroll
            for (int nx = 0; nx < NX4; nx++)
                LDSM4(bh[nx], bHiB + soff(brow + nx * 16, kk + bkb));
#pragma unroll
            for (int mt = 0; mt < 4; mt++)
#pragma unroll
                for (int nt = 0; nt < NT8; nt++)
                    mma_t<MODE>(acc[mt][nt], ah[mt], &bh[nt >> 1][(nt & 1) * 2]);

            if (MODE == 0) {
                uint32_t bl[NX4][4];
#pragma unroll
                for (int nx = 0; nx < NX4; nx++)
                    LDSM4(bl[nx], bLoB + soff(brow + nx * 16, kk + bkb));
#pragma unroll
                for (int mt = 0; mt < 4; mt++)
#pragma unroll
                    for (int nt = 0; nt < NT8; nt++)
                        mma_t<MODE>(acc[mt][nt], ah[mt], &bl[nt >> 1][(nt & 1) * 2]);
            }

            uint32_t al[4][4];
#pragma unroll
            for (int mt = 0; mt < 4; mt++)
                LDSM4(al[mt], aLoB + soff(arow + mt * 16, kk + akb));
#pragma unroll
            for (int mt = 0; mt < 4; mt++)
#pragma unroll
                for (int nt = 0; nt < NT8; nt++)
                    mma_t<MODE>(acc[mt][nt], al[mt], &bh[nt >> 1][(nt & 1) * 2]);
        }
        __syncthreads();
    }

    // epilogue
    float alpha = p.alpha_vec ? p.alpha_vec[z >> p.alpha_shift] : 1.0f;
    int r0 = by * 128 + m0 + (lane >> 2);
    int c0 = bx * TN + n0 + (lane & 3) * 2;
#pragma unroll
    for (int mt = 0; mt < 4; mt++) {
#pragma unroll
        for (int nt = 0; nt < NT8; nt++) {
            int row = r0 + mt * 16;
            int col = c0 + nt * 8;
            float b0 = 0.f, b1 = 0.f;
            if (p.bias) { b0 = p.bias[col]; b1 = p.bias[col + 1]; }
            float v00 = acc[mt][nt][0] * alpha + b0;
            float v01 = acc[mt][nt][1] * alpha + b1;
            float v10 = acc[mt][nt][2] * alpha + b0;
            float v11 = acc[mt][nt][3] * alpha + b1;
            if (p.emode == 1) {
                rot_store(row, col, v00, v01, true);
                rot_store(row + 8, col, v10, v11, true);
            } else if (p.emode == 2) {
                rot_store(row, col, v00, v01, false);
                rot_store(row + 8, col, v10, v11, false);
            } else {
                if (p.C) {
                    *(float2*)(p.C + cbase + (size_t)row * p.ldc + col) = make_float2(v00, v01);
                    *(float2*)(p.C + cbase + (size_t)(row + 8) * p.ldc + col) = make_float2(v10, v11);
                }
                if (p.Ch) {
                    uint16_t h0, l0, h1, l1;
                    hsplit(v00, h0, l0); hsplit(v01, h1, l1);
                    *(uint32_t*)(p.Ch + cbase + (size_t)row * p.ldc + col) = (uint32_t)h0 | ((uint32_t)h1 << 16);
                    *(uint32_t*)(p.Cl + cbase + (size_t)row * p.ldc + col) = (uint32_t)l0 | ((uint32_t)l1 << 16);
                    hsplit(v10, h0, l0); hsplit(v11, h1, l1);
                    *(uint32_t*)(p.Ch + cbase + (size_t)(row + 8) * p.ldc + col) = (uint32_t)h0 | ((uint32_t)h1 << 16);
                    *(uint32_t*)(p.Cl + cbase + (size_t)(row + 8) * p.ldc + col) = (uint32_t)l0 | ((uint32_t)l1 << 16);
                }
            }
        }
    }
}

// ---------------- launch -----------------------------------------------------
#define SYM(var, sym) decltype(&sym[0]) var; cudaGetSymbolAddress((void**)&var, sym)

extern "C" void kernel_launch(void* const* d_in, const int* in_sizes, int n_in,
                              void* d_out, int out_size) {
    const float* x    = (const float*)d_in[0];
    const void*  mask = d_in[1];
    const float* dw_w = (const float*)d_in[3];
    const float* dw_b = (const float*)d_in[4];
    const float* pw_w = (const float*)d_in[5];
    const float* pw_b = (const float*)d_in[6];
    const float* w_kv = (const float*)d_in[7];
    const float* w_o  = (const float*)d_in[8];
    const float* b_o  = (const float*)d_in[9];
    float* out = (float*)d_out;

    const int SM128_2 = 2 * (16384 + 128 * 64);    // 49152 (fp16 2-term)
    const int SM64_2  = 2 * (16384 + 64 * 64);     // 40960
    cudaFuncSetAttribute(k_mma<128, 1>, cudaFuncAttributeMaxDynamicSharedMemorySize, SM128_2);
    cudaFuncSetAttribute(k_mma<64, 1>,  cudaFuncAttributeMaxDynamicSharedMemorySize, SM64_2);

    SYM(v_p, g_v);  SYM(dots_p, g_dots);
    SYM(xs_h, g_xs_h);    SYM(xs_l, g_xs_l);
    SYM(hdw_h, g_hdw_h);  SYM(hdw_l, g_hdw_l);
    SYM(pww_h, g_pww_h);
    SYM(wkvT_h, g_wkvT_h);
    SYM(woT_h, g_woT_h);
    SYM(qr_h, g_qr_h);    SYM(qr_l, g_qr_l);
    SYM(kr_h, g_kr_h);
    SYM(attn_h, g_attn_h); SYM(attn_l, g_attn_l);
    SYM(vT_h, g_vT_h);
    SYM(oi_h, g_oi_h);    SYM(oi_l, g_oi_l);
    SYM(alpha_p, g_alpha);

    k_detect<<<1, 256>>>((const unsigned char*)mask);
    k_norm_mask<<<(BN_TOT * NN + 255) / 256, 256>>>(mask);
    k_hasrows<<<BN_TOT, 256>>>();
    k_many<<<NB, NN>>>();
    k_trig<<<NN, 32>>>();

    k_hsplit<<<(BN_TOT * NN * DIMC) / 256, 256>>>(x, xs_h, xs_l, BN_TOT * NN * DIMC);
    k_hi<<<(INNERD * DIMC) / 256, 256>>>(pw_w, pww_h, INNERD * DIMC);
    k_wkvT<<<(2 * INNERD * DIMC) / 256, 256>>>(w_kv);
    k_woT<<<(DIMC * INNERD) / 256, 256>>>(w_o);

    k_conv2<<<dim3(4, BN_TOT), 256>>>(x, dw_w, dw_b);

    // qproj + bias + rotary + has_rows -> qr (fp16 2-term)  (M=32768, N=512, K=256)
    {
        GemmP p = {hdw_h, hdw_l, DIMC, 0, pww_h, nullptr, DIMC, 0,
                   nullptr, nullptr, nullptr, 0, 0,
                   DIMC, pw_b, nullptr, 0, 0, 1};
        k_mma<128, 1><<<dim3(4, 256, 1), 256, SM128_2>>>(p);
    }
    // K proj + rotary -> kr (fp16 hi)  (M=32768, N=512, K=256)
    {
        GemmP p = {xs_h, xs_l, DIMC, 0, wkvT_h, nullptr, DIMC, 0,
                   nullptr, nullptr, nullptr, 0, 0,
                   DIMC, nullptr, nullptr, 0, 0, 2};
        k_mma<128, 1><<<dim3(4, 256, 1), 256, SM128_2>>>(p);
    }
    // V proj -> g_v fp32  (M=32768, N=512, K=256)
    {
        GemmP p = {xs_h, xs_l, DIMC, 0, wkvT_h + INNERD * DIMC, nullptr, DIMC, 0,
                   v_p, nullptr, nullptr, INNERD, 0,
                   DIMC, nullptr, nullptr, 0, 0, 0};
        k_mma<128, 1><<<dim3(4, 256, 1), 256, SM128_2>>>(p);
    }
    k_vT<<<dim3(16, 16, BN_TOT), dim3(32, 8)>>>();
    // dots: fp16 2-term, 16 batches, M=N=512, K=2048 -> fp32 (alpha per b)
    {
        GemmP p = {qr_h, qr_l, 2048, (long long)NN * 2048, kr_h, nullptr, 2048, (long long)NN * 2048,
                   dots_p, nullptr, nullptr, NN, (long long)NN * NN,
                   2048, nullptr, alpha_p, 3, 0, 0};
        k_mma<128, 1><<<dim3(4, 4, 16), 256, SM128_2>>>(p);
    }
    k_softmax<<<NB * HH * NN, 256>>>();
    // AV: fp16 2-term, 512 batches (bn,h), M=512, N=64, K=512 -> oi split
    {
        GemmP p = {attn_h, attn_l, NN, (long long)NN * NN, vT_h, nullptr, NN, (long long)DH * NN,
                   nullptr, oi_h, oi_l, INNERD, (long long)NN * INNERD,
                   NN, nullptr, nullptr, 0, 1, 0};
        k_mma<64, 1><<<dim3(1, 4, BN_TOT * HH), 256, SM64_2>>>(p);
    }
    // final: fp16 2-term, M=32768, N=256, K=512 -> out fp32 (+bias)
    {
        GemmP p = {oi_h, oi_l, INNERD, 0, woT_h, nullptr, INNERD, 0,
                   out, nullptr, nullptr, DIMC, 0,
                   INNERD, b_o, nullptr, 0, 0, 0};
        k_mma<128, 1><<<dim3(2, 256, 1), 256, SM128_2>>>(p);
    }
}

// round 9
// speedup vs baseline: 1.6324x; 1.1894x over previous
#include <cuda_runtime.h>
#include <cuda_bf16.h>
#include <cuda_fp16.h>
#include <float.h>
#include <math.h>
#include <stdint.h>

// Problem constants (fixed shapes)
#define BN_TOT 64      // b*r
#define NB 2           // b
#define RR 32          // r
#define NN 512         // n
#define DIMC 256       // DIM
#define HH 8           // heads
#define DH 64          // dim_head
#define INNERD 512     // HH*DH
#define KW 15          // conv kernel

// ---------------- scratch (device globals; no allocations allowed) ----------
__device__ float g_v[BN_TOT * NN * INNERD];         // v fp32 (bn, i, hd)
__device__ float g_dots[NB * HH * NN * NN];         // logits fp32

// fp16 operands: _h/_l = 2-term A-side, _h alone = hi-only
__device__ uint16_t g_xs_h[BN_TOT * NN * DIMC],  g_xs_l[BN_TOT * NN * DIMC];
__device__ uint16_t g_hdw_h[BN_TOT * NN * DIMC], g_hdw_l[BN_TOT * NN * DIMC];
__device__ uint16_t g_pww_h[INNERD * DIMC];
__device__ uint16_t g_wkvT_h[2 * INNERD * DIMC];
__device__ uint16_t g_woT_h[DIMC * INNERD];
__device__ uint16_t g_vT_h[BN_TOT * INNERD * NN];
__device__ uint16_t g_attn_h[NB * HH * NN * NN];            // hi only
__device__ uint16_t g_oi_h[BN_TOT * NN * INNERD], g_oi_l[BN_TOT * NN * INNERD];
__device__ uint16_t g_qr_h[NB * HH * NN * RR * DH];         // hi only
__device__ uint16_t g_kr_h[NB * HH * NN * RR * DH];         // hi only

__device__ unsigned char g_mask[BN_TOT * NN];
__device__ float g_has_rows[BN_TOT];
__device__ float g_m_any[NB * NN];
__device__ float g_alpha[NB];
__device__ float g_sin[NN * 32];
__device__ float g_cos[NN * 32];
__device__ int g_mask_mode;

// ========================= helpers ===========================================
__device__ __forceinline__ uint32_t smem_u32(const void* p) {
    uint32_t a;
    asm("{ .reg .u64 t; cvta.to.shared.u64 t, %1; cvt.u32.u64 %0, t; }" : "=r"(a) : "l"(p));
    return a;
}

#define LDSM4(r, addr)                                                          \
    asm volatile("ldmatrix.sync.aligned.m8n8.x4.shared.b16 {%0,%1,%2,%3}, [%4];" \
                 : "=r"((r)[0]), "=r"((r)[1]), "=r"((r)[2]), "=r"((r)[3])       \
                 : "r"(addr))

__device__ __forceinline__ void mma_h(float* c, const uint32_t* a, const uint32_t* b) {
    asm volatile("mma.sync.aligned.m16n8k16.row.col.f32.f16.f16.f32 "
                 "{%0,%1,%2,%3}, {%4,%5,%6,%7}, {%8,%9}, {%0,%1,%2,%3};"
                 : "+f"(c[0]), "+f"(c[1]), "+f"(c[2]), "+f"(c[3])
                 : "r"(a[0]), "r"(a[1]), "r"(a[2]), "r"(a[3]), "r"(b[0]), "r"(b[1]));
}

#define CP16(dst, src)                                                          \
    asm volatile("cp.async.cg.shared.global [%0], [%1], 16;" :: "r"(dst), "l"(src) : "memory")
#define CP_COMMIT() asm volatile("cp.async.commit_group;" ::: "memory")
#define CP_WAIT1()  asm volatile("cp.async.wait_group 1;" ::: "memory")
#define CP_WAIT0()  asm volatile("cp.async.wait_group 0;" ::: "memory")

// byte offset in a 64B-per-row 16-bit tile (32 k values/row), bank-swizzled
__device__ __forceinline__ uint32_t soff(int row, int kcol) {
    return (uint32_t)(row * 64 + ((kcol * 2) ^ (((row >> 1) & 3) << 4)));
}

// fp16 2-term split: v ≈ hi + lo exactly to ~22 bits
__device__ __forceinline__ void hsplit(float v, uint16_t& h, uint16_t& l) {
    __half hh = __float2half_rn(v);
    h = __half_as_ushort(hh);
    l = __half_as_ushort(__float2half_rn(v - __half2float(hh)));
}
__device__ __forceinline__ uint16_t h16(float v) {
    return __half_as_ushort(__float2half_rn(v));
}

// ========================= mask / small kernels ==============================
__global__ void k_detect(const unsigned char* m) {
    __shared__ int s_high, s_odd;
    if (threadIdx.x == 0) { s_high = 0; s_odd = 0; }
    __syncthreads();
    for (int idx = threadIdx.x; idx < BN_TOT * NN; idx += blockDim.x) {
        unsigned char v = m[idx];
        if (v > 1) s_high = 1;
        if ((idx & 3) && v) s_odd = 1;
    }
    __syncthreads();
    if (threadIdx.x == 0) g_mask_mode = s_high ? 2 : (s_odd ? 0 : 1);
}
__global__ void k_norm_mask(const void* m) {
    int idx = blockIdx.x * blockDim.x + threadIdx.x;
    if (idx >= BN_TOT * NN) return;
    int mode = g_mask_mode;
    unsigned char v;
    if (mode == 0)      v = (((const unsigned char*)m)[idx] != 0);
    else if (mode == 1) v = (((const int*)m)[idx] != 0);
    else                v = (((const float*)m)[idx] != 0.0f);
    g_mask[idx] = v;
}
__global__ void k_hasrows() {
    int bn = blockIdx.x;
    int any = 0;
    for (int j = threadIdx.x; j < NN; j += blockDim.x) any |= g_mask[bn * NN + j];
    __shared__ int s;
    if (threadIdx.x == 0) s = 0;
    __syncthreads();
    if (any) s = 1;
    __syncthreads();
    if (threadIdx.x == 0) g_has_rows[bn] = (float)s;
}
__global__ void k_many() {
    int b = blockIdx.x;
    int i = threadIdx.x;
    int any = 0;
    for (int r = 0; r < RR; r++) any |= g_mask[(b * RR + r) * NN + i];
    g_m_any[b * NN + i] = (float)any;
    if (i == 0) {
        float s = 0.f;
        for (int r = 0; r < RR; r++) s += g_has_rows[b * RR + r];
        g_alpha[b] = (s > 0.f) ? 0.125f * rsqrtf(s) : 0.f;
    }
}
__global__ void k_trig() {
    int i = blockIdx.x;        // 512
    int j = threadIdx.x;       // 32
    float inv = exp2f(-((float)(2 * j) / 64.0f) * 13.287712379549449f);
    float ang = (float)i * inv;
    g_sin[i * 32 + j] = sinf(ang);
    g_cos[i * 32 + j] = cosf(ang);
}

// ---------------- splits / transposes ---------------------------------------
__global__ void k_hsplit(const float* __restrict__ src, uint16_t* __restrict__ h,
                         uint16_t* __restrict__ l, int n) {
    int i = blockIdx.x * blockDim.x + threadIdx.x;
    if (i >= n) return;
    hsplit(src[i], h[i], l[i]);
}
__global__ void k_hi(const float* __restrict__ src, uint16_t* __restrict__ h, int n) {
    int i = blockIdx.x * blockDim.x + threadIdx.x;
    if (i >= n) return;
    h[i] = h16(src[i]);
}
__global__ void k_wkvT(const float* __restrict__ w) {   // (256,1024)->(1024,256) hi
    int i = blockIdx.x * 256 + threadIdx.x;
    int n = i >> 8, k = i & 255;
    g_wkvT_h[i] = h16(w[k * 1024 + n]);
}
__global__ void k_woT(const float* __restrict__ w) {    // (512,256)->(256,512) hi
    int i = blockIdx.x * 256 + threadIdx.x;
    int n = i >> 9, k = i & 511;
    g_woT_h[i] = h16(w[k * 256 + n]);
}
__global__ void k_vT() {   // v (bn, j, hd) -> vT_h[(bn*512+hd)*512 + j]
    __shared__ float t[32][33];
    int bn = blockIdx.z;
    int j0 = blockIdx.x * 32, hd0 = blockIdx.y * 32;
    int lx = threadIdx.x, ly = threadIdx.y;  // 32 x 8
    for (int dy = 0; dy < 32; dy += 8) {
        int j = j0 + ly + dy, hd = hd0 + lx;
        t[ly + dy][lx] = g_v[((size_t)bn * NN + j) * INNERD + hd];
    }
    __syncthreads();
    for (int dy = 0; dy < 32; dy += 8) {
        int hd = hd0 + ly + dy, j = j0 + lx;
        g_vT_h[((size_t)bn * 512 + hd) * 512 + j] = h16(t[lx][ly + dy]);
    }
}

// ---------------- depthwise conv: sliding register window --------------------
__global__ void __launch_bounds__(256) k_conv2(const float* __restrict__ x,
                                               const float* __restrict__ dww,
                                               const float* __restrict__ dwb) {
    int c = threadIdx.x;
    int bn = blockIdx.y, seg = blockIdx.x;
    int i0 = seg * 128;
    float w[KW];
#pragma unroll
    for (int k = 0; k < KW; k++) w[k] = dww[c * KW + k];
    float bias = dwb[c];
    const float* xr = x + (size_t)bn * NN * DIMC + c;

    float win[KW];
#pragma unroll
    for (int k = 0; k < KW; k++) {
        int ii = i0 - KW / 2 + k;
        win[k] = (ii >= 0 && ii < NN) ? xr[(size_t)ii * DIMC] : 0.f;
    }
    uint16_t* oh = g_hdw_h + ((size_t)bn * NN + i0) * DIMC + c;
    uint16_t* ol = g_hdw_l + ((size_t)bn * NN + i0) * DIMC + c;
    for (int i = i0; i < i0 + 128; i++) {
        float acc = bias;
#pragma unroll
        for (int k = 0; k < KW; k++) acc = fmaf(win[k], w[k], acc);
        uint16_t hh, ll;
        hsplit(acc, hh, ll);
        *oh = hh; *ol = ll;
        oh += DIMC; ol += DIMC;
#pragma unroll
        for (int k = 0; k < KW - 1; k++) win[k] = win[k + 1];
        int ii = i + KW / 2 + 1;
        win[KW - 1] = (ii < NN) ? xr[(size_t)ii * DIMC] : 0.f;
    }
}

// ---------------- masked softmax (writes fp16 hi) ----------------------------
__global__ void k_softmax() {
    int row = blockIdx.x;
    int b = row >> 12;
    int i = row & 511;
    const float* p = g_dots + (size_t)row * NN;
    float rv = g_m_any[b * NN + i];
    int t = threadIdx.x;

    float m0 = g_m_any[b * NN + t];
    float m1 = g_m_any[b * NN + t + 256];
    float x0 = (rv != 0.f && m0 != 0.f) ? p[t]       : -FLT_MAX;
    float x1 = (rv != 0.f && m1 != 0.f) ? p[t + 256] : -FLT_MAX;

    __shared__ float red[256];
    float mx = fmaxf(x0, x1);
    red[t] = mx;
    __syncthreads();
    for (int s = 128; s > 0; s >>= 1) {
        if (t < s) red[t] = fmaxf(red[t], red[t + s]);
        __syncthreads();
    }
    mx = red[0];
    __syncthreads();
    float e0 = expf(x0 - mx), e1 = expf(x1 - mx);
    red[t] = e0 + e1;
    __syncthreads();
    for (int s = 128; s > 0; s >>= 1) {
        if (t < s) red[t] += red[t + s];
        __syncthreads();
    }
    float inv = 1.0f / red[0];
    size_t o = (size_t)row * NN;
    g_attn_h[o + t]       = h16(e0 * inv);
    g_attn_h[o + t + 256] = h16(e1 * inv);
}

// ================== mma.sync fp16 NT GEMM (2-stage cp.async) =================
// MODE 1: A 2-term (hi+lo), B hi.  MODE 2: A hi, B hi (single MMA).
struct GemmP {
    const uint16_t *Ah, *Al; long long lda; long long a_bs;
    const uint16_t *Bh; long long ldb; long long b_bs;
    float* C;                                  // fp32 out (or null)
    uint16_t *Ch, *Cl;                         // split out (or null)
    long long ldc; long long c_bs;
    int K;
    const float* bias;
    const float* alpha_vec; int alpha_shift;
    int mode;   // 0 normal batch, 1 = AV addressing
    int emode;  // 0 plain, 1 rotary->qr hi (has_rows), 2 rotary->kr hi
};

// rotary epilogue: write fp16 hi-only q/k in (b,h,i,r*64+d) layout
__device__ __forceinline__ void rot_store(int row, int col, float ve, float vo,
                                          bool isq) {
    int i = row & 511, bn = row >> 9;
    int h = col >> 6, d = col & 63, j = d >> 1;
    float s = g_sin[i * 32 + j], c = g_cos[i * 32 + j];
    float oe = ve * c - vo * s;
    float oo = vo * c + ve * s;
    int b = bn >> 5, r = bn & 31;
    size_t dst = (((size_t)(b * HH + h) * NN + i) * (RR * DH)) + r * DH + d;
    if (isq) {
        float hr = g_has_rows[bn];
        oe *= hr; oo *= hr;
        *(uint32_t*)(g_qr_h + dst) = (uint32_t)h16(oe) | ((uint32_t)h16(oo) << 16);
    } else {
        *(uint32_t*)(g_kr_h + dst) = (uint32_t)h16(oe) | ((uint32_t)h16(oo) << 16);
    }
}

template <int TN, int MODE>
__global__ void __launch_bounds__(256) k_mma(GemmP p) {
    constexpr int NT8 = TN / 32;
    constexpr int NX4 = NT8 / 2;
    constexpr uint32_t ABY = (MODE == 2) ? 8192u : 16384u;
    constexpr uint32_t SS = ABY + TN * 64u;    // stage stride bytes
    extern __shared__ __align__(128) char dsm[];
    uint32_t sb = smem_u32(dsm);

    int tid = threadIdx.x, wid = tid >> 5, lane = tid & 31;
    int bx = blockIdx.x, by = blockIdx.y, z = blockIdx.z;

    size_t abase, cbase;
    size_t bbase = (size_t)z * p.b_bs + (size_t)bx * TN * p.ldb;
    if (p.mode == 0) {
        abase = (size_t)z * p.a_bs;
        cbase = (size_t)z * p.c_bs;
    } else {                                  // AV: z = bn*8 + h
        int bn = z >> 3, h = z & 7, b = bn >> 5;
        abase = (size_t)(b * HH + h) * p.a_bs;
        cbase = (size_t)bn * p.c_bs + h * 64;
    }
    abase += (size_t)by * 128 * p.lda;
    const uint16_t* Ah = p.Ah + abase;
    const uint16_t* Al = (MODE == 1) ? (p.Al + abase) : nullptr;
    const uint16_t* Bh = p.Bh + bbase;

    int m0 = (wid & 1) * 64;
    int n0 = (wid >> 1) * (TN / 4);
    int arow = m0 + (lane & 7) + ((lane >> 3) & 1) * 8;
    int akb  = ((lane >> 4) & 1) * 8;
    int brow = n0 + (lane & 7) + ((lane >> 4) & 1) * 8;
    int bkb  = ((lane >> 3) & 1) * 8;

    float acc[4][NT8][4];
#pragma unroll
    for (int i = 0; i < 4; i++)
#pragma unroll
        for (int j = 0; j < NT8; j++)
#pragma unroll
            for (int q = 0; q < 4; q++) acc[i][j][q] = 0.f;

    int KC = p.K >> 5;

    auto load_stage = [&](int st, int k0) {
        uint32_t base = sb + (uint32_t)st * SS;
#pragma unroll 2
        for (int idx = tid; idx < 512; idx += 256) {
            int row = idx >> 2, c = idx & 3;
            uint32_t off = (uint32_t)(row * 64 + ((c * 16) ^ (((row >> 1) & 3) << 4)));
            CP16(base + off, Ah + (size_t)row * p.lda + k0 + c * 8);
            if (MODE == 1)
                CP16(base + 8192 + off, Al + (size_t)row * p.lda + k0 + c * 8);
        }
#pragma unroll 2
        for (int idx = tid; idx < TN * 4; idx += 256) {
            int row = idx >> 2, c = idx & 3;
            uint32_t off = (uint32_t)(row * 64 + ((c * 16) ^ (((row >> 1) & 3) << 4)));
            CP16(base + ABY + off, Bh + (size_t)row * p.ldb + k0 + c * 8);
        }
    };

    load_stage(0, 0);
    CP_COMMIT();

    for (int ch = 0; ch < KC; ch++) {
        if (ch + 1 < KC) {
            load_stage((ch + 1) & 1, (ch + 1) << 5);
            CP_COMMIT();
            CP_WAIT1();
        } else {
            CP_WAIT0();
        }
        __syncthreads();

        uint32_t base = sb + (uint32_t)(ch & 1) * SS;
        uint32_t aHiB = base, aLoB = base + 8192;
        uint32_t bHiB = base + ABY;

#pragma unroll
        for (int kk = 0; kk < 32; kk += 16) {
            uint32_t ah[4][4];
#pragma unroll
            for (int mt = 0; mt < 4; mt++)
                LDSM4(ah[mt], aHiB + soff(arow + mt * 16, kk + akb));
            uint32_t bh[NX4][4];
#pragma unroll
            for (int nx = 0; nx < NX4; nx++)
                LDSM4(bh[nx], bHiB + soff(brow + nx * 16, kk + bkb));
#pragma unroll
            for (int mt = 0; mt < 4; mt++)
#pragma unroll
                for (int nt = 0; nt < NT8; nt++)
                    mma_h(acc[mt][nt], ah[mt], &bh[nt >> 1][(nt & 1) * 2]);

            if (MODE == 1) {
                uint32_t al[4][4];
#pragma unroll
                for (int mt = 0; mt < 4; mt++)
                    LDSM4(al[mt], aLoB + soff(arow + mt * 16, kk + akb));
#pragma unroll
                for (int mt = 0; mt < 4; mt++)
#pragma unroll
                    for (int nt = 0; nt < NT8; nt++)
                        mma_h(acc[mt][nt], al[mt], &bh[nt >> 1][(nt & 1) * 2]);
            }
        }
        __syncthreads();
    }

    // epilogue
    float alpha = p.alpha_vec ? p.alpha_vec[z >> p.alpha_shift] : 1.0f;
    int r0 = by * 128 + m0 + (lane >> 2);
    int c0 = bx * TN + n0 + (lane & 3) * 2;
#pragma unroll
    for (int mt = 0; mt < 4; mt++) {
#pragma unroll
        for (int nt = 0; nt < NT8; nt++) {
            int row = r0 + mt * 16;
            int col = c0 + nt * 8;
            float b0 = 0.f, b1 = 0.f;
            if (p.bias) { b0 = p.bias[col]; b1 = p.bias[col + 1]; }
            float v00 = acc[mt][nt][0] * alpha + b0;
            float v01 = acc[mt][nt][1] * alpha + b1;
            float v10 = acc[mt][nt][2] * alpha + b0;
            float v11 = acc[mt][nt][3] * alpha + b1;
            if (p.emode == 1) {
                rot_store(row, col, v00, v01, true);
                rot_store(row + 8, col, v10, v11, true);
            } else if (p.emode == 2) {
                rot_store(row, col, v00, v01, false);
                rot_store(row + 8, col, v10, v11, false);
            } else {
                if (p.C) {
                    *(float2*)(p.C + cbase + (size_t)row * p.ldc + col) = make_float2(v00, v01);
                    *(float2*)(p.C + cbase + (size_t)(row + 8) * p.ldc + col) = make_float2(v10, v11);
                }
                if (p.Ch) {
                    uint16_t h0, l0, h1, l1;
                    hsplit(v00, h0, l0); hsplit(v01, h1, l1);
                    *(uint32_t*)(p.Ch + cbase + (size_t)row * p.ldc + col) = (uint32_t)h0 | ((uint32_t)h1 << 16);
                    *(uint32_t*)(p.Cl + cbase + (size_t)row * p.ldc + col) = (uint32_t)l0 | ((uint32_t)l1 << 16);
                    hsplit(v10, h0, l0); hsplit(v11, h1, l1);
                    *(uint32_t*)(p.Ch + cbase + (size_t)(row + 8) * p.ldc + col) = (uint32_t)h0 | ((uint32_t)h1 << 16);
                    *(uint32_t*)(p.Cl + cbase + (size_t)(row + 8) * p.ldc + col) = (uint32_t)l0 | ((uint32_t)l1 << 16);
                }
            }
        }
    }
}

// ---------------- launch -----------------------------------------------------
#define SYM(var, sym) decltype(&sym[0]) var; cudaGetSymbolAddress((void**)&var, sym)

extern "C" void kernel_launch(void* const* d_in, const int* in_sizes, int n_in,
                              void* d_out, int out_size) {
    const float* x    = (const float*)d_in[0];
    const void*  mask = d_in[1];
    const float* dw_w = (const float*)d_in[3];
    const float* dw_b = (const float*)d_in[4];
    const float* pw_w = (const float*)d_in[5];
    const float* pw_b = (const float*)d_in[6];
    const float* w_kv = (const float*)d_in[7];
    const float* w_o  = (const float*)d_in[8];
    const float* b_o  = (const float*)d_in[9];
    float* out = (float*)d_out;

    const int SM128_1 = 2 * (16384 + 128 * 64);   // 49152 (A 2-term)
    const int SM128_2 = 2 * (8192 + 128 * 64);    // 32768 (A hi-only)
    const int SM64_2  = 2 * (8192 + 64 * 64);     // 24576
    cudaFuncSetAttribute(k_mma<128, 1>, cudaFuncAttributeMaxDynamicSharedMemorySize, SM128_1);
    cudaFuncSetAttribute(k_mma<128, 2>, cudaFuncAttributeMaxDynamicSharedMemorySize, SM128_2);
    cudaFuncSetAttribute(k_mma<64, 2>,  cudaFuncAttributeMaxDynamicSharedMemorySize, SM64_2);

    SYM(v_p, g_v);  SYM(dots_p, g_dots);
    SYM(xs_h, g_xs_h);    SYM(xs_l, g_xs_l);
    SYM(hdw_h, g_hdw_h);  SYM(hdw_l, g_hdw_l);
    SYM(pww_h, g_pww_h);
    SYM(wkvT_h, g_wkvT_h);
    SYM(woT_h, g_woT_h);
    SYM(qr_h, g_qr_h);
    SYM(kr_h, g_kr_h);
    SYM(attn_h, g_attn_h);
    SYM(vT_h, g_vT_h);
    SYM(oi_h, g_oi_h);    SYM(oi_l, g_oi_l);
    SYM(alpha_p, g_alpha);

    k_detect<<<1, 256>>>((const unsigned char*)mask);
    k_norm_mask<<<(BN_TOT * NN + 255) / 256, 256>>>(mask);
    k_hasrows<<<BN_TOT, 256>>>();
    k_many<<<NB, NN>>>();
    k_trig<<<NN, 32>>>();

    k_hsplit<<<(BN_TOT * NN * DIMC) / 256, 256>>>(x, xs_h, xs_l, BN_TOT * NN * DIMC);
    k_hi<<<(INNERD * DIMC) / 256, 256>>>(pw_w, pww_h, INNERD * DIMC);
    k_wkvT<<<(2 * INNERD * DIMC) / 256, 256>>>(w_kv);
    k_woT<<<(DIMC * INNERD) / 256, 256>>>(w_o);

    k_conv2<<<dim3(4, BN_TOT), 256>>>(x, dw_w, dw_b);

    // qproj + bias + rotary + has_rows -> qr hi  (M=32768, N=512, K=256)
    {
        GemmP p = {hdw_h, hdw_l, DIMC, 0, pww_h, DIMC, 0,
                   nullptr, nullptr, nullptr, 0, 0,
                   DIMC, pw_b, nullptr, 0, 0, 1};
        k_mma<128, 1><<<dim3(4, 256, 1), 256, SM128_1>>>(p);
    }
    // K proj + rotary -> kr hi  (M=32768, N=512, K=256)
    {
        GemmP p = {xs_h, xs_l, DIMC, 0, wkvT_h, DIMC, 0,
                   nullptr, nullptr, nullptr, 0, 0,
                   DIMC, nullptr, nullptr, 0, 0, 2};
        k_mma<128, 1><<<dim3(4, 256, 1), 256, SM128_1>>>(p);
    }
    // V proj -> g_v fp32  (M=32768, N=512, K=256)
    {
        GemmP p = {xs_h, xs_l, DIMC, 0, wkvT_h + INNERD * DIMC, DIMC, 0,
                   v_p, nullptr, nullptr, INNERD, 0,
                   DIMC, nullptr, nullptr, 0, 0, 0};
        k_mma<128, 1><<<dim3(4, 256, 1), 256, SM128_1>>>(p);
    }
    k_vT<<<dim3(16, 16, BN_TOT), dim3(32, 8)>>>();
    // dots: A hi, B hi — 16 batches, M=N=512, K=2048 -> fp32 (alpha per b)
    {
        GemmP p = {qr_h, nullptr, 2048, (long long)NN * 2048, kr_h, 2048, (long long)NN * 2048,
                   dots_p, nullptr, nullptr, NN, (long long)NN * NN,
                   2048, nullptr, alpha_p, 3, 0, 0};
        k_mma<128, 2><<<dim3(4, 4, 16), 256, SM128_2>>>(p);
    }
    k_softmax<<<NB * HH * NN, 256>>>();
    // AV: A hi, B hi — 512 batches (bn,h), M=512, N=64, K=512 -> oi split
    {
        GemmP p = {attn_h, nullptr, NN, (long long)NN * NN, vT_h, NN, (long long)DH * NN,
                   nullptr, oi_h, oi_l, INNERD, (long long)NN * INNERD,
                   NN, nullptr, nullptr, 0, 1, 0};
        k_mma<64, 2><<<dim3(1, 4, BN_TOT * HH), 256, SM64_2>>>(p);
    }
    // final: A 2-term, M=32768, N=256, K=512 -> out fp32 (+bias)
    {
        GemmP p = {oi_h, oi_l, INNERD, 0, woT_h, INNERD, 0,
                   out, nullptr, nullptr, DIMC, 0,
                   INNERD, b_o, nullptr, 0, 0, 0};
        k_mma<128, 1><<<dim3(2, 256, 1), 256, SM128_1>>>(p);
    }
}

// round 10
// speedup vs baseline: 1.8838x; 1.1540x over previous
#include <cuda_runtime.h>
#include <cuda_bf16.h>
#include <cuda_fp16.h>
#include <float.h>
#include <math.h>
#include <stdint.h>

// Problem constants (fixed shapes)
#define BN_TOT 64      // b*r
#define NB 2           // b
#define RR 32          // r
#define NN 512         // n
#define DIMC 256       // DIM
#define HH 8           // heads
#define DH 64          // dim_head
#define INNERD 512     // HH*DH
#define KW 15          // conv kernel

// ---------------- scratch (device globals; no allocations allowed) ----------
__device__ float g_v[BN_TOT * NN * INNERD];         // v fp32 (bn, i, hd)
__device__ float g_dots[NB * HH * NN * NN];         // logits fp32

// fp16 operands: _h/_l = 2-term A-side, _h alone = hi-only
__device__ uint16_t g_xs_h[BN_TOT * NN * DIMC];             // hi only
__device__ uint16_t g_hdw_h[BN_TOT * NN * DIMC];            // hi only
__device__ uint16_t g_pww_h[INNERD * DIMC];
__device__ uint16_t g_wkvT_h[2 * INNERD * DIMC];
__device__ uint16_t g_woT_h[DIMC * INNERD];
__device__ uint16_t g_vT_h[BN_TOT * INNERD * NN];
__device__ uint16_t g_attn_h[NB * HH * NN * NN];            // hi only
__device__ uint16_t g_oi_h[BN_TOT * NN * INNERD], g_oi_l[BN_TOT * NN * INNERD];
__device__ uint16_t g_qr_h[NB * HH * NN * RR * DH];         // hi only
__device__ uint16_t g_kr_h[NB * HH * NN * RR * DH];         // hi only

__device__ unsigned char g_mask[BN_TOT * NN];
__device__ float g_has_rows[BN_TOT];
__device__ float g_m_any[NB * NN];
__device__ float g_alpha[NB];
__device__ float g_sin[NN * 32];
__device__ float g_cos[NN * 32];
__device__ int g_mask_mode;

// ========================= helpers ===========================================
__device__ __forceinline__ uint32_t smem_u32(const void* p) {
    uint32_t a;
    asm("{ .reg .u64 t; cvta.to.shared.u64 t, %1; cvt.u32.u64 %0, t; }" : "=r"(a) : "l"(p));
    return a;
}

#define LDSM4(r, addr)                                                          \
    asm volatile("ldmatrix.sync.aligned.m8n8.x4.shared.b16 {%0,%1,%2,%3}, [%4];" \
                 : "=r"((r)[0]), "=r"((r)[1]), "=r"((r)[2]), "=r"((r)[3])       \
                 : "r"(addr))

__device__ __forceinline__ void mma_h(float* c, const uint32_t* a, const uint32_t* b) {
    asm volatile("mma.sync.aligned.m16n8k16.row.col.f32.f16.f16.f32 "
                 "{%0,%1,%2,%3}, {%4,%5,%6,%7}, {%8,%9}, {%0,%1,%2,%3};"
                 : "+f"(c[0]), "+f"(c[1]), "+f"(c[2]), "+f"(c[3])
                 : "r"(a[0]), "r"(a[1]), "r"(a[2]), "r"(a[3]), "r"(b[0]), "r"(b[1]));
}

#define CP16(dst, src)                                                          \
    asm volatile("cp.async.cg.shared.global [%0], [%1], 16;" :: "r"(dst), "l"(src) : "memory")
#define CP_COMMIT() asm volatile("cp.async.commit_group;" ::: "memory")
#define CP_WAIT1()  asm volatile("cp.async.wait_group 1;" ::: "memory")
#define CP_WAIT0()  asm volatile("cp.async.wait_group 0;" ::: "memory")

// byte offset in a 64B-per-row 16-bit tile (32 k values/row), bank-swizzled
__device__ __forceinline__ uint32_t soff(int row, int kcol) {
    return (uint32_t)(row * 64 + ((kcol * 2) ^ (((row >> 1) & 3) << 4)));
}

// fp16 2-term split: v ≈ hi + lo exactly to ~22 bits
__device__ __forceinline__ void hsplit(float v, uint16_t& h, uint16_t& l) {
    __half hh = __float2half_rn(v);
    h = __half_as_ushort(hh);
    l = __half_as_ushort(__float2half_rn(v - __half2float(hh)));
}
__device__ __forceinline__ uint16_t h16(float v) {
    return __half_as_ushort(__float2half_rn(v));
}

// ========================= mask / small kernels ==============================
__global__ void k_detect(const unsigned char* m) {
    __shared__ int s_high, s_odd;
    if (threadIdx.x == 0) { s_high = 0; s_odd = 0; }
    __syncthreads();
    for (int idx = threadIdx.x; idx < BN_TOT * NN; idx += blockDim.x) {
        unsigned char v = m[idx];
        if (v > 1) s_high = 1;
        if ((idx & 3) && v) s_odd = 1;
    }
    __syncthreads();
    if (threadIdx.x == 0) g_mask_mode = s_high ? 2 : (s_odd ? 0 : 1);
}
__global__ void k_norm_mask(const void* m) {
    int idx = blockIdx.x * blockDim.x + threadIdx.x;
    if (idx >= BN_TOT * NN) return;
    int mode = g_mask_mode;
    unsigned char v;
    if (mode == 0)      v = (((const unsigned char*)m)[idx] != 0);
    else if (mode == 1) v = (((const int*)m)[idx] != 0);
    else                v = (((const float*)m)[idx] != 0.0f);
    g_mask[idx] = v;
}
__global__ void k_hasrows() {
    int bn = blockIdx.x;
    int any = 0;
    for (int j = threadIdx.x; j < NN; j += blockDim.x) any |= g_mask[bn * NN + j];
    __shared__ int s;
    if (threadIdx.x == 0) s = 0;
    __syncthreads();
    if (any) s = 1;
    __syncthreads();
    if (threadIdx.x == 0) g_has_rows[bn] = (float)s;
}
__global__ void k_many() {
    int b = blockIdx.x;
    int i = threadIdx.x;
    int any = 0;
    for (int r = 0; r < RR; r++) any |= g_mask[(b * RR + r) * NN + i];
    g_m_any[b * NN + i] = (float)any;
    if (i == 0) {
        float s = 0.f;
        for (int r = 0; r < RR; r++) s += g_has_rows[b * RR + r];
        g_alpha[b] = (s > 0.f) ? 0.125f * rsqrtf(s) : 0.f;
    }
}
__global__ void k_trig() {
    int i = blockIdx.x;        // 512
    int j = threadIdx.x;       // 32
    float inv = exp2f(-((float)(2 * j) / 64.0f) * 13.287712379549449f);
    float ang = (float)i * inv;
    g_sin[i * 32 + j] = sinf(ang);
    g_cos[i * 32 + j] = cosf(ang);
}

// ---------------- splits / transposes ---------------------------------------
__global__ void k_hi(const float* __restrict__ src, uint16_t* __restrict__ h, int n) {
    int i = blockIdx.x * blockDim.x + threadIdx.x;
    if (i >= n) return;
    h[i] = h16(src[i]);
}
__global__ void k_wkvT(const float* __restrict__ w) {   // (256,1024)->(1024,256) hi
    int i = blockIdx.x * 256 + threadIdx.x;
    int n = i >> 8, k = i & 255;
    g_wkvT_h[i] = h16(w[k * 1024 + n]);
}
__global__ void k_woT(const float* __restrict__ w) {    // (512,256)->(256,512) hi
    int i = blockIdx.x * 256 + threadIdx.x;
    int n = i >> 9, k = i & 511;
    g_woT_h[i] = h16(w[k * 256 + n]);
}
__global__ void k_vT() {   // v (bn, j, hd) -> vT_h[(bn*512+hd)*512 + j]
    __shared__ float t[32][33];
    int bn = blockIdx.z;
    int j0 = blockIdx.x * 32, hd0 = blockIdx.y * 32;
    int lx = threadIdx.x, ly = threadIdx.y;  // 32 x 8
    for (int dy = 0; dy < 32; dy += 8) {
        int j = j0 + ly + dy, hd = hd0 + lx;
        t[ly + dy][lx] = g_v[((size_t)bn * NN + j) * INNERD + hd];
    }
    __syncthreads();
    for (int dy = 0; dy < 32; dy += 8) {
        int hd = hd0 + ly + dy, j = j0 + lx;
        g_vT_h[((size_t)bn * 512 + hd) * 512 + j] = h16(t[lx][ly + dy]);
    }
}

// ---------------- depthwise conv: sliding register window --------------------
__global__ void __launch_bounds__(256) k_conv2(const float* __restrict__ x,
                                               const float* __restrict__ dww,
                                               const float* __restrict__ dwb) {
    int c = threadIdx.x;
    int bn = blockIdx.y, seg = blockIdx.x;
    int i0 = seg * 128;
    float w[KW];
#pragma unroll
    for (int k = 0; k < KW; k++) w[k] = dww[c * KW + k];
    float bias = dwb[c];
    const float* xr = x + (size_t)bn * NN * DIMC + c;

    float win[KW];
#pragma unroll
    for (int k = 0; k < KW; k++) {
        int ii = i0 - KW / 2 + k;
        win[k] = (ii >= 0 && ii < NN) ? xr[(size_t)ii * DIMC] : 0.f;
    }
    uint16_t* oh = g_hdw_h + ((size_t)bn * NN + i0) * DIMC + c;
    for (int i = i0; i < i0 + 128; i++) {
        float acc = bias;
#pragma unroll
        for (int k = 0; k < KW; k++) acc = fmaf(win[k], w[k], acc);
        *oh = h16(acc);
        oh += DIMC;
#pragma unroll
        for (int k = 0; k < KW - 1; k++) win[k] = win[k + 1];
        int ii = i + KW / 2 + 1;
        win[KW - 1] = (ii < NN) ? xr[(size_t)ii * DIMC] : 0.f;
    }
}

// ---------------- masked softmax (writes fp16 hi) ----------------------------
__global__ void k_softmax() {
    int row = blockIdx.x;
    int b = row >> 12;
    int i = row & 511;
    const float* p = g_dots + (size_t)row * NN;
    float rv = g_m_any[b * NN + i];
    int t = threadIdx.x;

    float m0 = g_m_any[b * NN + t];
    float m1 = g_m_any[b * NN + t + 256];
    float x0 = (rv != 0.f && m0 != 0.f) ? p[t]       : -FLT_MAX;
    float x1 = (rv != 0.f && m1 != 0.f) ? p[t + 256] : -FLT_MAX;

    __shared__ float red[256];
    float mx = fmaxf(x0, x1);
    red[t] = mx;
    __syncthreads();
    for (int s = 128; s > 0; s >>= 1) {
        if (t < s) red[t] = fmaxf(red[t], red[t + s]);
        __syncthreads();
    }
    mx = red[0];
    __syncthreads();
    float e0 = expf(x0 - mx), e1 = expf(x1 - mx);
    red[t] = e0 + e1;
    __syncthreads();
    for (int s = 128; s > 0; s >>= 1) {
        if (t < s) red[t] += red[t + s];
        __syncthreads();
    }
    float inv = 1.0f / red[0];
    size_t o = (size_t)row * NN;
    g_attn_h[o + t]       = h16(e0 * inv);
    g_attn_h[o + t + 256] = h16(e1 * inv);
}

// ================== mma.sync fp16 NT GEMM (2-stage cp.async) =================
// MODE 1: A 2-term (hi+lo), B hi.  MODE 2: A hi, B hi (single MMA).
struct GemmP {
    const uint16_t *Ah, *Al; long long lda; long long a_bs;
    const uint16_t *Bh; long long ldb; long long b_bs;
    float* C;                                  // fp32 out (or null)
    uint16_t *Ch, *Cl;                         // split out (or null)
    long long ldc; long long c_bs;
    int K;
    const float* bias;
    const float* alpha_vec; int alpha_shift;
    int mode;   // 0 normal batch, 1 = AV addressing
    int emode;  // 0 plain, 1 rotary->qr hi (has_rows), 2 rotary->kr hi
};

// rotary epilogue: write fp16 hi-only q/k in (b,h,i,r*64+d) layout
__device__ __forceinline__ void rot_store(int row, int col, float ve, float vo,
                                          bool isq) {
    int i = row & 511, bn = row >> 9;
    int h = col >> 6, d = col & 63, j = d >> 1;
    float s = g_sin[i * 32 + j], c = g_cos[i * 32 + j];
    float oe = ve * c - vo * s;
    float oo = vo * c + ve * s;
    int b = bn >> 5, r = bn & 31;
    size_t dst = (((size_t)(b * HH + h) * NN + i) * (RR * DH)) + r * DH + d;
    if (isq) {
        float hr = g_has_rows[bn];
        oe *= hr; oo *= hr;
        *(uint32_t*)(g_qr_h + dst) = (uint32_t)h16(oe) | ((uint32_t)h16(oo) << 16);
    } else {
        *(uint32_t*)(g_kr_h + dst) = (uint32_t)h16(oe) | ((uint32_t)h16(oo) << 16);
    }
}

template <int TN, int MODE>
__global__ void __launch_bounds__(256) k_mma(GemmP p) {
    constexpr int NT8 = TN / 32;
    constexpr int NX4 = NT8 / 2;
    constexpr uint32_t ABY = (MODE == 2) ? 8192u : 16384u;
    constexpr uint32_t SS = ABY + TN * 64u;    // stage stride bytes
    extern __shared__ __align__(128) char dsm[];
    uint32_t sb = smem_u32(dsm);

    int tid = threadIdx.x, wid = tid >> 5, lane = tid & 31;
    int bx = blockIdx.x, by = blockIdx.y, z = blockIdx.z;

    size_t abase, cbase;
    size_t bbase = (size_t)z * p.b_bs + (size_t)bx * TN * p.ldb;
    if (p.mode == 0) {
        abase = (size_t)z * p.a_bs;
        cbase = (size_t)z * p.c_bs;
    } else {                                  // AV: z = bn*8 + h
        int bn = z >> 3, h = z & 7, b = bn >> 5;
        abase = (size_t)(b * HH + h) * p.a_bs;
        cbase = (size_t)bn * p.c_bs + h * 64;
    }
    abase += (size_t)by * 128 * p.lda;
    const uint16_t* Ah = p.Ah + abase;
    const uint16_t* Al = (MODE == 1) ? (p.Al + abase) : nullptr;
    const uint16_t* Bh = p.Bh + bbase;

    int m0 = (wid & 1) * 64;
    int n0 = (wid >> 1) * (TN / 4);
    int arow = m0 + (lane & 7) + ((lane >> 3) & 1) * 8;
    int akb  = ((lane >> 4) & 1) * 8;
    int brow = n0 + (lane & 7) + ((lane >> 4) & 1) * 8;
    int bkb  = ((lane >> 3) & 1) * 8;

    float acc[4][NT8][4];
#pragma unroll
    for (int i = 0; i < 4; i++)
#pragma unroll
        for (int j = 0; j < NT8; j++)
#pragma unroll
            for (int q = 0; q < 4; q++) acc[i][j][q] = 0.f;

    int KC = p.K >> 5;

    auto load_stage = [&](int st, int k0) {
        uint32_t base = sb + (uint32_t)st * SS;
#pragma unroll 2
        for (int idx = tid; idx < 512; idx += 256) {
            int row = idx >> 2, c = idx & 3;
            uint32_t off = (uint32_t)(row * 64 + ((c * 16) ^ (((row >> 1) & 3) << 4)));
            CP16(base + off, Ah + (size_t)row * p.lda + k0 + c * 8);
            if (MODE == 1)
                CP16(base + 8192 + off, Al + (size_t)row * p.lda + k0 + c * 8);
        }
#pragma unroll 2
        for (int idx = tid; idx < TN * 4; idx += 256) {
            int row = idx >> 2, c = idx & 3;
            uint32_t off = (uint32_t)(row * 64 + ((c * 16) ^ (((row >> 1) & 3) << 4)));
            CP16(base + ABY + off, Bh + (size_t)row * p.ldb + k0 + c * 8);
        }
    };

    load_stage(0, 0);
    CP_COMMIT();

    for (int ch = 0; ch < KC; ch++) {
        if (ch + 1 < KC) {
            load_stage((ch + 1) & 1, (ch + 1) << 5);
            CP_COMMIT();
            CP_WAIT1();
        } else {
            CP_WAIT0();
        }
        __syncthreads();

        uint32_t base = sb + (uint32_t)(ch & 1) * SS;
        uint32_t aHiB = base, aLoB = base + 8192;
        uint32_t bHiB = base + ABY;

#pragma unroll
        for (int kk = 0; kk < 32; kk += 16) {
            uint32_t ah[4][4];
#pragma unroll
            for (int mt = 0; mt < 4; mt++)
                LDSM4(ah[mt], aHiB + soff(arow + mt * 16, kk + akb));
            uint32_t bh[NX4][4];
#pragma unroll
            for (int nx = 0; nx < NX4; nx++)
                LDSM4(bh[nx], bHiB + soff(brow + nx * 16, kk + bkb));
#pragma unroll
            for (int mt = 0; mt < 4; mt++)
#pragma unroll
                for (int nt = 0; nt < NT8; nt++)
                    mma_h(acc[mt][nt], ah[mt], &bh[nt >> 1][(nt & 1) * 2]);

            if (MODE == 1) {
                uint32_t al[4][4];
#pragma unroll
                for (int mt = 0; mt < 4; mt++)
                    LDSM4(al[mt], aLoB + soff(arow + mt * 16, kk + akb));
#pragma unroll
                for (int mt = 0; mt < 4; mt++)
#pragma unroll
                    for (int nt = 0; nt < NT8; nt++)
                        mma_h(acc[mt][nt], al[mt], &bh[nt >> 1][(nt & 1) * 2]);
            }
        }
        __syncthreads();
    }

    // epilogue
    float alpha = p.alpha_vec ? p.alpha_vec[z >> p.alpha_shift] : 1.0f;
    int r0 = by * 128 + m0 + (lane >> 2);
    int c0 = bx * TN + n0 + (lane & 3) * 2;
#pragma unroll
    for (int mt = 0; mt < 4; mt++) {
#pragma unroll
        for (int nt = 0; nt < NT8; nt++) {
            int row = r0 + mt * 16;
            int col = c0 + nt * 8;
            float b0 = 0.f, b1 = 0.f;
            if (p.bias) { b0 = p.bias[col]; b1 = p.bias[col + 1]; }
            float v00 = acc[mt][nt][0] * alpha + b0;
            float v01 = acc[mt][nt][1] * alpha + b1;
            float v10 = acc[mt][nt][2] * alpha + b0;
            float v11 = acc[mt][nt][3] * alpha + b1;
            if (p.emode == 1) {
                rot_store(row, col, v00, v01, true);
                rot_store(row + 8, col, v10, v11, true);
            } else if (p.emode == 2) {
                rot_store(row, col, v00, v01, false);
                rot_store(row + 8, col, v10, v11, false);
            } else {
                if (p.C) {
                    *(float2*)(p.C + cbase + (size_t)row * p.ldc + col) = make_float2(v00, v01);
                    *(float2*)(p.C + cbase + (size_t)(row + 8) * p.ldc + col) = make_float2(v10, v11);
                }
                if (p.Ch) {
                    uint16_t h0, l0, h1, l1;
                    hsplit(v00, h0, l0); hsplit(v01, h1, l1);
                    *(uint32_t*)(p.Ch + cbase + (size_t)row * p.ldc + col) = (uint32_t)h0 | ((uint32_t)h1 << 16);
                    *(uint32_t*)(p.Cl + cbase + (size_t)row * p.ldc + col) = (uint32_t)l0 | ((uint32_t)l1 << 16);
                    hsplit(v10, h0, l0); hsplit(v11, h1, l1);
                    *(uint32_t*)(p.Ch + cbase + (size_t)(row + 8) * p.ldc + col) = (uint32_t)h0 | ((uint32_t)h1 << 16);
                    *(uint32_t*)(p.Cl + cbase + (size_t)(row + 8) * p.ldc + col) = (uint32_t)l0 | ((uint32_t)l1 << 16);
                }
            }
        }
    }
}

// ---------------- launch -----------------------------------------------------
#define SYM(var, sym) decltype(&sym[0]) var; cudaGetSymbolAddress((void**)&var, sym)

extern "C" void kernel_launch(void* const* d_in, const int* in_sizes, int n_in,
                              void* d_out, int out_size) {
    const float* x    = (const float*)d_in[0];
    const void*  mask = d_in[1];
    const float* dw_w = (const float*)d_in[3];
    const float* dw_b = (const float*)d_in[4];
    const float* pw_w = (const float*)d_in[5];
    const float* pw_b = (const float*)d_in[6];
    const float* w_kv = (const float*)d_in[7];
    const float* w_o  = (const float*)d_in[8];
    const float* b_o  = (const float*)d_in[9];
    float* out = (float*)d_out;

    const int SM128_1 = 2 * (16384 + 128 * 64);   // 49152 (A 2-term)
    const int SM128_2 = 2 * (8192 + 128 * 64);    // 32768 (A hi-only)
    const int SM64_2  = 2 * (8192 + 64 * 64);     // 24576
    cudaFuncSetAttribute(k_mma<128, 1>, cudaFuncAttributeMaxDynamicSharedMemorySize, SM128_1);
    cudaFuncSetAttribute(k_mma<128, 2>, cudaFuncAttributeMaxDynamicSharedMemorySize, SM128_2);
    cudaFuncSetAttribute(k_mma<64, 2>,  cudaFuncAttributeMaxDynamicSharedMemorySize, SM64_2);

    SYM(v_p, g_v);  SYM(dots_p, g_dots);
    SYM(xs_h, g_xs_h);
    SYM(hdw_h, g_hdw_h);
    SYM(pww_h, g_pww_h);
    SYM(wkvT_h, g_wkvT_h);
    SYM(woT_h, g_woT_h);
    SYM(qr_h, g_qr_h);
    SYM(kr_h, g_kr_h);
    SYM(attn_h, g_attn_h);
    SYM(vT_h, g_vT_h);
    SYM(oi_h, g_oi_h);    SYM(oi_l, g_oi_l);
    SYM(alpha_p, g_alpha);

    k_detect<<<1, 256>>>((const unsigned char*)mask);
    k_norm_mask<<<(BN_TOT * NN + 255) / 256, 256>>>(mask);
    k_hasrows<<<BN_TOT, 256>>>();
    k_many<<<NB, NN>>>();
    k_trig<<<NN, 32>>>();

    k_hi<<<(BN_TOT * NN * DIMC) / 256, 256>>>(x, xs_h, BN_TOT * NN * DIMC);
    k_hi<<<(INNERD * DIMC) / 256, 256>>>(pw_w, pww_h, INNERD * DIMC);
    k_wkvT<<<(2 * INNERD * DIMC) / 256, 256>>>(w_kv);
    k_woT<<<(DIMC * INNERD) / 256, 256>>>(w_o);

    k_conv2<<<dim3(4, BN_TOT), 256>>>(x, dw_w, dw_b);

    // qproj + bias + rotary + has_rows -> qr hi  (A hi-only; M=32768, N=512, K=256)
    {
        GemmP p = {hdw_h, nullptr, DIMC, 0, pww_h, DIMC, 0,
                   nullptr, nullptr, nullptr, 0, 0,
                   DIMC, pw_b, nullptr, 0, 0, 1};
        k_mma<128, 2><<<dim3(4, 256, 1), 256, SM128_2>>>(p);
    }
    // K proj + rotary -> kr hi  (A hi-only; M=32768, N=512, K=256)
    {
        GemmP p = {xs_h, nullptr, DIMC, 0, wkvT_h, DIMC, 0,
                   nullptr, nullptr, nullptr, 0, 0,
                   DIMC, nullptr, nullptr, 0, 0, 2};
        k_mma<128, 2><<<dim3(4, 256, 1), 256, SM128_2>>>(p);
    }
    // V proj -> g_v fp32  (A hi-only; M=32768, N=512, K=256)
    {
        GemmP p = {xs_h, nullptr, DIMC, 0, wkvT_h + INNERD * DIMC, DIMC, 0,
                   v_p, nullptr, nullptr, INNERD, 0,
                   DIMC, nullptr, nullptr, 0, 0, 0};
        k_mma<128, 2><<<dim3(4, 256, 1), 256, SM128_2>>>(p);
    }
    k_vT<<<dim3(16, 16, BN_TOT), dim3(32, 8)>>>();
    // dots: A hi, B hi — 16 batches, M=N=512, K=2048 -> fp32 (alpha per b)
    {
        GemmP p = {qr_h, nullptr, 2048, (long long)NN * 2048, kr_h, 2048, (long long)NN * 2048,
                   dots_p, nullptr, nullptr, NN, (long long)NN * NN,
                   2048, nullptr, alpha_p, 3, 0, 0};
        k_mma<128, 2><<<dim3(4, 4, 16), 256, SM128_2>>>(p);
    }
    k_softmax<<<NB * HH * NN, 256>>>();
    // AV: A hi, B hi — 512 batches (bn,h), M=512, N=64, K=512 -> oi split
    {
        GemmP p = {attn_h, nullptr, NN, (long long)NN * NN, vT_h, NN, (long long)DH * NN,
                   nullptr, oi_h, oi_l, INNERD, (long long)NN * INNERD,
                   NN, nullptr, nullptr, 0, 1, 0};
        k_mma<64, 2><<<dim3(1, 4, BN_TOT * HH), 256, SM64_2>>>(p);
    }
    // final: A 2-term, M=32768, N=256, K=512 -> out fp32 (+bias)
    {
        GemmP p = {oi_h, oi_l, INNERD, 0, woT_h, INNERD, 0,
                   out, nullptr, nullptr, DIMC, 0,
                   INNERD, b_o, nullptr, 0, 0, 0};
        k_mma<128, 1><<<dim3(2, 256, 1), 256, SM128_1>>>(p);
    }
}

// round 11
// speedup vs baseline: 2.0202x; 1.0724x over previous
#include <cuda_runtime.h>
#include <cuda_bf16.h>
#include <cuda_fp16.h>
#include <float.h>
#include <math.h>
#include <stdint.h>

// Problem constants (fixed shapes)
#define BN_TOT 64      // b*r
#define NB 2           // b
#define RR 32          // r
#define NN 512         // n
#define DIMC 256       // DIM
#define HH 8           // heads
#define DH 64          // dim_head
#define INNERD 512     // HH*DH
#define KW 15          // conv kernel

// ---------------- scratch (device globals; no allocations allowed) ----------
__device__ float g_v[BN_TOT * NN * INNERD];         // v fp32 (bn, i, hd)
__device__ float g_dots[NB * HH * NN * NN];         // logits fp32

// fp16 hi-only operands everywhere
__device__ uint16_t g_xs_h[BN_TOT * NN * DIMC];
__device__ uint16_t g_hdw_h[BN_TOT * NN * DIMC];
__device__ uint16_t g_pww_h[INNERD * DIMC];
__device__ uint16_t g_wkvT_h[2 * INNERD * DIMC];
__device__ uint16_t g_woT_h[DIMC * INNERD];
__device__ uint16_t g_vT_h[BN_TOT * INNERD * NN];
__device__ uint16_t g_attn_h[NB * HH * NN * NN];
__device__ uint16_t g_oi_h[BN_TOT * NN * INNERD];
__device__ uint16_t g_qr_h[NB * HH * NN * RR * DH];
__device__ uint16_t g_kr_h[NB * HH * NN * RR * DH];

__device__ unsigned char g_mask[BN_TOT * NN];
__device__ float g_has_rows[BN_TOT];
__device__ float g_m_any[NB * NN];
__device__ float g_alpha[NB];
__device__ float g_sin[NN * 32];
__device__ float g_cos[NN * 32];
__device__ int g_mask_mode;

// ========================= helpers ===========================================
__device__ __forceinline__ uint32_t smem_u32(const void* p) {
    uint32_t a;
    asm("{ .reg .u64 t; cvta.to.shared.u64 t, %1; cvt.u32.u64 %0, t; }" : "=r"(a) : "l"(p));
    return a;
}

#define LDSM4(r, addr)                                                          \
    asm volatile("ldmatrix.sync.aligned.m8n8.x4.shared.b16 {%0,%1,%2,%3}, [%4];" \
                 : "=r"((r)[0]), "=r"((r)[1]), "=r"((r)[2]), "=r"((r)[3])       \
                 : "r"(addr))

__device__ __forceinline__ void mma_h(float* c, const uint32_t* a, const uint32_t* b) {
    asm volatile("mma.sync.aligned.m16n8k16.row.col.f32.f16.f16.f32 "
                 "{%0,%1,%2,%3}, {%4,%5,%6,%7}, {%8,%9}, {%0,%1,%2,%3};"
                 : "+f"(c[0]), "+f"(c[1]), "+f"(c[2]), "+f"(c[3])
                 : "r"(a[0]), "r"(a[1]), "r"(a[2]), "r"(a[3]), "r"(b[0]), "r"(b[1]));
}

#define CP16(dst, src)                                                          \
    asm volatile("cp.async.cg.shared.global [%0], [%1], 16;" :: "r"(dst), "l"(src) : "memory")
#define CP_COMMIT() asm volatile("cp.async.commit_group;" ::: "memory")
#define CP_WAIT0()  asm volatile("cp.async.wait_group 0;" ::: "memory")

// byte offset in a 64B-per-row 16-bit tile (32 k values/row), bank-swizzled
__device__ __forceinline__ uint32_t soff(int row, int kcol) {
    return (uint32_t)(row * 64 + ((kcol * 2) ^ (((row >> 1) & 3) << 4)));
}

__device__ __forceinline__ uint16_t h16(float v) {
    return __half_as_ushort(__float2half_rn(v));
}

// ========================= mask / small kernels ==============================
__global__ void k_detect(const unsigned char* m) {
    __shared__ int s_high, s_odd;
    if (threadIdx.x == 0) { s_high = 0; s_odd = 0; }
    __syncthreads();
    for (int idx = threadIdx.x; idx < BN_TOT * NN; idx += blockDim.x) {
        unsigned char v = m[idx];
        if (v > 1) s_high = 1;
        if ((idx & 3) && v) s_odd = 1;
    }
    __syncthreads();
    if (threadIdx.x == 0) g_mask_mode = s_high ? 2 : (s_odd ? 0 : 1);
}
__global__ void k_norm_mask(const void* m) {
    int idx = blockIdx.x * blockDim.x + threadIdx.x;
    if (idx >= BN_TOT * NN) return;
    int mode = g_mask_mode;
    unsigned char v;
    if (mode == 0)      v = (((const unsigned char*)m)[idx] != 0);
    else if (mode == 1) v = (((const int*)m)[idx] != 0);
    else                v = (((const float*)m)[idx] != 0.0f);
    g_mask[idx] = v;
}
__global__ void k_hasrows() {
    int bn = blockIdx.x;
    int any = 0;
    for (int j = threadIdx.x; j < NN; j += blockDim.x) any |= g_mask[bn * NN + j];
    __shared__ int s;
    if (threadIdx.x == 0) s = 0;
    __syncthreads();
    if (any) s = 1;
    __syncthreads();
    if (threadIdx.x == 0) g_has_rows[bn] = (float)s;
}
__global__ void k_many() {
    int b = blockIdx.x;
    int i = threadIdx.x;
    int any = 0;
    for (int r = 0; r < RR; r++) any |= g_mask[(b * RR + r) * NN + i];
    g_m_any[b * NN + i] = (float)any;
    if (i == 0) {
        float s = 0.f;
        for (int r = 0; r < RR; r++) s += g_has_rows[b * RR + r];
        g_alpha[b] = (s > 0.f) ? 0.125f * rsqrtf(s) : 0.f;
    }
}
__global__ void k_trig() {
    int i = blockIdx.x;        // 512
    int j = threadIdx.x;       // 32
    float inv = exp2f(-((float)(2 * j) / 64.0f) * 13.287712379549449f);
    float ang = (float)i * inv;
    g_sin[i * 32 + j] = sinf(ang);
    g_cos[i * 32 + j] = cosf(ang);
}

// ---------------- splits / transposes ---------------------------------------
__global__ void k_hi(const float* __restrict__ src, uint16_t* __restrict__ h, int n) {
    int i = blockIdx.x * blockDim.x + threadIdx.x;
    if (i >= n) return;
    h[i] = h16(src[i]);
}
__global__ void k_wkvT(const float* __restrict__ w) {   // (256,1024)->(1024,256) hi
    int i = blockIdx.x * 256 + threadIdx.x;
    int n = i >> 8, k = i & 255;
    g_wkvT_h[i] = h16(w[k * 1024 + n]);
}
__global__ void k_woT(const float* __restrict__ w) {    // (512,256)->(256,512) hi
    int i = blockIdx.x * 256 + threadIdx.x;
    int n = i >> 9, k = i & 511;
    g_woT_h[i] = h16(w[k * 256 + n]);
}
__global__ void k_vT() {   // v (bn, j, hd) -> vT_h[(bn*512+hd)*512 + j]
    __shared__ float t[32][33];
    int bn = blockIdx.z;
    int j0 = blockIdx.x * 32, hd0 = blockIdx.y * 32;
    int lx = threadIdx.x, ly = threadIdx.y;  // 32 x 8
    for (int dy = 0; dy < 32; dy += 8) {
        int j = j0 + ly + dy, hd = hd0 + lx;
        t[ly + dy][lx] = g_v[((size_t)bn * NN + j) * INNERD + hd];
    }
    __syncthreads();
    for (int dy = 0; dy < 32; dy += 8) {
        int hd = hd0 + ly + dy, j = j0 + lx;
        g_vT_h[((size_t)bn * 512 + hd) * 512 + j] = h16(t[lx][ly + dy]);
    }
}

// ---------------- depthwise conv: sliding register window --------------------
__global__ void __launch_bounds__(256) k_conv2(const float* __restrict__ x,
                                               const float* __restrict__ dww,
                                               const float* __restrict__ dwb) {
    int c = threadIdx.x;
    int bn = blockIdx.y, seg = blockIdx.x;
    int i0 = seg * 128;
    float w[KW];
#pragma unroll
    for (int k = 0; k < KW; k++) w[k] = dww[c * KW + k];
    float bias = dwb[c];
    const float* xr = x + (size_t)bn * NN * DIMC + c;

    float win[KW];
#pragma unroll
    for (int k = 0; k < KW; k++) {
        int ii = i0 - KW / 2 + k;
        win[k] = (ii >= 0 && ii < NN) ? xr[(size_t)ii * DIMC] : 0.f;
    }
    uint16_t* oh = g_hdw_h + ((size_t)bn * NN + i0) * DIMC + c;
    for (int i = i0; i < i0 + 128; i++) {
        float acc = bias;
#pragma unroll
        for (int k = 0; k < KW; k++) acc = fmaf(win[k], w[k], acc);
        *oh = h16(acc);
        oh += DIMC;
#pragma unroll
        for (int k = 0; k < KW - 1; k++) win[k] = win[k + 1];
        int ii = i + KW / 2 + 1;
        win[KW - 1] = (ii < NN) ? xr[(size_t)ii * DIMC] : 0.f;
    }
}

// ---------------- masked softmax (writes fp16 hi) ----------------------------
__global__ void k_softmax() {
    int row = blockIdx.x;
    int b = row >> 12;
    int i = row & 511;
    const float* p = g_dots + (size_t)row * NN;
    float rv = g_m_any[b * NN + i];
    int t = threadIdx.x;

    float m0 = g_m_any[b * NN + t];
    float m1 = g_m_any[b * NN + t + 256];
    float x0 = (rv != 0.f && m0 != 0.f) ? p[t]       : -FLT_MAX;
    float x1 = (rv != 0.f && m1 != 0.f) ? p[t + 256] : -FLT_MAX;

    __shared__ float red[256];
    float mx = fmaxf(x0, x1);
    red[t] = mx;
    __syncthreads();
    for (int s = 128; s > 0; s >>= 1) {
        if (t < s) red[t] = fmaxf(red[t], red[t + s]);
        __syncthreads();
    }
    mx = red[0];
    __syncthreads();
    float e0 = expf(x0 - mx), e1 = expf(x1 - mx);
    red[t] = e0 + e1;
    __syncthreads();
    for (int s = 128; s > 0; s >>= 1) {
        if (t < s) red[t] += red[t + s];
        __syncthreads();
    }
    float inv = 1.0f / red[0];
    size_t o = (size_t)row * NN;
    g_attn_h[o + t]       = h16(e0 * inv);
    g_attn_h[o + t + 256] = h16(e1 * inv);
}

// ================== mma.sync fp16 NT GEMM (single-sync pipeline) =============
// All stages: A hi, B hi (single MMA per k-step).
struct GemmP {
    const uint16_t *Ah; long long lda; long long a_bs;
    const uint16_t *Bh; long long ldb; long long b_bs;
    float* C;                                  // fp32 out (or null)
    uint16_t *Ch;                              // fp16 hi out (or null)
    long long ldc; long long c_bs;
    int K;
    const float* bias;
    const float* alpha_vec; int alpha_shift;
    int mode;   // 0 normal batch, 1 = AV addressing
    int emode;  // 0 plain, 1 rotary->qr hi (has_rows), 5 combined k/v epilogue
};

// rotary epilogue: write fp16 hi-only q/k in (b,h,i,r*64+d) layout
__device__ __forceinline__ void rot_store(int row, int col, float ve, float vo,
                                          bool isq) {
    int i = row & 511, bn = row >> 9;
    int h = col >> 6, d = col & 63, j = d >> 1;
    float s = g_sin[i * 32 + j], c = g_cos[i * 32 + j];
    float oe = ve * c - vo * s;
    float oo = vo * c + ve * s;
    int b = bn >> 5, r = bn & 31;
    size_t dst = (((size_t)(b * HH + h) * NN + i) * (RR * DH)) + r * DH + d;
    if (isq) {
        float hr = g_has_rows[bn];
        oe *= hr; oo *= hr;
        *(uint32_t*)(g_qr_h + dst) = (uint32_t)h16(oe) | ((uint32_t)h16(oo) << 16);
    } else {
        *(uint32_t*)(g_kr_h + dst) = (uint32_t)h16(oe) | ((uint32_t)h16(oo) << 16);
    }
}

template <int TN>
__global__ void __launch_bounds__(256) k_mma(GemmP p) {
    constexpr int NT8 = TN / 32;
    constexpr int NX4 = NT8 / 2;
    constexpr uint32_t SS = 8192u + TN * 64u;    // stage stride bytes
    extern __shared__ __align__(128) char dsm[];
    uint32_t sb = smem_u32(dsm);

    int tid = threadIdx.x, wid = tid >> 5, lane = tid & 31;
    int bx = blockIdx.x, by = blockIdx.y, z = blockIdx.z;

    size_t abase, cbase;
    size_t bbase = (size_t)z * p.b_bs + (size_t)bx * TN * p.ldb;
    if (p.mode == 0) {
        abase = (size_t)z * p.a_bs;
        cbase = (size_t)z * p.c_bs;
    } else {                                  // AV: z = bn*8 + h
        int bn = z >> 3, h = z & 7, b = bn >> 5;
        abase = (size_t)(b * HH + h) * p.a_bs;
        cbase = (size_t)bn * p.c_bs + h * 64;
    }
    abase += (size_t)by * 128 * p.lda;
    const uint16_t* Ah = p.Ah + abase;
    const uint16_t* Bh = p.Bh + bbase;

    int m0 = (wid & 1) * 64;
    int n0 = (wid >> 1) * (TN / 4);
    int arow = m0 + (lane & 7) + ((lane >> 3) & 1) * 8;
    int akb  = ((lane >> 4) & 1) * 8;
    int brow = n0 + (lane & 7) + ((lane >> 4) & 1) * 8;
    int bkb  = ((lane >> 3) & 1) * 8;

    float acc[4][NT8][4];
#pragma unroll
    for (int i = 0; i < 4; i++)
#pragma unroll
        for (int j = 0; j < NT8; j++)
#pragma unroll
            for (int q = 0; q < 4; q++) acc[i][j][q] = 0.f;

    int KC = p.K >> 5;

    auto load_stage = [&](int st, int k0) {
        uint32_t base = sb + (uint32_t)st * SS;
#pragma unroll 2
        for (int idx = tid; idx < 512; idx += 256) {
            int row = idx >> 2, c = idx & 3;
            uint32_t off = (uint32_t)(row * 64 + ((c * 16) ^ (((row >> 1) & 3) << 4)));
            CP16(base + off, Ah + (size_t)row * p.lda + k0 + c * 8);
        }
#pragma unroll 2
        for (int idx = tid; idx < TN * 4; idx += 256) {
            int row = idx >> 2, c = idx & 3;
            uint32_t off = (uint32_t)(row * 64 + ((c * 16) ^ (((row >> 1) & 3) << 4)));
            CP16(base + 8192 + off, Bh + (size_t)row * p.ldb + k0 + c * 8);
        }
    };

    load_stage(0, 0);
    CP_COMMIT();

    for (int ch = 0; ch < KC; ch++) {
        CP_WAIT0();
        __syncthreads();            // stage ch visible; prior-buffer reads done
        if (ch + 1 < KC) {
            load_stage((ch + 1) & 1, (ch + 1) << 5);
            CP_COMMIT();
        }

        uint32_t base = sb + (uint32_t)(ch & 1) * SS;
        uint32_t aHiB = base, bHiB = base + 8192;

#pragma unroll
        for (int kk = 0; kk < 32; kk += 16) {
            uint32_t ah[4][4];
#pragma unroll
            for (int mt = 0; mt < 4; mt++)
                LDSM4(ah[mt], aHiB + soff(arow + mt * 16, kk + akb));
            uint32_t bh[NX4][4];
#pragma unroll
            for (int nx = 0; nx < NX4; nx++)
                LDSM4(bh[nx], bHiB + soff(brow + nx * 16, kk + bkb));
#pragma unroll
            for (int mt = 0; mt < 4; mt++)
#pragma unroll
                for (int nt = 0; nt < NT8; nt++)
                    mma_h(acc[mt][nt], ah[mt], &bh[nt >> 1][(nt & 1) * 2]);
        }
    }

    // epilogue
    float alpha = p.alpha_vec ? p.alpha_vec[z >> p.alpha_shift] : 1.0f;
    int r0 = by * 128 + m0 + (lane >> 2);
    int c0 = bx * TN + n0 + (lane & 3) * 2;
#pragma unroll
    for (int mt = 0; mt < 4; mt++) {
#pragma unroll
        for (int nt = 0; nt < NT8; nt++) {
            int row = r0 + mt * 16;
            int col = c0 + nt * 8;
            float b0 = 0.f, b1 = 0.f;
            if (p.bias) { b0 = p.bias[col]; b1 = p.bias[col + 1]; }
            float v00 = acc[mt][nt][0] * alpha + b0;
            float v01 = acc[mt][nt][1] * alpha + b1;
            float v10 = acc[mt][nt][2] * alpha + b0;
            float v11 = acc[mt][nt][3] * alpha + b1;
            if (p.emode == 1) {
                rot_store(row, col, v00, v01, true);
                rot_store(row + 8, col, v10, v11, true);
            } else if (p.emode == 5) {
                if (col < INNERD) {           // K half -> rotary kr
                    rot_store(row, col, v00, v01, false);
                    rot_store(row + 8, col, v10, v11, false);
                } else {                      // V half -> g_v fp32
                    int vc = col - INNERD;
                    *(float2*)(g_v + (size_t)row * INNERD + vc) = make_float2(v00, v01);
                    *(float2*)(g_v + (size_t)(row + 8) * INNERD + vc) = make_float2(v10, v11);
                }
            } else {
                if (p.C) {
                    *(float2*)(p.C + cbase + (size_t)row * p.ldc + col) = make_float2(v00, v01);
                    *(float2*)(p.C + cbase + (size_t)(row + 8) * p.ldc + col) = make_float2(v10, v11);
                }
                if (p.Ch) {
                    *(uint32_t*)(p.Ch + cbase + (size_t)row * p.ldc + col) =
                        (uint32_t)h16(v00) | ((uint32_t)h16(v01) << 16);
                    *(uint32_t*)(p.Ch + cbase + (size_t)(row + 8) * p.ldc + col) =
                        (uint32_t)h16(v10) | ((uint32_t)h16(v11) << 16);
                }
            }
        }
    }
}

// ---------------- launch -----------------------------------------------------
#define SYM(var, sym) decltype(&sym[0]) var; cudaGetSymbolAddress((void**)&var, sym)

extern "C" void kernel_launch(void* const* d_in, const int* in_sizes, int n_in,
                              void* d_out, int out_size) {
    const float* x    = (const float*)d_in[0];
    const void*  mask = d_in[1];
    const float* dw_w = (const float*)d_in[3];
    const float* dw_b = (const float*)d_in[4];
    const float* pw_w = (const float*)d_in[5];
    const float* pw_b = (const float*)d_in[6];
    const float* w_kv = (const float*)d_in[7];
    const float* w_o  = (const float*)d_in[8];
    const float* b_o  = (const float*)d_in[9];
    float* out = (float*)d_out;

    const int SM128 = 2 * (8192 + 128 * 64);    // 32768
    const int SM64  = 2 * (8192 + 64 * 64);     // 24576
    cudaFuncSetAttribute(k_mma<128>, cudaFuncAttributeMaxDynamicSharedMemorySize, SM128);
    cudaFuncSetAttribute(k_mma<64>,  cudaFuncAttributeMaxDynamicSharedMemorySize, SM64);

    SYM(v_p, g_v);  SYM(dots_p, g_dots);
    SYM(xs_h, g_xs_h);
    SYM(hdw_h, g_hdw_h);
    SYM(pww_h, g_pww_h);
    SYM(wkvT_h, g_wkvT_h);
    SYM(woT_h, g_woT_h);
    SYM(qr_h, g_qr_h);
    SYM(kr_h, g_kr_h);
    SYM(attn_h, g_attn_h);
    SYM(vT_h, g_vT_h);
    SYM(oi_h, g_oi_h);
    SYM(alpha_p, g_alpha);
    (void)v_p;

    k_detect<<<1, 256>>>((const unsigned char*)mask);
    k_norm_mask<<<(BN_TOT * NN + 255) / 256, 256>>>(mask);
    k_hasrows<<<BN_TOT, 256>>>();
    k_many<<<NB, NN>>>();
    k_trig<<<NN, 32>>>();

    k_hi<<<(BN_TOT * NN * DIMC) / 256, 256>>>(x, xs_h, BN_TOT * NN * DIMC);
    k_hi<<<(INNERD * DIMC) / 256, 256>>>(pw_w, pww_h, INNERD * DIMC);
    k_wkvT<<<(2 * INNERD * DIMC) / 256, 256>>>(w_kv);
    k_woT<<<(DIMC * INNERD) / 256, 256>>>(w_o);

    k_conv2<<<dim3(4, BN_TOT), 256>>>(x, dw_w, dw_b);

    // qproj + bias + rotary + has_rows -> qr hi  (M=32768, N=512, K=256)
    {
        GemmP p = {hdw_h, DIMC, 0, pww_h, DIMC, 0,
                   nullptr, nullptr, 0, 0,
                   DIMC, pw_b, nullptr, 0, 0, 1};
        k_mma<128><<<dim3(4, 256, 1), 256, SM128>>>(p);
    }
    // KV proj combined: K half -> rotary kr hi, V half -> g_v fp32
    // (M=32768, N=1024, K=256)
    {
        GemmP p = {xs_h, DIMC, 0, wkvT_h, DIMC, 0,
                   nullptr, nullptr, 0, 0,
                   DIMC, nullptr, nullptr, 0, 0, 5};
        k_mma<128><<<dim3(8, 256, 1), 256, SM128>>>(p);
    }
    k_vT<<<dim3(16, 16, BN_TOT), dim3(32, 8)>>>();
    // dots: 16 batches, M=N=512, K=2048 -> fp32 (alpha per b)
    {
        GemmP p = {qr_h, 2048, (long long)NN * 2048, kr_h, 2048, (long long)NN * 2048,
                   dots_p, nullptr, NN, (long long)NN * NN,
                   2048, nullptr, alpha_p, 3, 0, 0};
        k_mma<128><<<dim3(4, 4, 16), 256, SM128>>>(p);
    }
    k_softmax<<<NB * HH * NN, 256>>>();
    // AV: 512 batches (bn,h), M=512, N=64, K=512 -> oi hi
    {
        GemmP p = {attn_h, NN, (long long)NN * NN, vT_h, NN, (long long)DH * NN,
                   nullptr, oi_h, INNERD, (long long)NN * INNERD,
                   NN, nullptr, nullptr, 0, 1, 0};
        k_mma<64><<<dim3(1, 4, BN_TOT * HH), 256, SM64>>>(p);
    }
    // final: M=32768, N=256, K=512 -> out fp32 (+bias)
    {
        GemmP p = {oi_h, INNERD, 0, woT_h, INNERD, 0,
                   out, nullptr, DIMC, 0,
                   INNERD, b_o, nullptr, 0, 0, 0};
        k_mma<128><<<dim3(2, 256, 1), 256, SM128>>>(p);
    }
}

// round 12
// speedup vs baseline: 2.1650x; 1.0717x over previous
#include <cuda_runtime.h>
#include <cuda_bf16.h>
#include <cuda_fp16.h>
#include <float.h>
#include <math.h>
#include <stdint.h>

// Problem constants (fixed shapes)
#define BN_TOT 64      // b*r
#define NB 2           // b
#define RR 32          // r
#define NN 512         // n
#define DIMC 256       // DIM
#define HH 8           // heads
#define DH 64          // dim_head
#define INNERD 512     // HH*DH
#define KW 15          // conv kernel

// ---------------- scratch (device globals; no allocations allowed) ----------
__device__ float g_dots[NB * HH * NN * NN];         // logits fp32

// fp16 hi-only operands everywhere
__device__ uint16_t g_xs_h[BN_TOT * NN * DIMC];
__device__ uint16_t g_hdw_h[BN_TOT * NN * DIMC];
__device__ uint16_t g_pww_h[INNERD * DIMC];
__device__ uint16_t g_wkvT_h[2 * INNERD * DIMC];
__device__ uint16_t g_woT_h[DIMC * INNERD];
__device__ uint16_t g_vT_h[BN_TOT * INNERD * NN];
__device__ uint16_t g_attn_h[NB * HH * NN * NN];
__device__ uint16_t g_oi_h[BN_TOT * NN * INNERD];
__device__ uint16_t g_qr_h[NB * HH * NN * RR * DH];
__device__ uint16_t g_kr_h[NB * HH * NN * RR * DH];

__device__ unsigned char g_mask[BN_TOT * NN];
__device__ float g_has_rows[BN_TOT];
__device__ float g_m_any[NB * NN];
__device__ float g_alpha[NB];
__device__ float g_sin[NN * 32];
__device__ float g_cos[NN * 32];

// ========================= helpers ===========================================
__device__ __forceinline__ uint32_t smem_u32(const void* p) {
    uint32_t a;
    asm("{ .reg .u64 t; cvta.to.shared.u64 t, %1; cvt.u32.u64 %0, t; }" : "=r"(a) : "l"(p));
    return a;
}

#define LDSM4(r, addr)                                                          \
    asm volatile("ldmatrix.sync.aligned.m8n8.x4.shared.b16 {%0,%1,%2,%3}, [%4];" \
                 : "=r"((r)[0]), "=r"((r)[1]), "=r"((r)[2]), "=r"((r)[3])       \
                 : "r"(addr))

__device__ __forceinline__ void mma_h(float* c, const uint32_t* a, const uint32_t* b) {
    asm volatile("mma.sync.aligned.m16n8k16.row.col.f32.f16.f16.f32 "
                 "{%0,%1,%2,%3}, {%4,%5,%6,%7}, {%8,%9}, {%0,%1,%2,%3};"
                 : "+f"(c[0]), "+f"(c[1]), "+f"(c[2]), "+f"(c[3])
                 : "r"(a[0]), "r"(a[1]), "r"(a[2]), "r"(a[3]), "r"(b[0]), "r"(b[1]));
}

#define CP16(dst, src)                                                          \
    asm volatile("cp.async.cg.shared.global [%0], [%1], 16;" :: "r"(dst), "l"(src) : "memory")
#define CP_COMMIT() asm volatile("cp.async.commit_group;" ::: "memory")
#define CP_WAIT0()  asm volatile("cp.async.wait_group 0;" ::: "memory")

// byte offset in a 64B-per-row 16-bit tile (32 k values/row), bank-swizzled
__device__ __forceinline__ uint32_t soff(int row, int kcol) {
    return (uint32_t)(row * 64 + ((kcol * 2) ^ (((row >> 1) & 3) << 4)));
}

__device__ __forceinline__ uint16_t h16(float v) {
    return __half_as_ushort(__float2half_rn(v));
}

// ========================= fused prep (mask + trig), ONE block ===============
__global__ void __launch_bounds__(1024) k_prep(const void* mraw) {
    const unsigned char* mb = (const unsigned char*)mraw;
    int tid = threadIdx.x;
    __shared__ int s_high, s_odd;

    // phase 1: detect mask dtype from the guaranteed-min 32768 bytes
    if (tid == 0) { s_high = 0; s_odd = 0; }
    __syncthreads();
    for (int idx = tid; idx < BN_TOT * NN; idx += 1024) {
        unsigned char v = mb[idx];
        if (v > 1) s_high = 1;
        if ((idx & 3) && v) s_odd = 1;
    }
    __syncthreads();
    int mode = s_high ? 2 : (s_odd ? 0 : 1);

    // phase 2: normalize mask
    for (int idx = tid; idx < BN_TOT * NN; idx += 1024) {
        unsigned char v;
        if (mode == 0)      v = (mb[idx] != 0);
        else if (mode == 1) v = (((const int*)mraw)[idx] != 0);
        else                v = (((const float*)mraw)[idx] != 0.0f);
        g_mask[idx] = v;
    }
    __syncthreads();

    // phase 3: has_rows (32 warps x 2 bn each)
    int w = tid >> 5, lane = tid & 31;
    for (int bb = 0; bb < 2; bb++) {
        int bn = w * 2 + bb;
        int any = 0;
        for (int q = lane; q < NN; q += 32) any |= g_mask[bn * NN + q];
        any = __any_sync(0xFFFFFFFFu, any);
        if (lane == 0) g_has_rows[bn] = (float)any;
    }
    __syncthreads();

    // phase 4: m_any + alpha
    {
        int b = tid >> 9, i = tid & 511;
        int any = 0;
        for (int r = 0; r < RR; r++) any |= g_mask[(b * RR + r) * NN + i];
        g_m_any[b * NN + i] = (float)any;
        if (i == 0) {
            float s = 0.f;
            for (int r = 0; r < RR; r++) s += g_has_rows[b * RR + r];
            g_alpha[b] = (s > 0.f) ? 0.125f * rsqrtf(s) : 0.f;
        }
    }

    // phase 5: rotary trig table (independent of mask)
    for (int idx = tid; idx < NN * 32; idx += 1024) {
        int i = idx >> 5, j = idx & 31;
        float inv = exp2f(-((float)(2 * j) / 64.0f) * 13.287712379549449f);
        float ang = (float)i * inv;
        g_sin[idx] = sinf(ang);
        g_cos[idx] = cosf(ang);
    }
}

// ========================= fused weight transforms ===========================
// blocks [0,512): pww hi; [512,1536): wkvT; [1536,2048): woT
__global__ void k_wprep(const float* __restrict__ pw_w,
                        const float* __restrict__ w_kv,
                        const float* __restrict__ w_o) {
    int bid = blockIdx.x;
    int t = threadIdx.x;
    if (bid < 512) {
        int i = bid * 256 + t;                  // INNERD*DIMC = 131072
        g_pww_h[i] = h16(pw_w[i]);
    } else if (bid < 1536) {
        int i = (bid - 512) * 256 + t;          // 262144
        int n = i >> 8, k = i & 255;
        g_wkvT_h[i] = h16(w_kv[k * 1024 + n]);
    } else {
        int i = (bid - 1536) * 256 + t;         // 131072
        int n = i >> 9, k = i & 511;
        g_woT_h[i] = h16(w_o[k * 256 + n]);
    }
}

// ---------------- depthwise conv (also emits xs_h for free) ------------------
__global__ void __launch_bounds__(256) k_conv2(const float* __restrict__ x,
                                               const float* __restrict__ dww,
                                               const float* __restrict__ dwb) {
    int c = threadIdx.x;
    int bn = blockIdx.y, seg = blockIdx.x;
    int i0 = seg * 128;
    float w[KW];
#pragma unroll
    for (int k = 0; k < KW; k++) w[k] = dww[c * KW + k];
    float bias = dwb[c];
    const float* xr = x + (size_t)bn * NN * DIMC + c;

    float win[KW];
#pragma unroll
    for (int k = 0; k < KW; k++) {
        int ii = i0 - KW / 2 + k;
        win[k] = (ii >= 0 && ii < NN) ? xr[(size_t)ii * DIMC] : 0.f;
    }
    uint16_t* oh = g_hdw_h + ((size_t)bn * NN + i0) * DIMC + c;
    uint16_t* ox = g_xs_h + ((size_t)bn * NN + i0) * DIMC + c;
    for (int i = i0; i < i0 + 128; i++) {
        float acc = bias;
#pragma unroll
        for (int k = 0; k < KW; k++) acc = fmaf(win[k], w[k], acc);
        *oh = h16(acc);
        *ox = h16(win[KW / 2]);                // win center == x[i]
        oh += DIMC; ox += DIMC;
#pragma unroll
        for (int k = 0; k < KW - 1; k++) win[k] = win[k + 1];
        int ii = i + KW / 2 + 1;
        win[KW - 1] = (ii < NN) ? xr[(size_t)ii * DIMC] : 0.f;
    }
}

// ---------------- masked softmax (writes fp16 hi) ----------------------------
__global__ void k_softmax() {
    int row = blockIdx.x;
    int b = row >> 12;
    int i = row & 511;
    const float* p = g_dots + (size_t)row * NN;
    float rv = g_m_any[b * NN + i];
    int t = threadIdx.x;

    float m0 = g_m_any[b * NN + t];
    float m1 = g_m_any[b * NN + t + 256];
    float x0 = (rv != 0.f && m0 != 0.f) ? p[t]       : -FLT_MAX;
    float x1 = (rv != 0.f && m1 != 0.f) ? p[t + 256] : -FLT_MAX;

    __shared__ float red[256];
    float mx = fmaxf(x0, x1);
    red[t] = mx;
    __syncthreads();
    for (int s = 128; s > 0; s >>= 1) {
        if (t < s) red[t] = fmaxf(red[t], red[t + s]);
        __syncthreads();
    }
    mx = red[0];
    __syncthreads();
    float e0 = expf(x0 - mx), e1 = expf(x1 - mx);
    red[t] = e0 + e1;
    __syncthreads();
    for (int s = 128; s > 0; s >>= 1) {
        if (t < s) red[t] += red[t + s];
        __syncthreads();
    }
    float inv = 1.0f / red[0];
    size_t o = (size_t)row * NN;
    g_attn_h[o + t]       = h16(e0 * inv);
    g_attn_h[o + t + 256] = h16(e1 * inv);
}

// ================== mma.sync fp16 NT GEMM (single-sync pipeline) =============
struct GemmP {
    const uint16_t *Ah; long long lda; long long a_bs;
    const uint16_t *Bh; long long ldb; long long b_bs;
    float* C;                                  // fp32 out (or null)
    uint16_t *Ch;                              // fp16 hi out (or null)
    long long ldc; long long c_bs;
    int K;
    const float* bias;
    const float* alpha_vec; int alpha_shift;
    int mode;   // 0 normal batch, 1 = AV addressing
    int emode;  // 0 plain, 1 rotary->qr hi, 5 combined: K half rotary / V half vT
};

// rotary epilogue: write fp16 hi-only q/k in (b,h,i,r*64+d) layout
__device__ __forceinline__ void rot_store(int row, int col, float ve, float vo,
                                          bool isq) {
    int i = row & 511, bn = row >> 9;
    int h = col >> 6, d = col & 63, j = d >> 1;
    float s = g_sin[i * 32 + j], c = g_cos[i * 32 + j];
    float oe = ve * c - vo * s;
    float oo = vo * c + ve * s;
    int b = bn >> 5, r = bn & 31;
    size_t dst = (((size_t)(b * HH + h) * NN + i) * (RR * DH)) + r * DH + d;
    if (isq) {
        float hr = g_has_rows[bn];
        oe *= hr; oo *= hr;
        *(uint32_t*)(g_qr_h + dst) = (uint32_t)h16(oe) | ((uint32_t)h16(oo) << 16);
    } else {
        *(uint32_t*)(g_kr_h + dst) = (uint32_t)h16(oe) | ((uint32_t)h16(oo) << 16);
    }
}

template <int TN>
__global__ void __launch_bounds__(256) k_mma(GemmP p) {
    constexpr int NT8 = TN / 32;
    constexpr int NX4 = NT8 / 2;
    constexpr uint32_t SS = 8192u + TN * 64u;    // stage stride bytes
    extern __shared__ __align__(128) char dsm[];
    uint32_t sb = smem_u32(dsm);

    int tid = threadIdx.x, wid = tid >> 5, lane = tid & 31;
    int bx = blockIdx.x, by = blockIdx.y, z = blockIdx.z;

    size_t abase, cbase;
    size_t bbase = (size_t)z * p.b_bs + (size_t)bx * TN * p.ldb;
    if (p.mode == 0) {
        abase = (size_t)z * p.a_bs;
        cbase = (size_t)z * p.c_bs;
    } else {                                  // AV: z = bn*8 + h
        int bn = z >> 3, h = z & 7, b = bn >> 5;
        abase = (size_t)(b * HH + h) * p.a_bs;
        cbase = (size_t)bn * p.c_bs + h * 64;
    }
    abase += (size_t)by * 128 * p.lda;
    const uint16_t* Ah = p.Ah + abase;
    const uint16_t* Bh = p.Bh + bbase;

    int m0 = (wid & 1) * 64;
    int n0 = (wid >> 1) * (TN / 4);
    int arow = m0 + (lane & 7) + ((lane >> 3) & 1) * 8;
    int akb  = ((lane >> 4) & 1) * 8;
    int brow = n0 + (lane & 7) + ((lane >> 4) & 1) * 8;
    int bkb  = ((lane >> 3) & 1) * 8;

    float acc[4][NT8][4];
#pragma unroll
    for (int i = 0; i < 4; i++)
#pragma unroll
        for (int j = 0; j < NT8; j++)
#pragma unroll
            for (int q = 0; q < 4; q++) acc[i][j][q] = 0.f;

    int KC = p.K >> 5;

    auto load_stage = [&](int st, int k0) {
        uint32_t base = sb + (uint32_t)st * SS;
#pragma unroll 2
        for (int idx = tid; idx < 512; idx += 256) {
            int row = idx >> 2, c = idx & 3;
            uint32_t off = (uint32_t)(row * 64 + ((c * 16) ^ (((row >> 1) & 3) << 4)));
            CP16(base + off, Ah + (size_t)row * p.lda + k0 + c * 8);
        }
#pragma unroll 2
        for (int idx = tid; idx < TN * 4; idx += 256) {
            int row = idx >> 2, c = idx & 3;
            uint32_t off = (uint32_t)(row * 64 + ((c * 16) ^ (((row >> 1) & 3) << 4)));
            CP16(base + 8192 + off, Bh + (size_t)row * p.ldb + k0 + c * 8);
        }
    };

    load_stage(0, 0);
    CP_COMMIT();

    for (int ch = 0; ch < KC; ch++) {
        CP_WAIT0();
        __syncthreads();
        if (ch + 1 < KC) {
            load_stage((ch + 1) & 1, (ch + 1) << 5);
            CP_COMMIT();
        }

        uint32_t base = sb + (uint32_t)(ch & 1) * SS;
        uint32_t aHiB = base, bHiB = base + 8192;

#pragma unroll
        for (int kk = 0; kk < 32; kk += 16) {
            uint32_t ah[4][4];
#pragma unroll
            for (int mt = 0; mt < 4; mt++)
                LDSM4(ah[mt], aHiB + soff(arow + mt * 16, kk + akb));
            uint32_t bh[NX4][4];
#pragma unroll
            for (int nx = 0; nx < NX4; nx++)
                LDSM4(bh[nx], bHiB + soff(brow + nx * 16, kk + bkb));
#pragma unroll
            for (int mt = 0; mt < 4; mt++)
#pragma unroll
                for (int nt = 0; nt < NT8; nt++)
                    mma_h(acc[mt][nt], ah[mt], &bh[nt >> 1][(nt & 1) * 2]);
        }
    }

    // ---------------- epilogues ----------------
    float alpha = p.alpha_vec ? p.alpha_vec[z >> p.alpha_shift] : 1.0f;
    int r0 = by * 128 + m0 + (lane >> 2);
    int c0 = bx * TN + n0 + (lane & 3) * 2;

    if (p.emode == 5 && bx >= 4) {
        // V half: transpose 128x128 tile through smem -> vT_h (coalesced)
        __syncthreads();                       // all LDSM reads of smem done
        uint16_t* sm = (uint16_t*)dsm;         // needs 128*130*2 = 33280 B
        int rl0 = m0 + (lane >> 2);
        int cl0 = n0 + (lane & 3) * 2;
#pragma unroll
        for (int mt = 0; mt < 4; mt++)
#pragma unroll
            for (int nt = 0; nt < NT8; nt++) {
                int rl = rl0 + mt * 16, cl = cl0 + nt * 8;
                sm[(cl + 0) * 130 + rl]     = h16(acc[mt][nt][0]);
                sm[(cl + 1) * 130 + rl]     = h16(acc[mt][nt][1]);
                sm[(cl + 0) * 130 + rl + 8] = h16(acc[mt][nt][2]);
                sm[(cl + 1) * 130 + rl + 8] = h16(acc[mt][nt][3]);
            }
        __syncthreads();
        int bn = by >> 2, i0g = (by & 3) * 128;
        int hd0 = (bx - 4) * TN;
        int c = tid >> 1, half = tid & 1;
        size_t dst = ((size_t)bn * 512 + hd0 + c) * 512 + i0g + half * 64;
        const uint16_t* srow = sm + c * 130 + half * 64;
#pragma unroll 4
        for (int r = 0; r < 64; r += 4) {
            uint2 val;
            val.x = (uint32_t)srow[r]     | ((uint32_t)srow[r + 1] << 16);
            val.y = (uint32_t)srow[r + 2] | ((uint32_t)srow[r + 3] << 16);
            *(uint2*)(g_vT_h + dst + r) = val;
        }
        return;
    }

#pragma unroll
    for (int mt = 0; mt < 4; mt++) {
#pragma unroll
        for (int nt = 0; nt < NT8; nt++) {
            int row = r0 + mt * 16;
            int col = c0 + nt * 8;
            float b0 = 0.f, b1 = 0.f;
            if (p.bias) { b0 = p.bias[col]; b1 = p.bias[col + 1]; }
            float v00 = acc[mt][nt][0] * alpha + b0;
            float v01 = acc[mt][nt][1] * alpha + b1;
            float v10 = acc[mt][nt][2] * alpha + b0;
            float v11 = acc[mt][nt][3] * alpha + b1;
            if (p.emode == 1) {
                rot_store(row, col, v00, v01, true);
                rot_store(row + 8, col, v10, v11, true);
            } else if (p.emode == 5) {         // K half (bx < 4)
                rot_store(row, col, v00, v01, false);
                rot_store(row + 8, col, v10, v11, false);
            } else {
                if (p.C) {
                    *(float2*)(p.C + cbase + (size_t)row * p.ldc + col) = make_float2(v00, v01);
                    *(float2*)(p.C + cbase + (size_t)(row + 8) * p.ldc + col) = make_float2(v10, v11);
                }
                if (p.Ch) {
                    *(uint32_t*)(p.Ch + cbase + (size_t)row * p.ldc + col) =
                        (uint32_t)h16(v00) | ((uint32_t)h16(v01) << 16);
                    *(uint32_t*)(p.Ch + cbase + (size_t)(row + 8) * p.ldc + col) =
                        (uint32_t)h16(v10) | ((uint32_t)h16(v11) << 16);
                }
            }
        }
    }
}

// ---------------- launch -----------------------------------------------------
#define SYM(var, sym) decltype(&sym[0]) var; cudaGetSymbolAddress((void**)&var, sym)

extern "C" void kernel_launch(void* const* d_in, const int* in_sizes, int n_in,
                              void* d_out, int out_size) {
    const float* x    = (const float*)d_in[0];
    const void*  mask = d_in[1];
    const float* dw_w = (const float*)d_in[3];
    const float* dw_b = (const float*)d_in[4];
    const float* pw_w = (const float*)d_in[5];
    const float* pw_b = (const float*)d_in[6];
    const float* w_kv = (const float*)d_in[7];
    const float* w_o  = (const float*)d_in[8];
    const float* b_o  = (const float*)d_in[9];
    float* out = (float*)d_out;

    const int SM128 = 33536;                    // >= max(2 stages 32768, vT 33280)
    const int SM64  = 2 * (8192 + 64 * 64);     // 24576
    cudaFuncSetAttribute(k_mma<128>, cudaFuncAttributeMaxDynamicSharedMemorySize, SM128);
    cudaFuncSetAttribute(k_mma<64>,  cudaFuncAttributeMaxDynamicSharedMemorySize, SM64);

    SYM(dots_p, g_dots);
    SYM(xs_h, g_xs_h);
    SYM(hdw_h, g_hdw_h);
    SYM(pww_h, g_pww_h);
    SYM(wkvT_h, g_wkvT_h);
    SYM(woT_h, g_woT_h);
    SYM(qr_h, g_qr_h);
    SYM(kr_h, g_kr_h);
    SYM(attn_h, g_attn_h);
    SYM(vT_h, g_vT_h);
    SYM(oi_h, g_oi_h);
    SYM(alpha_p, g_alpha);

    k_prep<<<1, 1024>>>(mask);
    k_wprep<<<2048, 256>>>(pw_w, w_kv, w_o);
    k_conv2<<<dim3(4, BN_TOT), 256>>>(x, dw_w, dw_b);

    // qproj + bias + rotary + has_rows -> qr hi  (M=32768, N=512, K=256)
    {
        GemmP p = {hdw_h, DIMC, 0, pww_h, DIMC, 0,
                   nullptr, nullptr, 0, 0,
                   DIMC, pw_b, nullptr, 0, 0, 1};
        k_mma<128><<<dim3(4, 256, 1), 256, SM128>>>(p);
    }
    // KV proj combined: K half (bx<4) -> rotary kr hi; V half (bx>=4) -> vT_h transposed
    // (M=32768, N=1024, K=256)
    {
        GemmP p = {xs_h, DIMC, 0, wkvT_h, DIMC, 0,
                   nullptr, nullptr, 0, 0,
                   DIMC, nullptr, nullptr, 0, 0, 5};
        k_mma<128><<<dim3(8, 256, 1), 256, SM128>>>(p);
    }
    // dots: 16 batches, M=N=512, K=2048 -> fp32 (alpha per b)
    {
        GemmP p = {qr_h, 2048, (long long)NN * 2048, kr_h, 2048, (long long)NN * 2048,
                   dots_p, nullptr, NN, (long long)NN * NN,
                   2048, nullptr, alpha_p, 3, 0, 0};
        k_mma<128><<<dim3(4, 4, 16), 256, SM128>>>(p);
    }
    k_softmax<<<NB * HH * NN, 256>>>();
    // AV: 512 batches (bn,h), M=512, N=64, K=512 -> oi hi
    {
        GemmP p = {attn_h, NN, (long long)NN * NN, vT_h, NN, (long long)DH * NN,
                   nullptr, oi_h, INNERD, (long long)NN * INNERD,
                   NN, nullptr, nullptr, 0, 1, 0};
        k_mma<64><<<dim3(1, 4, BN_TOT * HH), 256, SM64>>>(p);
    }
    // final: M=32768, N=256, K=512 -> out fp32 (+bias)
    {
        GemmP p = {oi_h, INNERD, 0, woT_h, INNERD, 0,
                   out, nullptr, DIMC, 0,
                   INNERD, b_o, nullptr, 0, 0, 0};
        k_mma<128><<<dim3(2, 256, 1), 256, SM128>>>(p);
    }
}

// round 13
// speedup vs baseline: 2.3287x; 1.0756x over previous
#include <cuda_runtime.h>
#include <cuda_bf16.h>
#include <cuda_fp16.h>
#include <float.h>
#include <math.h>
#include <stdint.h>

// Problem constants (fixed shapes)
#define BN_TOT 64      // b*r
#define NB 2           // b
#define RR 32          // r
#define NN 512         // n
#define DIMC 256       // DIM
#define HH 8           // heads
#define DH 64          // dim_head
#define INNERD 512     // HH*DH
#define KW 15          // conv kernel

// ---------------- scratch (device globals; no allocations allowed) ----------
__device__ float g_dots[NB * HH * NN * NN];         // logits fp32

// fp16 hi-only operands everywhere
__device__ uint16_t g_xs_h[BN_TOT * NN * DIMC];
__device__ uint16_t g_hdw_h[BN_TOT * NN * DIMC];
__device__ uint16_t g_pww_h[INNERD * DIMC];
__device__ uint16_t g_wkvT_h[2 * INNERD * DIMC];
__device__ uint16_t g_woT_h[DIMC * INNERD];
__device__ uint16_t g_vT_h[BN_TOT * INNERD * NN];
__device__ uint16_t g_attn_h[NB * HH * NN * NN];
__device__ uint16_t g_oi_h[BN_TOT * NN * INNERD];
__device__ uint16_t g_qr_h[NB * HH * NN * RR * DH];
__device__ uint16_t g_kr_h[NB * HH * NN * RR * DH];

__device__ unsigned char g_mask[BN_TOT * NN];
__device__ float g_has_rows[BN_TOT];
__device__ float g_m_any[NB * NN];
__device__ float g_alpha[NB];
__device__ float g_sin[NN * 32];
__device__ float g_cos[NN * 32];

// ========================= helpers ===========================================
__device__ __forceinline__ uint32_t smem_u32(const void* p) {
    uint32_t a;
    asm("{ .reg .u64 t; cvta.to.shared.u64 t, %1; cvt.u32.u64 %0, t; }" : "=r"(a) : "l"(p));
    return a;
}

#define LDSM4(r, addr)                                                          \
    asm volatile("ldmatrix.sync.aligned.m8n8.x4.shared.b16 {%0,%1,%2,%3}, [%4];" \
                 : "=r"((r)[0]), "=r"((r)[1]), "=r"((r)[2]), "=r"((r)[3])       \
                 : "r"(addr))

__device__ __forceinline__ void mma_h(float* c, const uint32_t* a, const uint32_t* b) {
    asm volatile("mma.sync.aligned.m16n8k16.row.col.f32.f16.f16.f32 "
                 "{%0,%1,%2,%3}, {%4,%5,%6,%7}, {%8,%9}, {%0,%1,%2,%3};"
                 : "+f"(c[0]), "+f"(c[1]), "+f"(c[2]), "+f"(c[3])
                 : "r"(a[0]), "r"(a[1]), "r"(a[2]), "r"(a[3]), "r"(b[0]), "r"(b[1]));
}

#define CP16(dst, src)                                                          \
    asm volatile("cp.async.cg.shared.global [%0], [%1], 16;" :: "r"(dst), "l"(src) : "memory")
#define CP_COMMIT() asm volatile("cp.async.commit_group;" ::: "memory")
#define CP_WAIT0()  asm volatile("cp.async.wait_group 0;" ::: "memory")

// byte offset in a 128B-per-row fp16 tile (64 k values/row), bank-swizzled:
// 8 consecutive rows -> 8 distinct 16B groups (XOR bits[4:6] by row&7)
__device__ __forceinline__ uint32_t soff(int row, int kcol) {
    return (uint32_t)(row * 128 + ((kcol * 2) ^ ((row & 7) << 4)));
}

__device__ __forceinline__ uint16_t h16(float v) {
    return __half_as_ushort(__float2half_rn(v));
}

// ========================= fused prep (mask + trig), ONE block ===============
__global__ void __launch_bounds__(1024) k_prep(const void* mraw) {
    const unsigned char* mb = (const unsigned char*)mraw;
    int tid = threadIdx.x;
    __shared__ int s_high, s_odd;

    if (tid == 0) { s_high = 0; s_odd = 0; }
    __syncthreads();
    for (int idx = tid; idx < BN_TOT * NN; idx += 1024) {
        unsigned char v = mb[idx];
        if (v > 1) s_high = 1;
        if ((idx & 3) && v) s_odd = 1;
    }
    __syncthreads();
    int mode = s_high ? 2 : (s_odd ? 0 : 1);

    for (int idx = tid; idx < BN_TOT * NN; idx += 1024) {
        unsigned char v;
        if (mode == 0)      v = (mb[idx] != 0);
        else if (mode == 1) v = (((const int*)mraw)[idx] != 0);
        else                v = (((const float*)mraw)[idx] != 0.0f);
        g_mask[idx] = v;
    }
    __syncthreads();

    int w = tid >> 5, lane = tid & 31;
    for (int bb = 0; bb < 2; bb++) {
        int bn = w * 2 + bb;
        int any = 0;
        for (int q = lane; q < NN; q += 32) any |= g_mask[bn * NN + q];
        any = __any_sync(0xFFFFFFFFu, any);
        if (lane == 0) g_has_rows[bn] = (float)any;
    }
    __syncthreads();

    {
        int b = tid >> 9, i = tid & 511;
        int any = 0;
        for (int r = 0; r < RR; r++) any |= g_mask[(b * RR + r) * NN + i];
        g_m_any[b * NN + i] = (float)any;
        if (i == 0) {
            float s = 0.f;
            for (int r = 0; r < RR; r++) s += g_has_rows[b * RR + r];
            g_alpha[b] = (s > 0.f) ? 0.125f * rsqrtf(s) : 0.f;
        }
    }

    for (int idx = tid; idx < NN * 32; idx += 1024) {
        int i = idx >> 5, j = idx & 31;
        float inv = exp2f(-((float)(2 * j) / 64.0f) * 13.287712379549449f);
        float ang = (float)i * inv;
        g_sin[idx] = sinf(ang);
        g_cos[idx] = cosf(ang);
    }
}

// ========================= fused weight transforms ===========================
__global__ void k_wprep(const float* __restrict__ pw_w,
                        const float* __restrict__ w_kv,
                        const float* __restrict__ w_o) {
    int bid = blockIdx.x;
    int t = threadIdx.x;
    if (bid < 512) {
        int i = bid * 256 + t;
        g_pww_h[i] = h16(pw_w[i]);
    } else if (bid < 1536) {
        int i = (bid - 512) * 256 + t;
        int n = i >> 8, k = i & 255;
        g_wkvT_h[i] = h16(w_kv[k * 1024 + n]);
    } else {
        int i = (bid - 1536) * 256 + t;
        int n = i >> 9, k = i & 511;
        g_woT_h[i] = h16(w_o[k * 256 + n]);
    }
}

// ---------------- depthwise conv (also emits xs_h for free) ------------------
__global__ void __launch_bounds__(256) k_conv2(const float* __restrict__ x,
                                               const float* __restrict__ dww,
                                               const float* __restrict__ dwb) {
    int c = threadIdx.x;
    int bn = blockIdx.y, seg = blockIdx.x;
    int i0 = seg * 128;
    float w[KW];
#pragma unroll
    for (int k = 0; k < KW; k++) w[k] = dww[c * KW + k];
    float bias = dwb[c];
    const float* xr = x + (size_t)bn * NN * DIMC + c;

    float win[KW];
#pragma unroll
    for (int k = 0; k < KW; k++) {
        int ii = i0 - KW / 2 + k;
        win[k] = (ii >= 0 && ii < NN) ? xr[(size_t)ii * DIMC] : 0.f;
    }
    uint16_t* oh = g_hdw_h + ((size_t)bn * NN + i0) * DIMC + c;
    uint16_t* ox = g_xs_h + ((size_t)bn * NN + i0) * DIMC + c;
    for (int i = i0; i < i0 + 128; i++) {
        float acc = bias;
#pragma unroll
        for (int k = 0; k < KW; k++) acc = fmaf(win[k], w[k], acc);
        *oh = h16(acc);
        *ox = h16(win[KW / 2]);
        oh += DIMC; ox += DIMC;
#pragma unroll
        for (int k = 0; k < KW - 1; k++) win[k] = win[k + 1];
        int ii = i + KW / 2 + 1;
        win[KW - 1] = (ii < NN) ? xr[(size_t)ii * DIMC] : 0.f;
    }
}

// ---------------- masked softmax (writes fp16 hi) ----------------------------
__global__ void k_softmax() {
    int row = blockIdx.x;
    int b = row >> 12;
    int i = row & 511;
    const float* p = g_dots + (size_t)row * NN;
    float rv = g_m_any[b * NN + i];
    int t = threadIdx.x;

    float m0 = g_m_any[b * NN + t];
    float m1 = g_m_any[b * NN + t + 256];
    float x0 = (rv != 0.f && m0 != 0.f) ? p[t]       : -FLT_MAX;
    float x1 = (rv != 0.f && m1 != 0.f) ? p[t + 256] : -FLT_MAX;

    __shared__ float red[256];
    float mx = fmaxf(x0, x1);
    red[t] = mx;
    __syncthreads();
    for (int s = 128; s > 0; s >>= 1) {
        if (t < s) red[t] = fmaxf(red[t], red[t + s]);
        __syncthreads();
    }
    mx = red[0];
    __syncthreads();
    float e0 = expf(x0 - mx), e1 = expf(x1 - mx);
    red[t] = e0 + e1;
    __syncthreads();
    for (int s = 128; s > 0; s >>= 1) {
        if (t < s) red[t] += red[t + s];
        __syncthreads();
    }
    float inv = 1.0f / red[0];
    size_t o = (size_t)row * NN;
    g_attn_h[o + t]       = h16(e0 * inv);
    g_attn_h[o + t + 256] = h16(e1 * inv);
}

// ================== mma.sync fp16 NT GEMM, BK=64, single-sync pipeline =======
struct GemmP {
    const uint16_t *Ah; long long lda; long long a_bs;
    const uint16_t *Bh; long long ldb; long long b_bs;
    float* C;                                  // fp32 out (or null)
    uint16_t *Ch;                              // fp16 hi out (or null)
    long long ldc; long long c_bs;
    int K;
    const float* bias;
    const float* alpha_vec; int alpha_shift;
    int mode;   // 0 normal batch, 1 = AV addressing
    int emode;  // 0 plain, 6 merged proj (q/k rotary + v transpose)
};

// rotary epilogue: write fp16 hi-only q/k in (b,h,i,r*64+d) layout
__device__ __forceinline__ void rot_store(int row, int col, float ve, float vo,
                                          bool isq) {
    int i = row & 511, bn = row >> 9;
    int h = col >> 6, d = col & 63, j = d >> 1;
    float s = g_sin[i * 32 + j], c = g_cos[i * 32 + j];
    float oe = ve * c - vo * s;
    float oo = vo * c + ve * s;
    int b = bn >> 5, r = bn & 31;
    size_t dst = (((size_t)(b * HH + h) * NN + i) * (RR * DH)) + r * DH + d;
    if (isq) {
        float hr = g_has_rows[bn];
        oe *= hr; oo *= hr;
        *(uint32_t*)(g_qr_h + dst) = (uint32_t)h16(oe) | ((uint32_t)h16(oo) << 16);
    } else {
        *(uint32_t*)(g_kr_h + dst) = (uint32_t)h16(oe) | ((uint32_t)h16(oo) << 16);
    }
}

template <int TN>
__global__ void __launch_bounds__(256) k_mma(GemmP p) {
    constexpr int NT8 = TN / 32;
    constexpr int NX4 = NT8 / 2;
    constexpr uint32_t SS = 16384u + TN * 128u;    // stage stride bytes (BK=64)
    extern __shared__ __align__(128) char dsm[];
    uint32_t sb = smem_u32(dsm);

    int tid = threadIdx.x, wid = tid >> 5, lane = tid & 31;
    int bx = blockIdx.x, by = blockIdx.y, z = blockIdx.z;

    const uint16_t* Ah;
    const uint16_t* Bh;
    size_t cbase = 0;
    if (p.emode == 6) {
        if (bx < 4)      { Ah = g_hdw_h; Bh = g_pww_h + (size_t)bx * 128 * DIMC; }
        else if (bx < 8) { Ah = g_xs_h;  Bh = g_wkvT_h + (size_t)(bx - 4) * 128 * DIMC; }
        else             { Ah = g_xs_h;  Bh = g_wkvT_h + (size_t)(512 + (bx - 8) * 128) * DIMC; }
        Ah += (size_t)by * 128 * DIMC;
    } else {
        size_t abase;
        size_t bbase = (size_t)z * p.b_bs + (size_t)bx * TN * p.ldb;
        if (p.mode == 0) {
            abase = (size_t)z * p.a_bs;
            cbase = (size_t)z * p.c_bs;
        } else {                                  // AV: z = bn*8 + h
            int bn = z >> 3, h = z & 7, b = bn >> 5;
            abase = (size_t)(b * HH + h) * p.a_bs;
            cbase = (size_t)bn * p.c_bs + h * 64;
        }
        abase += (size_t)by * 128 * p.lda;
        Ah = p.Ah + abase;
        Bh = p.Bh + bbase;
    }

    int m0 = (wid & 1) * 64;
    int n0 = (wid >> 1) * (TN / 4);
    int arow = m0 + (lane & 7) + ((lane >> 3) & 1) * 8;
    int akb  = ((lane >> 4) & 1) * 8;
    int brow = n0 + (lane & 7) + ((lane >> 4) & 1) * 8;
    int bkb  = ((lane >> 3) & 1) * 8;

    float acc[4][NT8][4];
#pragma unroll
    for (int i = 0; i < 4; i++)
#pragma unroll
        for (int j = 0; j < NT8; j++)
#pragma unroll
            for (int q = 0; q < 4; q++) acc[i][j][q] = 0.f;

    int KC = p.K >> 6;                     // BK = 64

    auto load_stage = [&](int st, int k0) {
        uint32_t base = sb + (uint32_t)st * SS;
#pragma unroll 4
        for (int idx = tid; idx < 1024; idx += 256) {
            int row = idx >> 3, c = idx & 7;
            uint32_t off = (uint32_t)(row * 128 + ((c * 16) ^ ((row & 7) << 4)));
            CP16(base + off, Ah + (size_t)row * p.lda + k0 + c * 8);
        }
#pragma unroll 4
        for (int idx = tid; idx < TN * 8; idx += 256) {
            int row = idx >> 3, c = idx & 7;
            uint32_t off = (uint32_t)(row * 128 + ((c * 16) ^ ((row & 7) << 4)));
            CP16(base + 16384 + off, Bh + (size_t)row * p.ldb + k0 + c * 8);
        }
    };

    load_stage(0, 0);
    CP_COMMIT();

    for (int ch = 0; ch < KC; ch++) {
        CP_WAIT0();
        __syncthreads();
        if (ch + 1 < KC) {
            load_stage((ch + 1) & 1, (ch + 1) << 6);
            CP_COMMIT();
        }

        uint32_t base = sb + (uint32_t)(ch & 1) * SS;
        uint32_t aHiB = base, bHiB = base + 16384;

#pragma unroll
        for (int kk = 0; kk < 64; kk += 16) {
            uint32_t ah[4][4];
#pragma unroll
            for (int mt = 0; mt < 4; mt++)
                LDSM4(ah[mt], aHiB + soff(arow + mt * 16, kk + akb));
            uint32_t bh[NX4][4];
#pragma unroll
            for (int nx = 0; nx < NX4; nx++)
                LDSM4(bh[nx], bHiB + soff(brow + nx * 16, kk + bkb));
#pragma unroll
            for (int mt = 0; mt < 4; mt++)
#pragma unroll
                for (int nt = 0; nt < NT8; nt++)
                    mma_h(acc[mt][nt], ah[mt], &bh[nt >> 1][(nt & 1) * 2]);
        }
    }

    // ---------------- epilogues ----------------
    int r0 = by * 128 + m0 + (lane >> 2);

    if (p.emode == 6) {
        int ncol0 = (bx & 3) * 128;
        if (bx >= 8) {
            // V: transpose 128x128 tile through smem -> vT_h (coalesced)
            __syncthreads();
            uint16_t* sm = (uint16_t*)dsm;     // 128*130*2 = 33280 B < 2*SS
            int rl0 = m0 + (lane >> 2);
            int cl0 = n0 + (lane & 3) * 2;
#pragma unroll
            for (int mt = 0; mt < 4; mt++)
#pragma unroll
                for (int nt = 0; nt < NT8; nt++) {
                    int rl = rl0 + mt * 16, cl = cl0 + nt * 8;
                    sm[(cl + 0) * 130 + rl]     = h16(acc[mt][nt][0]);
                    sm[(cl + 1) * 130 + rl]     = h16(acc[mt][nt][1]);
                    sm[(cl + 0) * 130 + rl + 8] = h16(acc[mt][nt][2]);
                    sm[(cl + 1) * 130 + rl + 8] = h16(acc[mt][nt][3]);
                }
            __syncthreads();
            int bn = by >> 2, i0g = (by & 3) * 128;
            int hd0 = (bx - 8) * 128;
            int c = tid >> 1, half = tid & 1;
            size_t dst = ((size_t)bn * 512 + hd0 + c) * 512 + i0g + half * 64;
            const uint16_t* srow = sm + c * 130 + half * 64;
#pragma unroll 4
            for (int r = 0; r < 64; r += 4) {
                uint2 val;
                val.x = (uint32_t)srow[r]     | ((uint32_t)srow[r + 1] << 16);
                val.y = (uint32_t)srow[r + 2] | ((uint32_t)srow[r + 3] << 16);
                *(uint2*)(g_vT_h + dst + r) = val;
            }
            return;
        }
        bool isq = (bx < 4);
        int c0l = ncol0 + n0 + (lane & 3) * 2;
#pragma unroll
        for (int mt = 0; mt < 4; mt++)
#pragma unroll
            for (int nt = 0; nt < NT8; nt++) {
                int row = r0 + mt * 16;
                int col = c0l + nt * 8;
                float b0 = 0.f, b1 = 0.f;
                if (isq) { b0 = p.bias[col]; b1 = p.bias[col + 1]; }
                rot_store(row, col, acc[mt][nt][0] + b0, acc[mt][nt][1] + b1, isq);
                rot_store(row + 8, col, acc[mt][nt][2] + b0, acc[mt][nt][3] + b1, isq);
            }
        return;
    }

    float alpha = p.alpha_vec ? p.alpha_vec[z >> p.alpha_shift] : 1.0f;
    int c0 = bx * TN + n0 + (lane & 3) * 2;
#pragma unroll
    for (int mt = 0; mt < 4; mt++) {
#pragma unroll
        for (int nt = 0; nt < NT8; nt++) {
            int row = r0 + mt * 16;
            int col = c0 + nt * 8;
            float b0 = 0.f, b1 = 0.f;
            if (p.bias) { b0 = p.bias[col]; b1 = p.bias[col + 1]; }
            float v00 = acc[mt][nt][0] * alpha + b0;
            float v01 = acc[mt][nt][1] * alpha + b1;
            float v10 = acc[mt][nt][2] * alpha + b0;
            float v11 = acc[mt][nt][3] * alpha + b1;
            if (p.C) {
                *(float2*)(p.C + cbase + (size_t)row * p.ldc + col) = make_float2(v00, v01);
                *(float2*)(p.C + cbase + (size_t)(row + 8) * p.ldc + col) = make_float2(v10, v11);
            }
            if (p.Ch) {
                *(uint32_t*)(p.Ch + cbase + (size_t)row * p.ldc + col) =
                    (uint32_t)h16(v00) | ((uint32_t)h16(v01) << 16);
                *(uint32_t*)(p.Ch + cbase + (size_t)(row + 8) * p.ldc + col) =
                    (uint32_t)h16(v10) | ((uint32_t)h16(v11) << 16);
            }
        }
    }
}

// ---------------- launch -----------------------------------------------------
#define SYM(var, sym) decltype(&sym[0]) var; cudaGetSymbolAddress((void**)&var, sym)

extern "C" void kernel_launch(void* const* d_in, const int* in_sizes, int n_in,
                              void* d_out, int out_size) {
    const float* x    = (const float*)d_in[0];
    const void*  mask = d_in[1];
    const float* dw_w = (const float*)d_in[3];
    const float* dw_b = (const float*)d_in[4];
    const float* pw_w = (const float*)d_in[5];
    const float* pw_b = (const float*)d_in[6];
    const float* w_kv = (const float*)d_in[7];
    const float* w_o  = (const float*)d_in[8];
    const float* b_o  = (const float*)d_in[9];
    float* out = (float*)d_out;

    const int SM128 = 2 * (16384 + 128 * 128);   // 65536
    const int SM64  = 2 * (16384 + 64 * 128);    // 49152
    cudaFuncSetAttribute(k_mma<128>, cudaFuncAttributeMaxDynamicSharedMemorySize, SM128);
    cudaFuncSetAttribute(k_mma<64>,  cudaFuncAttributeMaxDynamicSharedMemorySize, SM64);

    SYM(dots_p, g_dots);
    SYM(qr_h, g_qr_h);
    SYM(kr_h, g_kr_h);
    SYM(attn_h, g_attn_h);
    SYM(vT_h, g_vT_h);
    SYM(oi_h, g_oi_h);
    SYM(woT_h, g_woT_h);
    SYM(alpha_p, g_alpha);

    k_prep<<<1, 1024>>>(mask);
    k_wprep<<<2048, 256>>>(pw_w, w_kv, w_o);
    k_conv2<<<dim3(4, BN_TOT), 256>>>(x, dw_w, dw_b);

    // merged projections: q (bias+rotary+has_rows), k (rotary), v (transpose->vT)
    // grid (12, 256): bx<4 q, 4..7 k, 8..11 v.  M=32768, N=512 each, K=256.
    {
        GemmP p = {nullptr, DIMC, 0, nullptr, DIMC, 0,
                   nullptr, nullptr, 0, 0,
                   DIMC, pw_b, nullptr, 0, 0, 6};
        k_mma<128><<<dim3(12, 256, 1), 256, SM128>>>(p);
    }
    // dots: 16 batches, M=N=512, K=2048 -> fp32 (alpha per b)
    {
        GemmP p = {qr_h, 2048, (long long)NN * 2048, kr_h, 2048, (long long)NN * 2048,
                   dots_p, nullptr, NN, (long long)NN * NN,
                   2048, nullptr, alpha_p, 3, 0, 0};
        k_mma<128><<<dim3(4, 4, 16), 256, SM128>>>(p);
    }
    k_softmax<<<NB * HH * NN, 256>>>();
    // AV: 512 batches (bn,h), M=512, N=64, K=512 -> oi hi
    {
        GemmP p = {attn_h, NN, (long long)NN * NN, vT_h, NN, (long long)DH * NN,
                   nullptr, oi_h, INNERD, (long long)NN * INNERD,
                   NN, nullptr, nullptr, 0, 1, 0};
        k_mma<64><<<dim3(1, 4, BN_TOT * HH), 256, SM64>>>(p);
    }
    // final: M=32768, N=256, K=512 -> out fp32 (+bias)
    {
        GemmP p = {oi_h, INNERD, 0, woT_h, INNERD, 0,
                   out, nullptr, DIMC, 0,
                   INNERD, b_o, nullptr, 0, 0, 0};
        k_mma<128><<<dim3(2, 256, 1), 256, SM128>>>(p);
    }
}